// round 11
// baseline (speedup 1.0000x reference)
#include <cuda_runtime.h>
#include <cuda_bf16.h>
#include <cstdint>

// ---------------- problem constants ----------------
#define B_   8
#define C_   512
#define HH_  32
#define WW_  32
#define L_   1024          // HH*WW
#define NH_  4
#define D_   128
#define KC_  4608          // 512*9 (im2col K)
#define QSCALE 0.08838834764831845f  // 128^-0.5

// ---------------- scratch (device globals; no allocations) ----------------
__device__ __nv_bfloat16 g_xn_hi[B_*L_*C_];        // relu(bn1(x)) transposed [b][l][c]
__device__ __nv_bfloat16 g_xn_lo[B_*L_*C_];
__device__ __nv_bfloat16 g_wqkv_hi[1536*512];      // [o][c], o: q|k|v
__device__ __nv_bfloat16 g_wqkv_lo[1536*512];
__device__ __nv_bfloat16 g_rel_hi[128*128];        // rows: 0..62 rel_w, 63..125 rel_h, 126..127 zero
__device__ __nv_bfloat16 g_rel_lo[128*128];
__device__ __nv_bfloat16 g_q_hi[32*L_*D_];         // [bn][l][d] (scaled)
__device__ __nv_bfloat16 g_q_lo[32*L_*D_];
__device__ __nv_bfloat16 g_k_hi[32*L_*D_];
__device__ __nv_bfloat16 g_k_lo[32*L_*D_];
__device__ __nv_bfloat16 g_v_hi[32*L_*D_];
__device__ __nv_bfloat16 g_v_lo[32*L_*D_];
__device__ float g_xres[B_*C_*L_];                 // mhsa out + x
__device__ __nv_bfloat16 g_y2t_hi[B_*L_*C_];       // relu(bn2(xres)) transposed [b][l][c]
__device__ __nv_bfloat16 g_y2t_lo[B_*L_*C_];
__device__ __nv_bfloat16 g_w_hi[(size_t)C_*KC_];   // reordered: [o][r9*512 + c]
__device__ __nv_bfloat16 g_w_lo[(size_t)C_*KC_];

// ================= mma.sync helpers =================
__device__ __forceinline__ uint32_t smem_u32(const void* p) {
    uint32_t a;
    asm("{ .reg .u64 t; cvta.to.shared.u64 t, %1; cvt.u32.u64 %0, t; }" : "=r"(a) : "l"(p));
    return a;
}
__device__ __forceinline__ void cp16(uint32_t s, const void* g) {
    asm volatile("cp.async.cg.shared.global [%0], [%1], 16;" :: "r"(s), "l"(g));
}
#define CP_COMMIT() asm volatile("cp.async.commit_group;" ::: "memory")
#define CP_WAIT(n)  asm volatile("cp.async.wait_group %0;" :: "n"(n) : "memory")

__device__ __forceinline__ void ldmx4(uint32_t* d, uint32_t addr) {
    asm volatile("ldmatrix.sync.aligned.m8n8.x4.shared.b16 {%0,%1,%2,%3}, [%4];"
                 : "=r"(d[0]), "=r"(d[1]), "=r"(d[2]), "=r"(d[3]) : "r"(addr));
}
__device__ __forceinline__ void ldmx4t(uint32_t* d, uint32_t addr) {
    asm volatile("ldmatrix.sync.aligned.m8n8.x4.trans.shared.b16 {%0,%1,%2,%3}, [%4];"
                 : "=r"(d[0]), "=r"(d[1]), "=r"(d[2]), "=r"(d[3]) : "r"(addr));
}
__device__ __forceinline__ void mma16816(float* c, const uint32_t* a, uint32_t b0, uint32_t b1) {
    asm volatile("mma.sync.aligned.m16n8k16.row.col.f32.bf16.bf16.f32 "
                 "{%0,%1,%2,%3}, {%4,%5,%6,%7}, {%8,%9}, {%0,%1,%2,%3};"
                 : "+f"(c[0]), "+f"(c[1]), "+f"(c[2]), "+f"(c[3])
                 : "r"(a[0]), "r"(a[1]), "r"(a[2]), "r"(a[3]), "r"(b0), "r"(b1));
}
#define SWZ(x) ((x) ^ (((x) >> 3) & 0x70))

__device__ __forceinline__ void hilo(float v, __nv_bfloat16& h, __nv_bfloat16& l) {
    h = __float2bfloat16(v);
    l = __float2bfloat16(v - __bfloat162float(h));
}
__device__ __forceinline__ uint32_t pack_hl(float a, float b, uint32_t& lo_out) {
    __nv_bfloat16 ah, al, bh, bl;
    hilo(a, ah, al); hilo(b, bh, bl);
    __nv_bfloat162 hp; hp.x = ah; hp.y = bh;
    __nv_bfloat162 lp; lp.x = al; lp.y = bl;
    lo_out = *(uint32_t*)&lp;
    return *(uint32_t*)&hp;
}

// ---------------- BN1 + ReLU + transpose -> bf16 hi/lo [b][l][c] ----------------
__global__ void bn1t_kernel(const float* __restrict__ x,
                            const float* __restrict__ g, const float* __restrict__ bb,
                            const float* __restrict__ m, const float* __restrict__ v) {
    __shared__ float t[32][33];
    const int b = blockIdx.z, c0 = blockIdx.y * 32, l0 = blockIdx.x * 32;
    const int tid = threadIdx.x;
    {
        const int cr = tid >> 3, l4 = (tid & 7) * 4;
        const int c = c0 + cr;
        float inv = g[c] * rsqrtf(v[c] + 1e-5f);
        float sh  = bb[c] - m[c] * inv;
        float4 xv = *(const float4*)(x + ((size_t)(b * C_ + c) << 10) + l0 + l4);
        t[cr][l4 + 0] = fmaxf(fmaf(xv.x, inv, sh), 0.f);
        t[cr][l4 + 1] = fmaxf(fmaf(xv.y, inv, sh), 0.f);
        t[cr][l4 + 2] = fmaxf(fmaf(xv.z, inv, sh), 0.f);
        t[cr][l4 + 3] = fmaxf(fmaf(xv.w, inv, sh), 0.f);
    }
    __syncthreads();
    {
        const int lr = tid >> 3, c4 = (tid & 7) * 4;
        __nv_bfloat16 h[4], lo[4];
        #pragma unroll
        for (int u = 0; u < 4; ++u) hilo(t[c4 + u][lr], h[u], lo[u]);
        size_t base = ((size_t)(b * L_ + l0 + lr) << 9) + c0 + c4;
        *(__nv_bfloat162*)(g_xn_hi + base)     = *(__nv_bfloat162*)&h[0];
        *(__nv_bfloat162*)(g_xn_hi + base + 2) = *(__nv_bfloat162*)&h[2];
        *(__nv_bfloat162*)(g_xn_lo + base)     = *(__nv_bfloat162*)&lo[0];
        *(__nv_bfloat162*)(g_xn_lo + base + 2) = *(__nv_bfloat162*)&lo[2];
    }
}

// ---------------- BN2 + ReLU + transpose -> bf16 hi/lo [b][l][c] ----------------
__global__ void bn2t_kernel(const float* __restrict__ g, const float* __restrict__ bb,
                            const float* __restrict__ m, const float* __restrict__ v) {
    __shared__ float t[32][33];
    const int b = blockIdx.z, c0 = blockIdx.y * 32, l0 = blockIdx.x * 32;
    const int tid = threadIdx.x;
    {
        const int cr = tid >> 3, l4 = (tid & 7) * 4;
        const int c = c0 + cr;
        float inv = g[c] * rsqrtf(v[c] + 1e-5f);
        float sh  = bb[c] - m[c] * inv;
        float4 xv = *(const float4*)(g_xres + ((size_t)(b * C_ + c) << 10) + l0 + l4);
        t[cr][l4 + 0] = fmaxf(fmaf(xv.x, inv, sh), 0.f);
        t[cr][l4 + 1] = fmaxf(fmaf(xv.y, inv, sh), 0.f);
        t[cr][l4 + 2] = fmaxf(fmaf(xv.z, inv, sh), 0.f);
        t[cr][l4 + 3] = fmaxf(fmaf(xv.w, inv, sh), 0.f);
    }
    __syncthreads();
    {
        const int lr = tid >> 3, c4 = (tid & 7) * 4;
        __nv_bfloat16 h[4], lo[4];
        #pragma unroll
        for (int u = 0; u < 4; ++u) hilo(t[c4 + u][lr], h[u], lo[u]);
        size_t base = ((size_t)(b * L_ + l0 + lr) << 9) + c0 + c4;
        *(__nv_bfloat162*)(g_y2t_hi + base)     = *(__nv_bfloat162*)&h[0];
        *(__nv_bfloat162*)(g_y2t_hi + base + 2) = *(__nv_bfloat162*)&h[2];
        *(__nv_bfloat162*)(g_y2t_lo + base)     = *(__nv_bfloat162*)&lo[0];
        *(__nv_bfloat162*)(g_y2t_lo + base + 2) = *(__nv_bfloat162*)&lo[2];
    }
}

// ---------------- qkv weights + rel tables -> bf16 hi/lo ----------------
__global__ void wqkv2bf_kernel(const float* __restrict__ w_qk, const float* __restrict__ w_v,
                               const float* __restrict__ rel_h, const float* __restrict__ rel_w) {
    int i = blockIdx.x * 256 + threadIdx.x;
    if (i < 1024 * 512) {
        hilo(w_qk[i], g_wqkv_hi[i], g_wqkv_lo[i]);
    } else if (i < 1536 * 512) {
        hilo(w_v[i - 1024 * 512], g_wqkv_hi[i], g_wqkv_lo[i]);
    } else {
        int j = i - 1536 * 512;          // 0..16383
        int rr = j >> 7, d = j & 127;
        float val = 0.f;
        if (rr < 63)       val = rel_w[rr * 128 + d];
        else if (rr < 126) val = rel_h[(rr - 63) * 128 + d];
        hilo(val, g_rel_hi[j], g_rel_lo[j]);
    }
}

// ---------------- conv weights -> bf16 hi/lo, reorder k' = r9*512 + c ----------------
__global__ void w2bf_kernel(const float* __restrict__ w) {
    int i = blockIdx.x * 256 + threadIdx.x;   // src: o*4608 + c*9 + r9
    int o = i / KC_, rem = i % KC_;
    int c = rem / 9, r9 = rem % 9;
    size_t dst = (size_t)o * KC_ + r9 * 512 + c;
    hilo(w[i], g_w_hi[dst], g_w_lo[dst]);
}

// ---------------- QKV projection via mma.sync (512 threads / 16 warps) ----------------
// block tile 128x128, warp tile 32x32 (4m x 4n warp grid), K-chunk 64.
#define P_SUB 16384
#define P_BUF (4 * P_SUB)
#define PROJ_SMEM (1024 + 2 * P_BUF)
__global__ __launch_bounds__(512, 1) void proj_mma_kernel() {
    extern __shared__ char smraw[];
    char* sm = (char*)(((uintptr_t)smraw + 1023) & ~(uintptr_t)1023);
    const uint32_t smb = smem_u32(sm);
    const int tid = threadIdx.x, wid = tid >> 5, lane = tid & 31;
    const int b = blockIdx.z, m0 = blockIdx.y * 128, n0 = blockIdx.x * 128;

    const char* gAh = (const char*)g_xn_hi + (size_t)(b * L_ + m0) * 1024;
    const char* gAl = (const char*)g_xn_lo + (size_t)(b * L_ + m0) * 1024;
    const char* gBh = (const char*)g_wqkv_hi + (size_t)n0 * 1024;
    const char* gBl = (const char*)g_wqkv_lo + (size_t)n0 * 1024;

    auto stage = [&](int it, int buf) {
        const uint32_t sb = smb + buf * P_BUF;
        #pragma unroll
        for (int p = 0; p < 2; ++p) {
            int e = tid + (p << 9);
            int row = e >> 3;
            int sg = (e & 7) << 4;
            size_t go = (size_t)row * 1024 + (size_t)it * 128 + sg;
            uint32_t s = SWZ((row << 7) + sg);
            cp16(sb + s,             gAh + go);
            cp16(sb + P_SUB + s,     gAl + go);
            cp16(sb + 2 * P_SUB + s, gBh + go);
            cp16(sb + 3 * P_SUB + s, gBl + go);
        }
    };

    float acc[2][4][4];
    #pragma unroll
    for (int i = 0; i < 2; i++)
        #pragma unroll
        for (int j = 0; j < 4; j++)
            #pragma unroll
            for (int t = 0; t < 4; t++) acc[i][j][t] = 0.f;

    const int wm = (wid & 3) << 5, wn = (wid >> 2) << 5;   // 4m x 4n warps
    const int r = lane & 15, hf = lane >> 4;

    stage(0, 0);
    CP_COMMIT();
    #pragma unroll 1
    for (int it = 0; it < 8; ++it) {
        const int buf = it & 1;
        if (it + 1 < 8) { stage(it + 1, buf ^ 1); CP_COMMIT(); CP_WAIT(1); }
        else CP_WAIT(0);
        __syncthreads();
        const uint32_t sA = smb + buf * P_BUF, sAl = sA + P_SUB;
        const uint32_t sB = sA + 2 * P_SUB, sBl = sA + 3 * P_SUB;
        #pragma unroll
        for (int ks = 0; ks < 4; ++ks) {
            const int kb = ks << 5;
            uint32_t ah[2][4], al[2][4];
            #pragma unroll
            for (int mt = 0; mt < 2; ++mt) {
                uint32_t rel = SWZ(((wm + (mt << 4) + r) << 7) + kb + (hf << 4));
                ldmx4(ah[mt], sA + rel);
                ldmx4(al[mt], sAl + rel);
            }
            uint32_t bh[2][4], bl[2][4];
            #pragma unroll
            for (int np = 0; np < 2; ++np) {
                uint32_t rel = SWZ(((wn + (np << 4) + r) << 7) + kb + (hf << 4));
                ldmx4(bh[np], sB + rel);
                ldmx4(bl[np], sBl + rel);
            }
            #pragma unroll
            for (int mt = 0; mt < 2; ++mt)
                #pragma unroll
                for (int np = 0; np < 2; ++np)
                    #pragma unroll
                    for (int sub = 0; sub < 2; ++sub) {
                        float* c = acc[mt][np * 2 + sub];
                        mma16816(c, ah[mt], bh[np][sub], bh[np][sub + 2]);
                        mma16816(c, ah[mt], bl[np][sub], bl[np][sub + 2]);
                        mma16816(c, al[mt], bh[np][sub], bh[np][sub + 2]);
                    }
        }
        __syncthreads();
    }

    const int region = n0 >> 9;                 // 0=q,1=k,2=v
    const int head = (n0 >> 7) & 3;
    const float scale = (region == 0) ? QSCALE : 1.0f;
    __nv_bfloat16 *dh, *dl;
    if (region == 0)      { dh = g_q_hi; dl = g_q_lo; }
    else if (region == 1) { dh = g_k_hi; dl = g_k_lo; }
    else                  { dh = g_v_hi; dl = g_v_lo; }
    const size_t bnbase = (size_t)(b * NH_ + head) * L_ * D_;
    const int lrow = lane >> 2, lcol = (lane & 3) << 1;
    #pragma unroll
    for (int mt = 0; mt < 2; ++mt) {
        #pragma unroll
        for (int nt = 0; nt < 4; ++nt) {
            const float* c = acc[mt][nt];
            const int d0 = wn + (nt << 3) + lcol;
            #pragma unroll
            for (int half = 0; half < 2; ++half) {
                int lv = m0 + wm + (mt << 4) + lrow + half * 8;
                float v0 = c[half * 2 + 0] * scale;
                float v1 = c[half * 2 + 1] * scale;
                size_t base = bnbase + ((size_t)lv << 7) + d0;
                uint32_t lo;
                uint32_t hi = pack_hl(v0, v1, lo);
                *(uint32_t*)(dh + base) = hi;
                *(uint32_t*)(dl + base) = lo;
            }
        }
    }
}

// ---------------- fused flash attention + rel-pos + residual ----------------
// grid (8 m-tiles, 32 bn), 256 threads = 8 warps, each warp 16 rows.
// smem: rdot 64KB | Q-lo 32KB (persistent) | 2 stages x 64KB (Kh|Kl|Vh|Vl)
#define FA_QLO 65536
#define FA_STG 98304
#define FA_STAGE 65536
#define FA_SMEM (1024 + FA_STG + 2 * FA_STAGE)   // 230400 bytes
__global__ __launch_bounds__(256, 1) void flash_kernel(const float* __restrict__ x) {
    extern __shared__ char smraw[];
    char* sm = (char*)(((uintptr_t)smraw + 1023) & ~(uintptr_t)1023);
    const uint32_t smb = smem_u32(sm);
    const int tid = threadIdx.x, wid = tid >> 5, lane = tid & 31;
    const int m0 = blockIdx.x * 128, bn = blockIdx.y;
    const int b = bn >> 2, head = bn & 3;
    const int r = lane & 15, hf = lane >> 4;
    const int r2 = lane >> 2, lcol = (lane & 3) << 1;
    const int tj = (lane & 7) + ((lane >> 4) << 3);
    const int tn = ((lane >> 3) & 1) << 3;
    const int wm = wid << 4;

    // Q: hi staged into stage buf 1 temporarily -> regs; lo -> persistent smem
    uint32_t qh[8][4];
    {
        const char* gQh = (const char*)g_q_hi + ((size_t)bn * L_ + m0) * 256;
        const char* gQl = (const char*)g_q_lo + ((size_t)bn * L_ + m0) * 256;
        const uint32_t sbq = smb + FA_STG + FA_STAGE;
        const uint32_t sbl = smb + FA_QLO;
        #pragma unroll
        for (int p = 0; p < 8; ++p) {
            int e = tid + (p << 8);
            int row = e >> 4, sg = (e & 15) << 4;
            uint32_t s = ((sg >> 7) << 14) + SWZ((row << 7) + (sg & 127));
            size_t go = (size_t)row * 256 + sg;
            cp16(sbq + s, gQh + go);
            cp16(sbl + s, gQl + go);
        }
        CP_COMMIT(); CP_WAIT(0); __syncthreads();
        #pragma unroll
        for (int ks = 0; ks < 8; ++ks) {
            int ab = (ks << 5) + (hf << 4);
            uint32_t rel = ((ab >> 7) << 14) + SWZ(((wm + r) << 7) + (ab & 127));
            ldmx4(qh[ks], sbq + rel);
        }
        __syncthreads();
    }

    // ---- prologue: rdot = Q @ rel^T into rdot smem ----
    {
        const char* gRh = (const char*)g_rel_hi;
        const char* gRl = (const char*)g_rel_lo;
        const uint32_t sb = smb + FA_STG;
        #pragma unroll
        for (int p = 0; p < 8; ++p) {
            int e = tid + (p << 8);
            int row = e >> 4, sg = (e & 15) << 4;
            uint32_t s = ((sg >> 7) << 14) + SWZ((row << 7) + (sg & 127));
            size_t go = (size_t)row * 256 + sg;
            cp16(sb + s,         gRh + go);
            cp16(sb + 32768 + s, gRl + go);
        }
        CP_COMMIT(); CP_WAIT(0); __syncthreads();
        float* rsm = (float*)sm;
        #pragma unroll 1
        for (int ss2 = 0; ss2 < 4; ++ss2) {
            float rs[4][4];
            #pragma unroll
            for (int t = 0; t < 4; ++t)
                #pragma unroll
                for (int u = 0; u < 4; ++u) rs[t][u] = 0.f;
            #pragma unroll
            for (int ks = 0; ks < 8; ++ks) {
                const int ab = (ks << 5) + (hf << 4);
                uint32_t qlf[4];
                {
                    uint32_t rel = ((ab >> 7) << 14) + SWZ(((wm + r) << 7) + (ab & 127));
                    ldmx4(qlf, smb + FA_QLO + rel);
                }
                uint32_t bhf[2][4], blf[2][4];
                #pragma unroll
                for (int np = 0; np < 2; ++np) {
                    int jr = (ss2 << 5) + (np << 4) + r;
                    uint32_t rel = ((ab >> 7) << 14) + SWZ((jr << 7) + (ab & 127));
                    ldmx4(bhf[np], sb + rel);
                    ldmx4(blf[np], sb + 32768 + rel);
                }
                #pragma unroll
                for (int np = 0; np < 2; ++np)
                    #pragma unroll
                    for (int sub = 0; sub < 2; ++sub) {
                        float* c = rs[np * 2 + sub];
                        mma16816(c, qh[ks], bhf[np][sub], bhf[np][sub + 2]);
                        mma16816(c, qh[ks], blf[np][sub], blf[np][sub + 2]);
                        mma16816(c, qlf,    bhf[np][sub], bhf[np][sub + 2]);
                    }
            }
            const int j0 = ss2 << 5;
            #pragma unroll
            for (int t = 0; t < 4; ++t) {
                int jj = j0 + (t << 3) + lcol;
                rsm[(wm + r2) * 128 + jj]           = rs[t][0];
                rsm[(wm + r2) * 128 + jj + 1]       = rs[t][1];
                rsm[(wm + r2 + 8) * 128 + jj]       = rs[t][2];
                rsm[(wm + r2 + 8) * 128 + jj + 1]   = rs[t][3];
            }
        }
        __syncthreads();
    }

    const char* gKh = (const char*)g_k_hi + (size_t)bn * L_ * 256;
    const char* gKl = (const char*)g_k_lo + (size_t)bn * L_ * 256;
    const char* gVh = (const char*)g_v_hi + (size_t)bn * L_ * 256;
    const char* gVl = (const char*)g_v_lo + (size_t)bn * L_ * 256;

    auto stageKV = [&](int jt, int buf) {
        const uint32_t sb = smb + FA_STG + buf * FA_STAGE;
        const size_t base = (size_t)(jt * 64) * 256;
        #pragma unroll
        for (int p = 0; p < 4; ++p) {
            int e = tid + (p << 8);
            int row = e >> 4, sg = (e & 15) << 4;
            uint32_t s = ((sg >> 7) << 13) + SWZ((row << 7) + (sg & 127));
            size_t go = base + (size_t)row * 256 + sg;
            cp16(sb + s,          gKh + go);
            cp16(sb + 16384 + s,  gKl + go);
            cp16(sb + 32768 + s,  gVh + go);
            cp16(sb + 49152 + s,  gVl + go);
        }
    };

    const int i0 = m0 + wm + r2, i1 = i0 + 8;
    const int h0 = i0 >> 5, w0 = i0 & 31;
    const int h1 = i1 >> 5, w1 = i1 & 31;
    const float* rd0 = (const float*)(sm + (size_t)(wm + r2) * 512);
    const float* rd1 = (const float*)(sm + (size_t)(wm + r2 + 8) * 512);

    float o[16][4];
    #pragma unroll
    for (int nt = 0; nt < 16; ++nt)
        #pragma unroll
        for (int u = 0; u < 4; ++u) o[nt][u] = 0.f;
    float m0r = -1e30f, m1r = -1e30f, s0r = 0.f, s1r = 0.f;

    stageKV(0, 0);
    CP_COMMIT();

    #pragma unroll 1
    for (int jt = 0; jt < 16; ++jt) {
        const int buf = jt & 1;
        if (jt + 1 < 16) { stageKV(jt + 1, buf ^ 1); CP_COMMIT(); CP_WAIT(1); }
        else CP_WAIT(0);
        __syncthreads();
        const uint32_t kb_s = smb + FA_STG + buf * FA_STAGE;
        const uint32_t vb_s = kb_s + 32768;

        #pragma unroll
        for (int ss = 0; ss < 2; ++ss) {
            float s[4][4];
            #pragma unroll
            for (int t = 0; t < 4; ++t)
                #pragma unroll
                for (int u = 0; u < 4; ++u) s[t][u] = 0.f;
            #pragma unroll
            for (int ks = 0; ks < 8; ++ks) {
                const int ab = (ks << 5) + (hf << 4);
                uint32_t qlf[4];
                {
                    uint32_t rel = ((ab >> 7) << 14) + SWZ(((wm + r) << 7) + (ab & 127));
                    ldmx4(qlf, smb + FA_QLO + rel);
                }
                uint32_t bhf[2][4], blf[2][4];
                #pragma unroll
                for (int np = 0; np < 2; ++np) {
                    int jr = (ss << 5) + (np << 4) + r;
                    uint32_t rel = ((ab >> 7) << 13) + SWZ((jr << 7) + (ab & 127));
                    ldmx4(bhf[np], kb_s + rel);
                    ldmx4(blf[np], kb_s + 16384 + rel);
                }
                #pragma unroll
                for (int np = 0; np < 2; ++np)
                    #pragma unroll
                    for (int sub = 0; sub < 2; ++sub) {
                        float* c = s[np * 2 + sub];
                        mma16816(c, qh[ks], bhf[np][sub], bhf[np][sub + 2]);
                        mma16816(c, qh[ks], blf[np][sub], blf[np][sub + 2]);
                        mma16816(c, qlf,    bhf[np][sub], bhf[np][sub + 2]);
                    }
            }

            const int j0 = jt * 64 + (ss << 5);
            float t0 = -1e30f, t1 = -1e30f;
            #pragma unroll
            for (int t = 0; t < 4; ++t) {
                int jj = j0 + t * 8 + lcol;
                int h2 = jj >> 5, w2 = jj & 31;
                float bh0 = rd0[94 + h2 - h0];
                float bh1 = rd1[94 + h2 - h1];
                s[t][0] += rd0[w2 - w0 + 31] + bh0;
                s[t][1] += rd0[w2 + 1 - w0 + 31] + bh0;
                s[t][2] += rd1[w2 - w1 + 31] + bh1;
                s[t][3] += rd1[w2 + 1 - w1 + 31] + bh1;
                t0 = fmaxf(t0, fmaxf(s[t][0], s[t][1]));
                t1 = fmaxf(t1, fmaxf(s[t][2], s[t][3]));
            }
            t0 = fmaxf(t0, __shfl_xor_sync(~0u, t0, 1));
            t0 = fmaxf(t0, __shfl_xor_sync(~0u, t0, 2));
            t1 = fmaxf(t1, __shfl_xor_sync(~0u, t1, 1));
            t1 = fmaxf(t1, __shfl_xor_sync(~0u, t1, 2));

            float mn0 = fmaxf(m0r, t0), mn1 = fmaxf(m1r, t1);
            float a0 = __expf(m0r - mn0), a1 = __expf(m1r - mn1);
            if (!(a0 == 1.0f && a1 == 1.0f)) {
                #pragma unroll
                for (int nt = 0; nt < 16; ++nt) {
                    o[nt][0] *= a0; o[nt][1] *= a0; o[nt][2] *= a1; o[nt][3] *= a1;
                }
            }
            uint32_t ph[2][4], pl[2][4];
            float ts0 = 0.f, ts1 = 0.f;
            #pragma unroll
            for (int t = 0; t < 4; ++t) {
                float p0 = __expf(s[t][0] - mn0), p1 = __expf(s[t][1] - mn0);
                float p2 = __expf(s[t][2] - mn1), p3 = __expf(s[t][3] - mn1);
                ts0 += p0 + p1; ts1 += p2 + p3;
                int kt = t >> 1, wc = (t & 1) << 1;
                ph[kt][wc]     = pack_hl(p0, p1, pl[kt][wc]);
                ph[kt][wc + 1] = pack_hl(p2, p3, pl[kt][wc + 1]);
            }
            ts0 += __shfl_xor_sync(~0u, ts0, 1); ts0 += __shfl_xor_sync(~0u, ts0, 2);
            ts1 += __shfl_xor_sync(~0u, ts1, 1); ts1 += __shfl_xor_sync(~0u, ts1, 2);
            s0r = s0r * a0 + ts0; s1r = s1r * a1 + ts1;
            m0r = mn0; m1r = mn1;

            #pragma unroll
            for (int kt = 0; kt < 2; ++kt) {
                #pragma unroll
                for (int np = 0; np < 8; ++np) {
                    int jrow = (ss << 5) + (kt << 4) + tj;
                    int db = ((np << 4) + tn) << 1;
                    uint32_t rel = ((db >> 7) << 13) + SWZ((jrow << 7) + (db & 127));
                    uint32_t vh4[4], vl4[4];
                    ldmx4t(vh4, vb_s + rel);
                    ldmx4t(vl4, vb_s + 16384 + rel);
                    #pragma unroll
                    for (int sub = 0; sub < 2; ++sub) {
                        float* c = o[np * 2 + sub];
                        mma16816(c, ph[kt], vh4[sub], vh4[sub + 2]);
                        mma16816(c, ph[kt], vl4[sub], vl4[sub + 2]);
                        mma16816(c, pl[kt], vh4[sub], vh4[sub + 2]);
                    }
                }
            }
        }
        __syncthreads();
    }

    // ---- epilogue: normalize -> smem transpose -> coalesced residual+store ----
    __syncthreads();
    float* so = (float*)sm;
    const float inv0 = 1.f / s0r, inv1 = 1.f / s1r;
    #pragma unroll
    for (int nt = 0; nt < 16; ++nt) {
        const int d0 = (nt << 3) + lcol;
        #pragma unroll
        for (int u = 0; u < 2; ++u) {
            so[(d0 + u) * 136 + wm + r2]     = o[nt][u] * inv0;
            so[(d0 + u) * 136 + wm + r2 + 8] = o[nt][2 + u] * inv1;
        }
    }
    __syncthreads();
    #pragma unroll
    for (int ch = 0; ch < 16; ++ch) {
        const int d = (ch << 3) + (tid >> 5);
        const int i4 = (tid & 31) << 2;
        const size_t idx = ((size_t)(b * C_ + head * D_ + d) << 10) + m0 + i4;
        float4 xr = *(const float4*)(x + idx);
        float4 ov = *(const float4*)(so + d * 136 + i4);
        ov.x += xr.x; ov.y += xr.y; ov.z += xr.z; ov.w += xr.w;
        *(float4*)(g_xres + idx) = ov;
    }
}

// ---------------- conv GEMM via mma.sync bf16 (hi/lo), implicit im2col ----------------
// tile M=128 (o) x N=256 (l); grid (4,4,8) = 128 CTAs. 512 threads / 16 warps,
// warp grid 4m x 4n, warp tile 32x64.
#define NCHUNK 72
#define CV_SUBA 16384
#define CV_SUBB 32768
#define CV_BUF (2 * CV_SUBA + 2 * CV_SUBB)   // 96KB
#define CONV_SMEM (1024 + 2 * CV_BUF)
__global__ __launch_bounds__(512, 1) void conv_mma_kernel(const float* __restrict__ bias_fc,
                                                          float* __restrict__ out) {
    extern __shared__ char smraw[];
    char* sm = (char*)(((uintptr_t)smraw + 1023) & ~(uintptr_t)1023);
    const uint32_t smb = smem_u32(sm);
    const int tid = threadIdx.x, wid = tid >> 5, lane = tid & 31;
    const int bb = blockIdx.z, m0 = blockIdx.y * 128, n0 = blockIdx.x * 256;

    const char* gAh = (const char*)g_w_hi  + (size_t)m0 * (KC_ * 2);
    const char* gAl = (const char*)g_w_lo  + (size_t)m0 * (KC_ * 2);
    const char* yh  = (const char*)g_y2t_hi + (size_t)bb * L_ * 1024;
    const char* yl  = (const char*)g_y2t_lo + (size_t)bb * L_ * 1024;

    auto stage = [&](int it, int buf) {
        const size_t koff = (size_t)it * 128;
        const uint32_t sb = smb + buf * CV_BUF;
        #pragma unroll
        for (int p = 0; p < 2; ++p) {   // A: 128 rows x 8 segs = 1024
            int e = tid + (p << 9);
            int row = e >> 3;
            int sg = (e & 7) << 4;
            size_t g = (size_t)row * (KC_ * 2) + koff + sg;
            uint32_t s = SWZ((row << 7) + sg);
            cp16(sb + s,           gAh + g);
            cp16(sb + CV_SUBA + s, gAl + g);
        }
        const int r9 = it >> 3;
        const int dh = r9 / 3 - 1, dw = r9 % 3 - 1;
        const int cb2 = ((it & 7) << 6) * 2;
        #pragma unroll
        for (int p = 0; p < 4; ++p) {   // B: 256 rows x 8 segs = 2048
            int e = tid + (p << 9);
            int row = e >> 3;
            int sg = (e & 7) << 4;
            uint32_t s = SWZ((row << 7) + sg);
            int l = n0 + row;
            int h = (l >> 5) + dh, w = (l & 31) + dw;
            if ((unsigned)h < 32u && (unsigned)w < 32u) {
                size_t g = ((size_t)(l + dh * 32 + dw) << 10) + cb2 + sg;
                cp16(sb + 2 * CV_SUBA + s,           yh + g);
                cp16(sb + 2 * CV_SUBA + CV_SUBB + s, yl + g);
            } else {
                uint4 z = make_uint4(0u, 0u, 0u, 0u);
                *(uint4*)(sm + ((size_t)buf * CV_BUF + 2 * CV_SUBA + s)) = z;
                *(uint4*)(sm + ((size_t)buf * CV_BUF + 2 * CV_SUBA + CV_SUBB + s)) = z;
            }
        }
    };

    float acc[2][8][4];
    #pragma unroll
    for (int i = 0; i < 2; i++)
        #pragma unroll
        for (int j = 0; j < 8; j++)
            #pragma unroll
            for (int t = 0; t < 4; t++) acc[i][j][t] = 0.f;

    const int wm = (wid & 3) << 5, wn = (wid >> 2) << 6;   // 4m x 4n warps
    const int r = lane & 15, hf = lane >> 4;

    stage(0, 0);
    CP_COMMIT();
    #pragma unroll 1
    for (int it = 0; it < NCHUNK; ++it) {
        const int buf = it & 1;
        if (it + 1 < NCHUNK) { stage(it + 1, buf ^ 1); CP_COMMIT(); CP_WAIT(1); }
        else CP_WAIT(0);
        __syncthreads();
        const uint32_t sA = smb + buf * CV_BUF, sAl = sA + CV_SUBA;
        const uint32_t sB = sA + 2 * CV_SUBA, sBl = sB + CV_SUBB;
        #pragma unroll
        for (int ks = 0; ks < 4; ++ks) {
            const int kb = ks << 5;
            uint32_t ah[2][4], al[2][4];
            #pragma unroll
            for (int mt = 0; mt < 2; ++mt) {
                uint32_t rel = SWZ(((wm + (mt << 4) + r) << 7) + kb + (hf << 4));
                ldmx4(ah[mt], sA + rel);
                ldmx4(al[mt], sAl + rel);
            }
            #pragma unroll
            for (int np = 0; np < 4; ++np) {
                uint32_t rel = SWZ(((wn + (np << 4) + r) << 7) + kb + (hf << 4));
                uint32_t bh[4], bl[4];
                ldmx4(bh, sB + rel);
                ldmx4(bl, sBl + rel);
                #pragma unroll
                for (int mt = 0; mt < 2; ++mt)
                    #pragma unroll
                    for (int sub = 0; sub < 2; ++sub) {
                        float* c = acc[mt][np * 2 + sub];
                        mma16816(c, ah[mt], bh[sub], bh[sub + 2]);
                        mma16816(c, ah[mt], bl[sub], bl[sub + 2]);
                        mma16816(c, al[mt], bh[sub], bh[sub + 2]);
                    }
            }
        }
        __syncthreads();
    }

    const int lrow = lane >> 2, lcol = (lane & 3) << 1;
    #pragma unroll
    for (int mt = 0; mt < 2; ++mt) {
        #pragma unroll
        for (int nt = 0; nt < 8; ++nt) {
            const float* c = acc[mt][nt];
            int l = n0 + wn + (nt << 3) + lcol;
            #pragma unroll
            for (int half = 0; half < 2; ++half) {
                int o = m0 + wm + (mt << 4) + lrow + half * 8;
                float bv = bias_fc[o];
                size_t idx = ((size_t)(bb * C_ + o) << 10) + l;
                float2 xr = *(const float2*)(g_xres + idx);
                float2 o2;
                o2.x = c[half * 2 + 0] + bv + xr.x;
                o2.y = c[half * 2 + 1] + bv + xr.y;
                *(float2*)(out + idx) = o2;
            }
        }
    }
}

// ---------------- launch ----------------
extern "C" void kernel_launch(void* const* d_in, const int* in_sizes, int n_in,
                              void* d_out, int out_size) {
    const float* x       = (const float*)d_in[0];
    const float* w_qk    = (const float*)d_in[1];
    const float* w_v     = (const float*)d_in[2];
    const float* rel_h   = (const float*)d_in[3];
    const float* rel_w   = (const float*)d_in[4];
    const float* g1      = (const float*)d_in[5];
    const float* b1      = (const float*)d_in[6];
    const float* m1      = (const float*)d_in[7];
    const float* v1      = (const float*)d_in[8];
    const float* g2      = (const float*)d_in[9];
    const float* b2      = (const float*)d_in[10];
    const float* m2      = (const float*)d_in[11];
    const float* v2      = (const float*)d_in[12];
    const float* w_fc    = (const float*)d_in[13];
    const float* bias_fc = (const float*)d_in[14];
    float* out = (float*)d_out;

    cudaFuncSetAttribute(proj_mma_kernel, cudaFuncAttributeMaxDynamicSharedMemorySize, PROJ_SMEM);
    cudaFuncSetAttribute(flash_kernel,    cudaFuncAttributeMaxDynamicSharedMemorySize, FA_SMEM);
    cudaFuncSetAttribute(conv_mma_kernel, cudaFuncAttributeMaxDynamicSharedMemorySize, CONV_SMEM);

    wqkv2bf_kernel<<<(1536 * 512 + 16384) / 256, 256>>>(w_qk, w_v, rel_h, rel_w);
    w2bf_kernel<<<(C_ * KC_) / 256, 256>>>(w_fc);
    bn1t_kernel<<<dim3(32, 16, B_), 256>>>(x, g1, b1, m1, v1);
    proj_mma_kernel<<<dim3(12, 8, B_), 512, PROJ_SMEM>>>();
    flash_kernel<<<dim3(8, 32), 256, FA_SMEM>>>(x);
    bn2t_kernel<<<dim3(32, 16, B_), 256>>>(g2, b2, m2, v2);
    conv_mma_kernel<<<dim3(4, 4, B_), 512, CONV_SMEM>>>(bias_fc, out);
}

// round 12
// speedup vs baseline: 1.2114x; 1.2114x over previous
#include <cuda_runtime.h>
#include <cuda_bf16.h>
#include <cuda_fp16.h>
#include <cstdint>

// ---------------- problem constants ----------------
#define B_   8
#define C_   512
#define HH_  32
#define WW_  32
#define L_   1024          // HH*WW
#define NH_  4
#define D_   128
#define KC_  4608          // 512*9 (im2col K)
#define QSCALE 0.08838834764831845f  // 128^-0.5

// ---------------- scratch (device globals; no allocations) ----------------
__device__ __nv_bfloat16 g_xn_hi[B_*L_*C_];        // relu(bn1(x)) transposed [b][l][c]
__device__ __nv_bfloat16 g_xn_lo[B_*L_*C_];
__device__ __nv_bfloat16 g_wqkv_hi[1536*512];      // [o][c], o: q|k|v
__device__ __nv_bfloat16 g_wqkv_lo[1536*512];
__device__ __nv_bfloat16 g_rel_hi[128*128];        // rows: 0..62 rel_w, 63..125 rel_h, 126..127 zero
__device__ __nv_bfloat16 g_rel_lo[128*128];
__device__ __nv_bfloat16 g_q_hi[32*L_*D_];         // [bn][l][d] (scaled)
__device__ __nv_bfloat16 g_q_lo[32*L_*D_];
__device__ __nv_bfloat16 g_k_hi[32*L_*D_];
__device__ __nv_bfloat16 g_k_lo[32*L_*D_];
__device__ __nv_bfloat16 g_v_hi[32*L_*D_];
__device__ __nv_bfloat16 g_v_lo[32*L_*D_];
__device__ float g_xres[B_*C_*L_];                 // mhsa out + x
__device__ __half g_y2t_hi[B_*L_*C_];              // relu(bn2(xres)) transposed [b][l][c] fp16 hi/lo
__device__ __half g_y2t_lo[B_*L_*C_];
__device__ __half g_w_f[(size_t)C_*KC_];           // conv weights fp16, reordered [o][r9*512 + c]

// ================= mma.sync helpers =================
__device__ __forceinline__ uint32_t smem_u32(const void* p) {
    uint32_t a;
    asm("{ .reg .u64 t; cvta.to.shared.u64 t, %1; cvt.u32.u64 %0, t; }" : "=r"(a) : "l"(p));
    return a;
}
__device__ __forceinline__ void cp16(uint32_t s, const void* g) {
    asm volatile("cp.async.cg.shared.global [%0], [%1], 16;" :: "r"(s), "l"(g));
}
#define CP_COMMIT() asm volatile("cp.async.commit_group;" ::: "memory")
#define CP_WAIT(n)  asm volatile("cp.async.wait_group %0;" :: "n"(n) : "memory")

__device__ __forceinline__ void ldmx4(uint32_t* d, uint32_t addr) {
    asm volatile("ldmatrix.sync.aligned.m8n8.x4.shared.b16 {%0,%1,%2,%3}, [%4];"
                 : "=r"(d[0]), "=r"(d[1]), "=r"(d[2]), "=r"(d[3]) : "r"(addr));
}
__device__ __forceinline__ void ldmx4t(uint32_t* d, uint32_t addr) {
    asm volatile("ldmatrix.sync.aligned.m8n8.x4.trans.shared.b16 {%0,%1,%2,%3}, [%4];"
                 : "=r"(d[0]), "=r"(d[1]), "=r"(d[2]), "=r"(d[3]) : "r"(addr));
}
__device__ __forceinline__ void mma16816(float* c, const uint32_t* a, uint32_t b0, uint32_t b1) {
    asm volatile("mma.sync.aligned.m16n8k16.row.col.f32.bf16.bf16.f32 "
                 "{%0,%1,%2,%3}, {%4,%5,%6,%7}, {%8,%9}, {%0,%1,%2,%3};"
                 : "+f"(c[0]), "+f"(c[1]), "+f"(c[2]), "+f"(c[3])
                 : "r"(a[0]), "r"(a[1]), "r"(a[2]), "r"(a[3]), "r"(b0), "r"(b1));
}
__device__ __forceinline__ void mma16816h(float* c, const uint32_t* a, uint32_t b0, uint32_t b1) {
    asm volatile("mma.sync.aligned.m16n8k16.row.col.f32.f16.f16.f32 "
                 "{%0,%1,%2,%3}, {%4,%5,%6,%7}, {%8,%9}, {%0,%1,%2,%3};"
                 : "+f"(c[0]), "+f"(c[1]), "+f"(c[2]), "+f"(c[3])
                 : "r"(a[0]), "r"(a[1]), "r"(a[2]), "r"(a[3]), "r"(b0), "r"(b1));
}
#define SWZ(x) ((x) ^ (((x) >> 3) & 0x70))

__device__ __forceinline__ void hilo(float v, __nv_bfloat16& h, __nv_bfloat16& l) {
    h = __float2bfloat16(v);
    l = __float2bfloat16(v - __bfloat162float(h));
}
__device__ __forceinline__ void hilo_h(float v, __half& h, __half& l) {
    h = __float2half(v);
    l = __float2half(v - __half2float(h));
}
__device__ __forceinline__ uint32_t pack_hl(float a, float b, uint32_t& lo_out) {
    __nv_bfloat16 ah, al, bh, bl;
    hilo(a, ah, al); hilo(b, bh, bl);
    __nv_bfloat162 hp; hp.x = ah; hp.y = bh;
    __nv_bfloat162 lp; lp.x = al; lp.y = bl;
    lo_out = *(uint32_t*)&lp;
    return *(uint32_t*)&hp;
}

// ---------------- BN1 + ReLU + transpose -> bf16 hi/lo [b][l][c] ----------------
__global__ void bn1t_kernel(const float* __restrict__ x,
                            const float* __restrict__ g, const float* __restrict__ bb,
                            const float* __restrict__ m, const float* __restrict__ v) {
    __shared__ float t[32][33];
    const int b = blockIdx.z, c0 = blockIdx.y * 32, l0 = blockIdx.x * 32;
    const int tid = threadIdx.x;
    {
        const int cr = tid >> 3, l4 = (tid & 7) * 4;
        const int c = c0 + cr;
        float inv = g[c] * rsqrtf(v[c] + 1e-5f);
        float sh  = bb[c] - m[c] * inv;
        float4 xv = *(const float4*)(x + ((size_t)(b * C_ + c) << 10) + l0 + l4);
        t[cr][l4 + 0] = fmaxf(fmaf(xv.x, inv, sh), 0.f);
        t[cr][l4 + 1] = fmaxf(fmaf(xv.y, inv, sh), 0.f);
        t[cr][l4 + 2] = fmaxf(fmaf(xv.z, inv, sh), 0.f);
        t[cr][l4 + 3] = fmaxf(fmaf(xv.w, inv, sh), 0.f);
    }
    __syncthreads();
    {
        const int lr = tid >> 3, c4 = (tid & 7) * 4;
        __nv_bfloat16 h[4], lo[4];
        #pragma unroll
        for (int u = 0; u < 4; ++u) hilo(t[c4 + u][lr], h[u], lo[u]);
        size_t base = ((size_t)(b * L_ + l0 + lr) << 9) + c0 + c4;
        *(__nv_bfloat162*)(g_xn_hi + base)     = *(__nv_bfloat162*)&h[0];
        *(__nv_bfloat162*)(g_xn_hi + base + 2) = *(__nv_bfloat162*)&h[2];
        *(__nv_bfloat162*)(g_xn_lo + base)     = *(__nv_bfloat162*)&lo[0];
        *(__nv_bfloat162*)(g_xn_lo + base + 2) = *(__nv_bfloat162*)&lo[2];
    }
}

// ---------------- BN2 + ReLU + transpose -> fp16 hi/lo [b][l][c] ----------------
__global__ void bn2t_kernel(const float* __restrict__ g, const float* __restrict__ bb,
                            const float* __restrict__ m, const float* __restrict__ v) {
    __shared__ float t[32][33];
    const int b = blockIdx.z, c0 = blockIdx.y * 32, l0 = blockIdx.x * 32;
    const int tid = threadIdx.x;
    {
        const int cr = tid >> 3, l4 = (tid & 7) * 4;
        const int c = c0 + cr;
        float inv = g[c] * rsqrtf(v[c] + 1e-5f);
        float sh  = bb[c] - m[c] * inv;
        float4 xv = *(const float4*)(g_xres + ((size_t)(b * C_ + c) << 10) + l0 + l4);
        t[cr][l4 + 0] = fmaxf(fmaf(xv.x, inv, sh), 0.f);
        t[cr][l4 + 1] = fmaxf(fmaf(xv.y, inv, sh), 0.f);
        t[cr][l4 + 2] = fmaxf(fmaf(xv.z, inv, sh), 0.f);
        t[cr][l4 + 3] = fmaxf(fmaf(xv.w, inv, sh), 0.f);
    }
    __syncthreads();
    {
        const int lr = tid >> 3, c4 = (tid & 7) * 4;
        __half h[4], lo[4];
        #pragma unroll
        for (int u = 0; u < 4; ++u) hilo_h(t[c4 + u][lr], h[u], lo[u]);
        size_t base = ((size_t)(b * L_ + l0 + lr) << 9) + c0 + c4;
        *(__half2*)(g_y2t_hi + base)     = *(__half2*)&h[0];
        *(__half2*)(g_y2t_hi + base + 2) = *(__half2*)&h[2];
        *(__half2*)(g_y2t_lo + base)     = *(__half2*)&lo[0];
        *(__half2*)(g_y2t_lo + base + 2) = *(__half2*)&lo[2];
    }
}

// ---------------- qkv weights + rel tables -> bf16 hi/lo ----------------
__global__ void wqkv2bf_kernel(const float* __restrict__ w_qk, const float* __restrict__ w_v,
                               const float* __restrict__ rel_h, const float* __restrict__ rel_w) {
    int i = blockIdx.x * 256 + threadIdx.x;
    if (i < 1024 * 512) {
        hilo(w_qk[i], g_wqkv_hi[i], g_wqkv_lo[i]);
    } else if (i < 1536 * 512) {
        hilo(w_v[i - 1024 * 512], g_wqkv_hi[i], g_wqkv_lo[i]);
    } else {
        int j = i - 1536 * 512;          // 0..16383
        int rr = j >> 7, d = j & 127;
        float val = 0.f;
        if (rr < 63)       val = rel_w[rr * 128 + d];
        else if (rr < 126) val = rel_h[(rr - 63) * 128 + d];
        hilo(val, g_rel_hi[j], g_rel_lo[j]);
    }
}

// ---------------- conv weights -> fp16 single, reorder k' = r9*512 + c ----------------
__global__ void w2bf_kernel(const float* __restrict__ w) {
    int i = blockIdx.x * 256 + threadIdx.x;   // src: o*4608 + c*9 + r9
    int o = i / KC_, rem = i % KC_;
    int c = rem / 9, r9 = rem % 9;
    size_t dst = (size_t)o * KC_ + r9 * 512 + c;
    g_w_f[dst] = __float2half(w[i]);
}

// ---------------- QKV projection via mma.sync (256 threads) ----------------
#define P_SUB 16384
#define P_BUF (4 * P_SUB)
#define PROJ_SMEM (1024 + 2 * P_BUF)
__global__ __launch_bounds__(256, 1) void proj_mma_kernel() {
    extern __shared__ char smraw[];
    char* sm = (char*)(((uintptr_t)smraw + 1023) & ~(uintptr_t)1023);
    const uint32_t smb = smem_u32(sm);
    const int tid = threadIdx.x, wid = tid >> 5, lane = tid & 31;
    const int b = blockIdx.z, m0 = blockIdx.y * 128, n0 = blockIdx.x * 128;

    const char* gAh = (const char*)g_xn_hi + (size_t)(b * L_ + m0) * 1024;
    const char* gAl = (const char*)g_xn_lo + (size_t)(b * L_ + m0) * 1024;
    const char* gBh = (const char*)g_wqkv_hi + (size_t)n0 * 1024;
    const char* gBl = (const char*)g_wqkv_lo + (size_t)n0 * 1024;

    auto stage = [&](int it, int buf) {
        const uint32_t sb = smb + buf * P_BUF;
        #pragma unroll
        for (int p = 0; p < 4; ++p) {
            int e = tid + (p << 8);
            int row = e >> 3;
            int sg = (e & 7) << 4;
            size_t go = (size_t)row * 1024 + (size_t)it * 128 + sg;
            uint32_t s = SWZ((row << 7) + sg);
            cp16(sb + s,             gAh + go);
            cp16(sb + P_SUB + s,     gAl + go);
            cp16(sb + 2 * P_SUB + s, gBh + go);
            cp16(sb + 3 * P_SUB + s, gBl + go);
        }
    };

    float acc[2][8][4];
    #pragma unroll
    for (int i = 0; i < 2; i++)
        #pragma unroll
        for (int j = 0; j < 8; j++)
            #pragma unroll
            for (int t = 0; t < 4; t++) acc[i][j][t] = 0.f;

    const int wm = (wid & 3) << 5, wn = (wid >> 2) << 6;
    const int r = lane & 15, hf = lane >> 4;

    stage(0, 0);
    CP_COMMIT();
    #pragma unroll 1
    for (int it = 0; it < 8; ++it) {
        const int buf = it & 1;
        if (it + 1 < 8) { stage(it + 1, buf ^ 1); CP_COMMIT(); CP_WAIT(1); }
        else CP_WAIT(0);
        __syncthreads();
        const uint32_t sA = smb + buf * P_BUF, sAl = sA + P_SUB;
        const uint32_t sB = sA + 2 * P_SUB, sBl = sA + 3 * P_SUB;
        #pragma unroll
        for (int ks = 0; ks < 4; ++ks) {
            const int kb = ks << 5;
            uint32_t ah[2][4], al[2][4];
            #pragma unroll
            for (int mt = 0; mt < 2; ++mt) {
                uint32_t rel = SWZ(((wm + (mt << 4) + r) << 7) + kb + (hf << 4));
                ldmx4(ah[mt], sA + rel);
                ldmx4(al[mt], sAl + rel);
            }
            uint32_t bh[4][4], bl[4][4];
            #pragma unroll
            for (int np = 0; np < 4; ++np) {
                uint32_t rel = SWZ(((wn + (np << 4) + r) << 7) + kb + (hf << 4));
                ldmx4(bh[np], sB + rel);
                ldmx4(bl[np], sBl + rel);
            }
            #pragma unroll
            for (int mt = 0; mt < 2; ++mt)
                #pragma unroll
                for (int np = 0; np < 4; ++np)
                    #pragma unroll
                    for (int sub = 0; sub < 2; ++sub) {
                        float* c = acc[mt][np * 2 + sub];
                        mma16816(c, ah[mt], bh[np][sub], bh[np][sub + 2]);
                        mma16816(c, ah[mt], bl[np][sub], bl[np][sub + 2]);
                        mma16816(c, al[mt], bh[np][sub], bh[np][sub + 2]);
                    }
        }
        __syncthreads();
    }

    const int region = n0 >> 9;                 // 0=q,1=k,2=v
    const int head = (n0 >> 7) & 3;
    const float scale = (region == 0) ? QSCALE : 1.0f;
    __nv_bfloat16 *dh, *dl;
    if (region == 0)      { dh = g_q_hi; dl = g_q_lo; }
    else if (region == 1) { dh = g_k_hi; dl = g_k_lo; }
    else                  { dh = g_v_hi; dl = g_v_lo; }
    const size_t bnbase = (size_t)(b * NH_ + head) * L_ * D_;
    const int lrow = lane >> 2, lcol = (lane & 3) << 1;
    #pragma unroll
    for (int mt = 0; mt < 2; ++mt) {
        #pragma unroll
        for (int nt = 0; nt < 8; ++nt) {
            const float* c = acc[mt][nt];
            const int d0 = wn + (nt << 3) + lcol;
            #pragma unroll
            for (int half = 0; half < 2; ++half) {
                int lv = m0 + wm + (mt << 4) + lrow + half * 8;
                float v0 = c[half * 2 + 0] * scale;
                float v1 = c[half * 2 + 1] * scale;
                size_t base = bnbase + ((size_t)lv << 7) + d0;
                uint32_t lo;
                uint32_t hi = pack_hl(v0, v1, lo);
                *(uint32_t*)(dh + base) = hi;
                *(uint32_t*)(dl + base) = lo;
            }
        }
    }
}

// ---------------- fused flash attention + rel-pos + residual ----------------
// grid (8 m-tiles, 32 bn), 256 threads = 8 warps, each warp 16 rows.
// smem: rdot 64KB | Q-lo 32KB (persistent) | 2 stages x 64KB (Kh|Kl|Vh|Vl)
#define FA_QLO 65536
#define FA_STG 98304
#define FA_STAGE 65536
#define FA_SMEM (1024 + FA_STG + 2 * FA_STAGE)   // 230400 bytes
__global__ __launch_bounds__(256, 1) void flash_kernel(const float* __restrict__ x) {
    extern __shared__ char smraw[];
    char* sm = (char*)(((uintptr_t)smraw + 1023) & ~(uintptr_t)1023);
    const uint32_t smb = smem_u32(sm);
    const int tid = threadIdx.x, wid = tid >> 5, lane = tid & 31;
    const int m0 = blockIdx.x * 128, bn = blockIdx.y;
    const int b = bn >> 2, head = bn & 3;
    const int r = lane & 15, hf = lane >> 4;
    const int r2 = lane >> 2, lcol = (lane & 3) << 1;
    const int tj = (lane & 7) + ((lane >> 4) << 3);
    const int tn = ((lane >> 3) & 1) << 3;
    const int wm = wid << 4;

    // Q: hi staged into stage buf 1 temporarily -> regs; lo -> persistent smem
    uint32_t qh[8][4];
    {
        const char* gQh = (const char*)g_q_hi + ((size_t)bn * L_ + m0) * 256;
        const char* gQl = (const char*)g_q_lo + ((size_t)bn * L_ + m0) * 256;
        const uint32_t sbq = smb + FA_STG + FA_STAGE;
        const uint32_t sbl = smb + FA_QLO;
        #pragma unroll
        for (int p = 0; p < 8; ++p) {
            int e = tid + (p << 8);
            int row = e >> 4, sg = (e & 15) << 4;
            uint32_t s = ((sg >> 7) << 14) + SWZ((row << 7) + (sg & 127));
            size_t go = (size_t)row * 256 + sg;
            cp16(sbq + s, gQh + go);
            cp16(sbl + s, gQl + go);
        }
        CP_COMMIT(); CP_WAIT(0); __syncthreads();
        #pragma unroll
        for (int ks = 0; ks < 8; ++ks) {
            int ab = (ks << 5) + (hf << 4);
            uint32_t rel = ((ab >> 7) << 14) + SWZ(((wm + r) << 7) + (ab & 127));
            ldmx4(qh[ks], sbq + rel);
        }
        __syncthreads();
    }

    // ---- prologue: rdot = Q @ rel^T into rdot smem ----
    {
        const char* gRh = (const char*)g_rel_hi;
        const char* gRl = (const char*)g_rel_lo;
        const uint32_t sb = smb + FA_STG;
        #pragma unroll
        for (int p = 0; p < 8; ++p) {
            int e = tid + (p << 8);
            int row = e >> 4, sg = (e & 15) << 4;
            uint32_t s = ((sg >> 7) << 14) + SWZ((row << 7) + (sg & 127));
            size_t go = (size_t)row * 256 + sg;
            cp16(sb + s,         gRh + go);
            cp16(sb + 32768 + s, gRl + go);
        }
        CP_COMMIT(); CP_WAIT(0); __syncthreads();
        float* rsm = (float*)sm;
        #pragma unroll 1
        for (int ss2 = 0; ss2 < 4; ++ss2) {
            float rs[4][4];
            #pragma unroll
            for (int t = 0; t < 4; ++t)
                #pragma unroll
                for (int u = 0; u < 4; ++u) rs[t][u] = 0.f;
            #pragma unroll
            for (int ks = 0; ks < 8; ++ks) {
                const int ab = (ks << 5) + (hf << 4);
                uint32_t qlf[4];
                {
                    uint32_t rel = ((ab >> 7) << 14) + SWZ(((wm + r) << 7) + (ab & 127));
                    ldmx4(qlf, smb + FA_QLO + rel);
                }
                uint32_t bhf[2][4], blf[2][4];
                #pragma unroll
                for (int np = 0; np < 2; ++np) {
                    int jr = (ss2 << 5) + (np << 4) + r;
                    uint32_t rel = ((ab >> 7) << 14) + SWZ((jr << 7) + (ab & 127));
                    ldmx4(bhf[np], sb + rel);
                    ldmx4(blf[np], sb + 32768 + rel);
                }
                #pragma unroll
                for (int np = 0; np < 2; ++np)
                    #pragma unroll
                    for (int sub = 0; sub < 2; ++sub) {
                        float* c = rs[np * 2 + sub];
                        mma16816(c, qh[ks], bhf[np][sub], bhf[np][sub + 2]);
                        mma16816(c, qh[ks], blf[np][sub], blf[np][sub + 2]);
                        mma16816(c, qlf,    bhf[np][sub], bhf[np][sub + 2]);
                    }
            }
            const int j0 = ss2 << 5;
            #pragma unroll
            for (int t = 0; t < 4; ++t) {
                int jj = j0 + (t << 3) + lcol;
                rsm[(wm + r2) * 128 + jj]           = rs[t][0];
                rsm[(wm + r2) * 128 + jj + 1]       = rs[t][1];
                rsm[(wm + r2 + 8) * 128 + jj]       = rs[t][2];
                rsm[(wm + r2 + 8) * 128 + jj + 1]   = rs[t][3];
            }
        }
        __syncthreads();
    }

    const char* gKh = (const char*)g_k_hi + (size_t)bn * L_ * 256;
    const char* gKl = (const char*)g_k_lo + (size_t)bn * L_ * 256;
    const char* gVh = (const char*)g_v_hi + (size_t)bn * L_ * 256;
    const char* gVl = (const char*)g_v_lo + (size_t)bn * L_ * 256;

    auto stageKV = [&](int jt, int buf) {
        const uint32_t sb = smb + FA_STG + buf * FA_STAGE;
        const size_t base = (size_t)(jt * 64) * 256;
        #pragma unroll
        for (int p = 0; p < 4; ++p) {
            int e = tid + (p << 8);
            int row = e >> 4, sg = (e & 15) << 4;
            uint32_t s = ((sg >> 7) << 13) + SWZ((row << 7) + (sg & 127));
            size_t go = base + (size_t)row * 256 + sg;
            cp16(sb + s,          gKh + go);
            cp16(sb + 16384 + s,  gKl + go);
            cp16(sb + 32768 + s,  gVh + go);
            cp16(sb + 49152 + s,  gVl + go);
        }
    };

    const int i0 = m0 + wm + r2, i1 = i0 + 8;
    const int h0 = i0 >> 5, w0 = i0 & 31;
    const int h1 = i1 >> 5, w1 = i1 & 31;
    const float* rd0 = (const float*)(sm + (size_t)(wm + r2) * 512);
    const float* rd1 = (const float*)(sm + (size_t)(wm + r2 + 8) * 512);

    float o[16][4];
    #pragma unroll
    for (int nt = 0; nt < 16; ++nt)
        #pragma unroll
        for (int u = 0; u < 4; ++u) o[nt][u] = 0.f;
    float m0r = -1e30f, m1r = -1e30f, s0r = 0.f, s1r = 0.f;

    stageKV(0, 0);
    CP_COMMIT();

    #pragma unroll 1
    for (int jt = 0; jt < 16; ++jt) {
        const int buf = jt & 1;
        if (jt + 1 < 16) { stageKV(jt + 1, buf ^ 1); CP_COMMIT(); CP_WAIT(1); }
        else CP_WAIT(0);
        __syncthreads();
        const uint32_t kb_s = smb + FA_STG + buf * FA_STAGE;
        const uint32_t vb_s = kb_s + 32768;

        #pragma unroll
        for (int ss = 0; ss < 2; ++ss) {
            float s[4][4];
            #pragma unroll
            for (int t = 0; t < 4; ++t)
                #pragma unroll
                for (int u = 0; u < 4; ++u) s[t][u] = 0.f;
            #pragma unroll
            for (int ks = 0; ks < 8; ++ks) {
                const int ab = (ks << 5) + (hf << 4);
                uint32_t qlf[4];
                {
                    uint32_t rel = ((ab >> 7) << 14) + SWZ(((wm + r) << 7) + (ab & 127));
                    ldmx4(qlf, smb + FA_QLO + rel);
                }
                uint32_t bhf[2][4], blf[2][4];
                #pragma unroll
                for (int np = 0; np < 2; ++np) {
                    int jr = (ss << 5) + (np << 4) + r;
                    uint32_t rel = ((ab >> 7) << 13) + SWZ((jr << 7) + (ab & 127));
                    ldmx4(bhf[np], kb_s + rel);
                    ldmx4(blf[np], kb_s + 16384 + rel);
                }
                #pragma unroll
                for (int np = 0; np < 2; ++np)
                    #pragma unroll
                    for (int sub = 0; sub < 2; ++sub) {
                        float* c = s[np * 2 + sub];
                        mma16816(c, qh[ks], bhf[np][sub], bhf[np][sub + 2]);
                        mma16816(c, qh[ks], blf[np][sub], blf[np][sub + 2]);
                        mma16816(c, qlf,    bhf[np][sub], bhf[np][sub + 2]);
                    }
            }

            const int j0 = jt * 64 + (ss << 5);
            float t0 = -1e30f, t1 = -1e30f;
            #pragma unroll
            for (int t = 0; t < 4; ++t) {
                int jj = j0 + t * 8 + lcol;
                int h2 = jj >> 5, w2 = jj & 31;
                float bh0 = rd0[94 + h2 - h0];
                float bh1 = rd1[94 + h2 - h1];
                s[t][0] += rd0[w2 - w0 + 31] + bh0;
                s[t][1] += rd0[w2 + 1 - w0 + 31] + bh0;
                s[t][2] += rd1[w2 - w1 + 31] + bh1;
                s[t][3] += rd1[w2 + 1 - w1 + 31] + bh1;
                t0 = fmaxf(t0, fmaxf(s[t][0], s[t][1]));
                t1 = fmaxf(t1, fmaxf(s[t][2], s[t][3]));
            }
            t0 = fmaxf(t0, __shfl_xor_sync(~0u, t0, 1));
            t0 = fmaxf(t0, __shfl_xor_sync(~0u, t0, 2));
            t1 = fmaxf(t1, __shfl_xor_sync(~0u, t1, 1));
            t1 = fmaxf(t1, __shfl_xor_sync(~0u, t1, 2));

            float mn0 = fmaxf(m0r, t0), mn1 = fmaxf(m1r, t1);
            float a0 = __expf(m0r - mn0), a1 = __expf(m1r - mn1);
            if (!(a0 == 1.0f && a1 == 1.0f)) {
                #pragma unroll
                for (int nt = 0; nt < 16; ++nt) {
                    o[nt][0] *= a0; o[nt][1] *= a0; o[nt][2] *= a1; o[nt][3] *= a1;
                }
            }
            uint32_t ph[2][4], pl[2][4];
            float ts0 = 0.f, ts1 = 0.f;
            #pragma unroll
            for (int t = 0; t < 4; ++t) {
                float p0 = __expf(s[t][0] - mn0), p1 = __expf(s[t][1] - mn0);
                float p2 = __expf(s[t][2] - mn1), p3 = __expf(s[t][3] - mn1);
                ts0 += p0 + p1; ts1 += p2 + p3;
                int kt = t >> 1, wc = (t & 1) << 1;
                ph[kt][wc]     = pack_hl(p0, p1, pl[kt][wc]);
                ph[kt][wc + 1] = pack_hl(p2, p3, pl[kt][wc + 1]);
            }
            ts0 += __shfl_xor_sync(~0u, ts0, 1); ts0 += __shfl_xor_sync(~0u, ts0, 2);
            ts1 += __shfl_xor_sync(~0u, ts1, 1); ts1 += __shfl_xor_sync(~0u, ts1, 2);
            s0r = s0r * a0 + ts0; s1r = s1r * a1 + ts1;
            m0r = mn0; m1r = mn1;

            #pragma unroll
            for (int kt = 0; kt < 2; ++kt) {
                #pragma unroll
                for (int np = 0; np < 8; ++np) {
                    int jrow = (ss << 5) + (kt << 4) + tj;
                    int db = ((np << 4) + tn) << 1;
                    uint32_t rel = ((db >> 7) << 13) + SWZ((jrow << 7) + (db & 127));
                    uint32_t vh4[4], vl4[4];
                    ldmx4t(vh4, vb_s + rel);
                    ldmx4t(vl4, vb_s + 16384 + rel);
                    #pragma unroll
                    for (int sub = 0; sub < 2; ++sub) {
                        float* c = o[np * 2 + sub];
                        mma16816(c, ph[kt], vh4[sub], vh4[sub + 2]);
                        mma16816(c, ph[kt], vl4[sub], vl4[sub + 2]);
                        mma16816(c, pl[kt], vh4[sub], vh4[sub + 2]);
                    }
                }
            }
        }
        __syncthreads();
    }

    // ---- epilogue: normalize -> smem transpose -> coalesced residual+store ----
    __syncthreads();
    float* so = (float*)sm;
    const float inv0 = 1.f / s0r, inv1 = 1.f / s1r;
    #pragma unroll
    for (int nt = 0; nt < 16; ++nt) {
        const int d0 = (nt << 3) + lcol;
        #pragma unroll
        for (int u = 0; u < 2; ++u) {
            so[(d0 + u) * 136 + wm + r2]     = o[nt][u] * inv0;
            so[(d0 + u) * 136 + wm + r2 + 8] = o[nt][2 + u] * inv1;
        }
    }
    __syncthreads();
    #pragma unroll
    for (int ch = 0; ch < 16; ++ch) {
        const int d = (ch << 3) + (tid >> 5);
        const int i4 = (tid & 31) << 2;
        const size_t idx = ((size_t)(b * C_ + head * D_ + d) << 10) + m0 + i4;
        float4 xr = *(const float4*)(x + idx);
        float4 ov = *(const float4*)(so + d * 136 + i4);
        ov.x += xr.x; ov.y += xr.y; ov.z += xr.z; ov.w += xr.w;
        *(float4*)(g_xres + idx) = ov;
    }
}

// ---------------- conv GEMM via mma.sync fp16 (W single + Y hi/lo, 2 MMA terms) ----------
// tile M=128 (o) x N=256 (l); grid (4,4,8) = 128 CTAs = one full wave. 256 threads.
#define NCHUNK 72
#define CV_SUBA 16384
#define CV_SUBB 32768
#define CV_BUF (CV_SUBA + 2 * CV_SUBB)       // A | Bh | Bl = 80KB
#define CONV_SMEM (1024 + 2 * CV_BUF)
__global__ __launch_bounds__(256, 1) void conv_mma_kernel(const float* __restrict__ bias_fc,
                                                          float* __restrict__ out) {
    extern __shared__ char smraw[];
    char* sm = (char*)(((uintptr_t)smraw + 1023) & ~(uintptr_t)1023);
    const uint32_t smb = smem_u32(sm);
    const int tid = threadIdx.x, wid = tid >> 5, lane = tid & 31;
    const int bb = blockIdx.z, m0 = blockIdx.y * 128, n0 = blockIdx.x * 256;

    const char* gA = (const char*)g_w_f + (size_t)m0 * (KC_ * 2);
    const char* yh = (const char*)g_y2t_hi + (size_t)bb * L_ * 1024;
    const char* yl = (const char*)g_y2t_lo + (size_t)bb * L_ * 1024;

    auto stage = [&](int it, int buf) {
        const size_t koff = (size_t)it * 128;
        const uint32_t sb = smb + buf * CV_BUF;
        #pragma unroll
        for (int p = 0; p < 4; ++p) {   // A: weights 128 rows x 128B
            int e = tid + (p << 8);
            int row = e >> 3;
            int sg = (e & 7) << 4;
            size_t g = (size_t)row * (KC_ * 2) + koff + sg;
            uint32_t s = SWZ((row << 7) + sg);
            cp16(sb + s, gA + g);
        }
        const int r9 = it >> 3;
        const int dh = r9 / 3 - 1, dw = r9 % 3 - 1;
        const int cb2 = ((it & 7) << 6) * 2;
        #pragma unroll
        for (int p = 0; p < 8; ++p) {             // B: 256 rows x 128B (hi + lo)
            int e = tid + (p << 8);
            int row = e >> 3;
            int sg = (e & 7) << 4;
            uint32_t s = SWZ((row << 7) + sg);
            int l = n0 + row;
            int h = (l >> 5) + dh, w = (l & 31) + dw;
            if ((unsigned)h < 32u && (unsigned)w < 32u) {
                size_t g = ((size_t)(l + dh * 32 + dw) << 10) + cb2 + sg;
                cp16(sb + CV_SUBA + s,           yh + g);
                cp16(sb + CV_SUBA + CV_SUBB + s, yl + g);
            } else {
                uint4 z = make_uint4(0u, 0u, 0u, 0u);
                *(uint4*)(sm + ((size_t)buf * CV_BUF + CV_SUBA + s)) = z;
                *(uint4*)(sm + ((size_t)buf * CV_BUF + CV_SUBA + CV_SUBB + s)) = z;
            }
        }
    };

    float acc[2][16][4];
    #pragma unroll
    for (int i = 0; i < 2; i++)
        #pragma unroll
        for (int j = 0; j < 16; j++)
            #pragma unroll
            for (int t = 0; t < 4; t++) acc[i][j][t] = 0.f;

    const int wm = (wid & 3) << 5, wn = (wid >> 2) << 7;
    const int r = lane & 15, hf = lane >> 4;

    stage(0, 0);
    CP_COMMIT();
    #pragma unroll 1
    for (int it = 0; it < NCHUNK; ++it) {
        const int buf = it & 1;
        if (it + 1 < NCHUNK) { stage(it + 1, buf ^ 1); CP_COMMIT(); CP_WAIT(1); }
        else CP_WAIT(0);
        __syncthreads();
        const uint32_t sA = smb + buf * CV_BUF;
        const uint32_t sB = sA + CV_SUBA, sBl = sB + CV_SUBB;
        #pragma unroll
        for (int ks = 0; ks < 4; ++ks) {
            const int kb = ks << 5;
            uint32_t ah[2][4];
            #pragma unroll
            for (int mt = 0; mt < 2; ++mt) {
                uint32_t rel = SWZ(((wm + (mt << 4) + r) << 7) + kb + (hf << 4));
                ldmx4(ah[mt], sA + rel);
            }
            #pragma unroll
            for (int np = 0; np < 8; ++np) {
                uint32_t rel = SWZ(((wn + (np << 4) + r) << 7) + kb + (hf << 4));
                uint32_t bh[4], bl[4];
                ldmx4(bh, sB + rel);
                ldmx4(bl, sBl + rel);
                #pragma unroll
                for (int mt = 0; mt < 2; ++mt)
                    #pragma unroll
                    for (int sub = 0; sub < 2; ++sub) {
                        float* c = acc[mt][np * 2 + sub];
                        mma16816h(c, ah[mt], bh[sub], bh[sub + 2]);
                        mma16816h(c, ah[mt], bl[sub], bl[sub + 2]);
                    }
            }
        }
        __syncthreads();
    }

    const int lrow = lane >> 2, lcol = (lane & 3) << 1;
    #pragma unroll
    for (int mt = 0; mt < 2; ++mt) {
        #pragma unroll
        for (int nt = 0; nt < 16; ++nt) {
            const float* c = acc[mt][nt];
            int l = n0 + wn + (nt << 3) + lcol;
            #pragma unroll
            for (int half = 0; half < 2; ++half) {
                int o = m0 + wm + (mt << 4) + lrow + half * 8;
                float bv = bias_fc[o];
                size_t idx = ((size_t)(bb * C_ + o) << 10) + l;
                float2 xr = *(const float2*)(g_xres + idx);
                float2 o2;
                o2.x = c[half * 2 + 0] + bv + xr.x;
                o2.y = c[half * 2 + 1] + bv + xr.y;
                *(float2*)(out + idx) = o2;
            }
        }
    }
}

// ---------------- launch ----------------
extern "C" void kernel_launch(void* const* d_in, const int* in_sizes, int n_in,
                              void* d_out, int out_size) {
    const float* x       = (const float*)d_in[0];
    const float* w_qk    = (const float*)d_in[1];
    const float* w_v     = (const float*)d_in[2];
    const float* rel_h   = (const float*)d_in[3];
    const float* rel_w   = (const float*)d_in[4];
    const float* g1      = (const float*)d_in[5];
    const float* b1      = (const float*)d_in[6];
    const float* m1      = (const float*)d_in[7];
    const float* v1      = (const float*)d_in[8];
    const float* g2      = (const float*)d_in[9];
    const float* b2      = (const float*)d_in[10];
    const float* m2      = (const float*)d_in[11];
    const float* v2      = (const float*)d_in[12];
    const float* w_fc    = (const float*)d_in[13];
    const float* bias_fc = (const float*)d_in[14];
    float* out = (float*)d_out;

    cudaFuncSetAttribute(proj_mma_kernel, cudaFuncAttributeMaxDynamicSharedMemorySize, PROJ_SMEM);
    cudaFuncSetAttribute(flash_kernel,    cudaFuncAttributeMaxDynamicSharedMemorySize, FA_SMEM);
    cudaFuncSetAttribute(conv_mma_kernel, cudaFuncAttributeMaxDynamicSharedMemorySize, CONV_SMEM);

    wqkv2bf_kernel<<<(1536 * 512 + 16384) / 256, 256>>>(w_qk, w_v, rel_h, rel_w);
    w2bf_kernel<<<(C_ * KC_) / 256, 256>>>(w_fc);
    bn1t_kernel<<<dim3(32, 16, B_), 256>>>(x, g1, b1, m1, v1);
    proj_mma_kernel<<<dim3(12, 8, B_), 256, PROJ_SMEM>>>();
    flash_kernel<<<dim3(8, 32), 256, FA_SMEM>>>(x);
    bn2t_kernel<<<dim3(32, 16, B_), 256>>>(g2, b2, m2, v2);
    conv_mma_kernel<<<dim3(4, 4, B_), 256, CONV_SMEM>>>(bias_fc, out);
}

// round 13
// speedup vs baseline: 1.7569x; 1.4503x over previous
#include <cuda_runtime.h>
#include <cuda_bf16.h>
#include <cuda_fp16.h>
#include <cstdint>

// ---------------- problem constants ----------------
#define B_   8
#define C_   512
#define HH_  32
#define WW_  32
#define L_   1024          // HH*WW
#define NH_  4
#define D_   128
#define KC_  4608          // 512*9 (im2col K)
#define QSCALE 0.08838834764831845f  // 128^-0.5

// ---------------- scratch (device globals; no allocations) ----------------
__device__ __half g_xn[B_*L_*C_];            // relu(bn1(x)) transposed [b][l][c] fp16
__device__ __half g_wqkv[1536*512];          // [o][c], o: q|k|v  fp16
__device__ __half g_rel[128*128];            // rows: 0..62 rel_w, 63..125 rel_h, 126..127 zero
__device__ __half g_q[32*L_*D_];             // [bn][l][d] (scaled) fp16
__device__ __half g_k[32*L_*D_];
__device__ __half g_v[32*L_*D_];
__device__ float g_xres[B_*C_*L_];           // mhsa out + x
__device__ __half g_y2t_hi[B_*L_*C_];        // relu(bn2(xres)) transposed fp16 hi/lo
__device__ __half g_y2t_lo[B_*L_*C_];
__device__ __half g_w_f[(size_t)C_*KC_];     // conv weights fp16, reordered [o][r9*512 + c]

// ================= mma.sync helpers =================
__device__ __forceinline__ uint32_t smem_u32(const void* p) {
    uint32_t a;
    asm("{ .reg .u64 t; cvta.to.shared.u64 t, %1; cvt.u32.u64 %0, t; }" : "=r"(a) : "l"(p));
    return a;
}
__device__ __forceinline__ void cp16(uint32_t s, const void* g) {
    asm volatile("cp.async.cg.shared.global [%0], [%1], 16;" :: "r"(s), "l"(g));
}
#define CP_COMMIT() asm volatile("cp.async.commit_group;" ::: "memory")
#define CP_WAIT(n)  asm volatile("cp.async.wait_group %0;" :: "n"(n) : "memory")

__device__ __forceinline__ void ldmx4(uint32_t* d, uint32_t addr) {
    asm volatile("ldmatrix.sync.aligned.m8n8.x4.shared.b16 {%0,%1,%2,%3}, [%4];"
                 : "=r"(d[0]), "=r"(d[1]), "=r"(d[2]), "=r"(d[3]) : "r"(addr));
}
__device__ __forceinline__ void ldmx4t(uint32_t* d, uint32_t addr) {
    asm volatile("ldmatrix.sync.aligned.m8n8.x4.trans.shared.b16 {%0,%1,%2,%3}, [%4];"
                 : "=r"(d[0]), "=r"(d[1]), "=r"(d[2]), "=r"(d[3]) : "r"(addr));
}
__device__ __forceinline__ void mma16816h(float* c, const uint32_t* a, uint32_t b0, uint32_t b1) {
    asm volatile("mma.sync.aligned.m16n8k16.row.col.f32.f16.f16.f32 "
                 "{%0,%1,%2,%3}, {%4,%5,%6,%7}, {%8,%9}, {%0,%1,%2,%3};"
                 : "+f"(c[0]), "+f"(c[1]), "+f"(c[2]), "+f"(c[3])
                 : "r"(a[0]), "r"(a[1]), "r"(a[2]), "r"(a[3]), "r"(b0), "r"(b1));
}
#define SWZ(x) ((x) ^ (((x) >> 3) & 0x70))

__device__ __forceinline__ void hilo_h(float v, __half& h, __half& l) {
    h = __float2half(v);
    l = __float2half(v - __half2float(h));
}
__device__ __forceinline__ uint32_t pack_h2(float a, float b) {
    __half2 h = __floats2half2_rn(a, b);
    return *(uint32_t*)&h;
}

// ---------------- BN1 + ReLU + transpose -> fp16 [b][l][c] ----------------
__global__ void bn1t_kernel(const float* __restrict__ x,
                            const float* __restrict__ g, const float* __restrict__ bb,
                            const float* __restrict__ m, const float* __restrict__ v) {
    __shared__ float t[32][33];
    const int b = blockIdx.z, c0 = blockIdx.y * 32, l0 = blockIdx.x * 32;
    const int tid = threadIdx.x;
    {
        const int cr = tid >> 3, l4 = (tid & 7) * 4;
        const int c = c0 + cr;
        float inv = g[c] * rsqrtf(v[c] + 1e-5f);
        float sh  = bb[c] - m[c] * inv;
        float4 xv = *(const float4*)(x + ((size_t)(b * C_ + c) << 10) + l0 + l4);
        t[cr][l4 + 0] = fmaxf(fmaf(xv.x, inv, sh), 0.f);
        t[cr][l4 + 1] = fmaxf(fmaf(xv.y, inv, sh), 0.f);
        t[cr][l4 + 2] = fmaxf(fmaf(xv.z, inv, sh), 0.f);
        t[cr][l4 + 3] = fmaxf(fmaf(xv.w, inv, sh), 0.f);
    }
    __syncthreads();
    {
        const int lr = tid >> 3, c4 = (tid & 7) * 4;
        size_t base = ((size_t)(b * L_ + l0 + lr) << 9) + c0 + c4;
        *(uint32_t*)(g_xn + base)     = pack_h2(t[c4 + 0][lr], t[c4 + 1][lr]);
        *(uint32_t*)(g_xn + base + 2) = pack_h2(t[c4 + 2][lr], t[c4 + 3][lr]);
    }
}

// ---------------- BN2 + ReLU + transpose -> fp16 hi/lo [b][l][c] ----------------
__global__ void bn2t_kernel(const float* __restrict__ g, const float* __restrict__ bb,
                            const float* __restrict__ m, const float* __restrict__ v) {
    __shared__ float t[32][33];
    const int b = blockIdx.z, c0 = blockIdx.y * 32, l0 = blockIdx.x * 32;
    const int tid = threadIdx.x;
    {
        const int cr = tid >> 3, l4 = (tid & 7) * 4;
        const int c = c0 + cr;
        float inv = g[c] * rsqrtf(v[c] + 1e-5f);
        float sh  = bb[c] - m[c] * inv;
        float4 xv = *(const float4*)(g_xres + ((size_t)(b * C_ + c) << 10) + l0 + l4);
        t[cr][l4 + 0] = fmaxf(fmaf(xv.x, inv, sh), 0.f);
        t[cr][l4 + 1] = fmaxf(fmaf(xv.y, inv, sh), 0.f);
        t[cr][l4 + 2] = fmaxf(fmaf(xv.z, inv, sh), 0.f);
        t[cr][l4 + 3] = fmaxf(fmaf(xv.w, inv, sh), 0.f);
    }
    __syncthreads();
    {
        const int lr = tid >> 3, c4 = (tid & 7) * 4;
        __half h[4], lo[4];
        #pragma unroll
        for (int u = 0; u < 4; ++u) hilo_h(t[c4 + u][lr], h[u], lo[u]);
        size_t base = ((size_t)(b * L_ + l0 + lr) << 9) + c0 + c4;
        *(__half2*)(g_y2t_hi + base)     = *(__half2*)&h[0];
        *(__half2*)(g_y2t_hi + base + 2) = *(__half2*)&h[2];
        *(__half2*)(g_y2t_lo + base)     = *(__half2*)&lo[0];
        *(__half2*)(g_y2t_lo + base + 2) = *(__half2*)&lo[2];
    }
}

// ---------------- qkv weights + rel tables -> fp16 ----------------
__global__ void wqkv2bf_kernel(const float* __restrict__ w_qk, const float* __restrict__ w_v,
                               const float* __restrict__ rel_h, const float* __restrict__ rel_w) {
    int i = blockIdx.x * 256 + threadIdx.x;
    if (i < 1024 * 512) {
        g_wqkv[i] = __float2half(w_qk[i]);
    } else if (i < 1536 * 512) {
        g_wqkv[i] = __float2half(w_v[i - 1024 * 512]);
    } else {
        int j = i - 1536 * 512;          // 0..16383
        int rr = j >> 7, d = j & 127;
        float val = 0.f;
        if (rr < 63)       val = rel_w[rr * 128 + d];
        else if (rr < 126) val = rel_h[(rr - 63) * 128 + d];
        g_rel[j] = __float2half(val);
    }
}

// ---------------- conv weights -> fp16 single, reorder k' = r9*512 + c ----------------
__global__ void w2bf_kernel(const float* __restrict__ w) {
    int i = blockIdx.x * 256 + threadIdx.x;   // src: o*4608 + c*9 + r9
    int o = i / KC_, rem = i % KC_;
    int c = rem / 9, r9 = rem % 9;
    size_t dst = (size_t)o * KC_ + r9 * 512 + c;
    g_w_f[dst] = __float2half(w[i]);
}

// ---------------- QKV projection via mma.sync fp16 single ----------------
// block tile 128x128, K-chunk 64, 256 threads. 1 MMA per product.
#define P_SUB 16384
#define P_BUF (2 * P_SUB)
#define PROJ_SMEM (1024 + 2 * P_BUF)
__global__ __launch_bounds__(256, 1) void proj_mma_kernel() {
    extern __shared__ char smraw[];
    char* sm = (char*)(((uintptr_t)smraw + 1023) & ~(uintptr_t)1023);
    const uint32_t smb = smem_u32(sm);
    const int tid = threadIdx.x, wid = tid >> 5, lane = tid & 31;
    const int b = blockIdx.z, m0 = blockIdx.y * 128, n0 = blockIdx.x * 128;

    const char* gA = (const char*)g_xn + (size_t)(b * L_ + m0) * 1024;
    const char* gB = (const char*)g_wqkv + (size_t)n0 * 1024;

    auto stage = [&](int it, int buf) {
        const uint32_t sb = smb + buf * P_BUF;
        #pragma unroll
        for (int p = 0; p < 4; ++p) {
            int e = tid + (p << 8);
            int row = e >> 3;
            int sg = (e & 7) << 4;
            size_t go = (size_t)row * 1024 + (size_t)it * 128 + sg;
            uint32_t s = SWZ((row << 7) + sg);
            cp16(sb + s,         gA + go);
            cp16(sb + P_SUB + s, gB + go);
        }
    };

    float acc[2][8][4];
    #pragma unroll
    for (int i = 0; i < 2; i++)
        #pragma unroll
        for (int j = 0; j < 8; j++)
            #pragma unroll
            for (int t = 0; t < 4; t++) acc[i][j][t] = 0.f;

    const int wm = (wid & 3) << 5, wn = (wid >> 2) << 6;
    const int r = lane & 15, hf = lane >> 4;

    stage(0, 0);
    CP_COMMIT();
    #pragma unroll 1
    for (int it = 0; it < 8; ++it) {
        const int buf = it & 1;
        if (it + 1 < 8) { stage(it + 1, buf ^ 1); CP_COMMIT(); CP_WAIT(1); }
        else CP_WAIT(0);
        __syncthreads();
        const uint32_t sA = smb + buf * P_BUF, sB = sA + P_SUB;
        #pragma unroll
        for (int ks = 0; ks < 4; ++ks) {
            const int kb = ks << 5;
            uint32_t ah[2][4];
            #pragma unroll
            for (int mt = 0; mt < 2; ++mt) {
                uint32_t rel = SWZ(((wm + (mt << 4) + r) << 7) + kb + (hf << 4));
                ldmx4(ah[mt], sA + rel);
            }
            uint32_t bh[4][4];
            #pragma unroll
            for (int np = 0; np < 4; ++np) {
                uint32_t rel = SWZ(((wn + (np << 4) + r) << 7) + kb + (hf << 4));
                ldmx4(bh[np], sB + rel);
            }
            #pragma unroll
            for (int mt = 0; mt < 2; ++mt)
                #pragma unroll
                for (int np = 0; np < 4; ++np)
                    #pragma unroll
                    for (int sub = 0; sub < 2; ++sub)
                        mma16816h(acc[mt][np * 2 + sub], ah[mt], bh[np][sub], bh[np][sub + 2]);
        }
        __syncthreads();
    }

    const int region = n0 >> 9;                 // 0=q,1=k,2=v
    const int head = (n0 >> 7) & 3;
    const float scale = (region == 0) ? QSCALE : 1.0f;
    __half* dst;
    if (region == 0)      dst = g_q;
    else if (region == 1) dst = g_k;
    else                  dst = g_v;
    const size_t bnbase = (size_t)(b * NH_ + head) * L_ * D_;
    const int lrow = lane >> 2, lcol = (lane & 3) << 1;
    #pragma unroll
    for (int mt = 0; mt < 2; ++mt) {
        #pragma unroll
        for (int nt = 0; nt < 8; ++nt) {
            const float* c = acc[mt][nt];
            const int d0 = wn + (nt << 3) + lcol;
            #pragma unroll
            for (int half = 0; half < 2; ++half) {
                int lv = m0 + wm + (mt << 4) + lrow + half * 8;
                size_t base = bnbase + ((size_t)lv << 7) + d0;
                *(uint32_t*)(dst + base) =
                    pack_h2(c[half * 2 + 0] * scale, c[half * 2 + 1] * scale);
            }
        }
    }
}

// ---------------- fused flash attention (fp16 single) + rel-pos + residual ----------------
// grid (8 m-tiles, 32 bn), 256 threads = 8 warps, each warp 16 rows.
// smem: rdot 64KB fp32 | 2 stages x 32KB (K 16K | V 16K)
#define FA_STG 65536
#define FA_STAGE 32768
#define FA_SMEM (1024 + FA_STG + 2 * FA_STAGE)   // 132096
__global__ __launch_bounds__(256, 1) void flash_kernel(const float* __restrict__ x) {
    extern __shared__ char smraw[];
    char* sm = (char*)(((uintptr_t)smraw + 1023) & ~(uintptr_t)1023);
    const uint32_t smb = smem_u32(sm);
    const int tid = threadIdx.x, wid = tid >> 5, lane = tid & 31;
    const int m0 = blockIdx.x * 128, bn = blockIdx.y;
    const int b = bn >> 2, head = bn & 3;
    const int r = lane & 15, hf = lane >> 4;
    const int r2 = lane >> 2, lcol = (lane & 3) << 1;
    const int tj = (lane & 7) + ((lane >> 4) << 3);
    const int tn = ((lane >> 3) & 1) << 3;
    const int wm = wid << 4;

    // Q -> regs via temp staging in stage buf 1 (32KB, two 128B halves)
    uint32_t qh[8][4];
    {
        const char* gQ = (const char*)g_q + ((size_t)bn * L_ + m0) * 256;
        const uint32_t sbq = smb + FA_STG + FA_STAGE;
        #pragma unroll
        for (int p = 0; p < 8; ++p) {
            int e = tid + (p << 8);
            int row = e >> 4, sg = (e & 15) << 4;
            uint32_t s = ((sg >> 7) << 14) + SWZ((row << 7) + (sg & 127));
            cp16(sbq + s, gQ + (size_t)row * 256 + sg);
        }
        CP_COMMIT(); CP_WAIT(0); __syncthreads();
        #pragma unroll
        for (int ks = 0; ks < 8; ++ks) {
            int ab = (ks << 5) + (hf << 4);
            uint32_t rel = ((ab >> 7) << 14) + SWZ(((wm + r) << 7) + (ab & 127));
            ldmx4(qh[ks], sbq + rel);
        }
        __syncthreads();
    }

    // ---- prologue: rdot = Q @ rel^T into rdot smem (rel staged in buf 0, 32KB) ----
    {
        const char* gR = (const char*)g_rel;
        const uint32_t sb = smb + FA_STG;
        #pragma unroll
        for (int p = 0; p < 8; ++p) {
            int e = tid + (p << 8);
            int row = e >> 4, sg = (e & 15) << 4;
            uint32_t s = ((sg >> 7) << 14) + SWZ((row << 7) + (sg & 127));
            cp16(sb + s, gR + (size_t)row * 256 + sg);
        }
        CP_COMMIT(); CP_WAIT(0); __syncthreads();
        float* rsm = (float*)sm;
        #pragma unroll 1
        for (int ss2 = 0; ss2 < 4; ++ss2) {
            float rs[4][4];
            #pragma unroll
            for (int t = 0; t < 4; ++t)
                #pragma unroll
                for (int u = 0; u < 4; ++u) rs[t][u] = 0.f;
            #pragma unroll
            for (int ks = 0; ks < 8; ++ks) {
                const int ab = (ks << 5) + (hf << 4);
                uint32_t bhf[2][4];
                #pragma unroll
                for (int np = 0; np < 2; ++np) {
                    int jr = (ss2 << 5) + (np << 4) + r;
                    uint32_t rel = ((ab >> 7) << 14) + SWZ((jr << 7) + (ab & 127));
                    ldmx4(bhf[np], sb + rel);
                }
                #pragma unroll
                for (int np = 0; np < 2; ++np)
                    #pragma unroll
                    for (int sub = 0; sub < 2; ++sub)
                        mma16816h(rs[np * 2 + sub], qh[ks], bhf[np][sub], bhf[np][sub + 2]);
            }
            const int j0 = ss2 << 5;
            #pragma unroll
            for (int t = 0; t < 4; ++t) {
                int jj = j0 + (t << 3) + lcol;
                rsm[(wm + r2) * 128 + jj]           = rs[t][0];
                rsm[(wm + r2) * 128 + jj + 1]       = rs[t][1];
                rsm[(wm + r2 + 8) * 128 + jj]       = rs[t][2];
                rsm[(wm + r2 + 8) * 128 + jj + 1]   = rs[t][3];
            }
        }
        __syncthreads();
    }

    const char* gK = (const char*)g_k + (size_t)bn * L_ * 256;
    const char* gV = (const char*)g_v + (size_t)bn * L_ * 256;

    auto stageKV = [&](int jt, int buf) {
        const uint32_t sb = smb + FA_STG + buf * FA_STAGE;
        const size_t base = (size_t)(jt * 64) * 256;
        #pragma unroll
        for (int p = 0; p < 4; ++p) {
            int e = tid + (p << 8);
            int row = e >> 4, sg = (e & 15) << 4;
            uint32_t s = ((sg >> 7) << 13) + SWZ((row << 7) + (sg & 127));
            size_t go = base + (size_t)row * 256 + sg;
            cp16(sb + s,         gK + go);
            cp16(sb + 16384 + s, gV + go);
        }
    };

    const int i0 = m0 + wm + r2, i1 = i0 + 8;
    const int h0 = i0 >> 5, w0 = i0 & 31;
    const int h1 = i1 >> 5, w1 = i1 & 31;
    const float* rd0 = (const float*)(sm + (size_t)(wm + r2) * 512);
    const float* rd1 = (const float*)(sm + (size_t)(wm + r2 + 8) * 512);

    float o[16][4];
    #pragma unroll
    for (int nt = 0; nt < 16; ++nt)
        #pragma unroll
        for (int u = 0; u < 4; ++u) o[nt][u] = 0.f;
    float m0r = -1e30f, m1r = -1e30f, s0r = 0.f, s1r = 0.f;

    stageKV(0, 0);
    CP_COMMIT();

    #pragma unroll 1
    for (int jt = 0; jt < 16; ++jt) {
        const int buf = jt & 1;
        if (jt + 1 < 16) { stageKV(jt + 1, buf ^ 1); CP_COMMIT(); CP_WAIT(1); }
        else CP_WAIT(0);
        __syncthreads();
        const uint32_t kb_s = smb + FA_STG + buf * FA_STAGE;
        const uint32_t vb_s = kb_s + 16384;

        #pragma unroll
        for (int ss = 0; ss < 2; ++ss) {
            // ---- S = Q K^T over this 32-j substep (1 MMA per product) ----
            float s[4][4];
            #pragma unroll
            for (int t = 0; t < 4; ++t)
                #pragma unroll
                for (int u = 0; u < 4; ++u) s[t][u] = 0.f;
            #pragma unroll
            for (int ks = 0; ks < 8; ++ks) {
                const int ab = (ks << 5) + (hf << 4);
                uint32_t bhf[2][4];
                #pragma unroll
                for (int np = 0; np < 2; ++np) {
                    int jr = (ss << 5) + (np << 4) + r;
                    uint32_t rel = ((ab >> 7) << 13) + SWZ((jr << 7) + (ab & 127));
                    ldmx4(bhf[np], kb_s + rel);
                }
                #pragma unroll
                for (int np = 0; np < 2; ++np)
                    #pragma unroll
                    for (int sub = 0; sub < 2; ++sub)
                        mma16816h(s[np * 2 + sub], qh[ks], bhf[np][sub], bhf[np][sub + 2]);
            }

            // ---- bias + row max (32 j) ----
            const int j0 = jt * 64 + (ss << 5);
            float t0 = -1e30f, t1 = -1e30f;
            #pragma unroll
            for (int t = 0; t < 4; ++t) {
                int jj = j0 + t * 8 + lcol;
                int h2 = jj >> 5, w2 = jj & 31;
                float bh0 = rd0[94 + h2 - h0];
                float bh1 = rd1[94 + h2 - h1];
                s[t][0] += rd0[w2 - w0 + 31] + bh0;
                s[t][1] += rd0[w2 + 1 - w0 + 31] + bh0;
                s[t][2] += rd1[w2 - w1 + 31] + bh1;
                s[t][3] += rd1[w2 + 1 - w1 + 31] + bh1;
                t0 = fmaxf(t0, fmaxf(s[t][0], s[t][1]));
                t1 = fmaxf(t1, fmaxf(s[t][2], s[t][3]));
            }
            t0 = fmaxf(t0, __shfl_xor_sync(~0u, t0, 1));
            t0 = fmaxf(t0, __shfl_xor_sync(~0u, t0, 2));
            t1 = fmaxf(t1, __shfl_xor_sync(~0u, t1, 1));
            t1 = fmaxf(t1, __shfl_xor_sync(~0u, t1, 2));

            // ---- online softmax update ----
            float mn0 = fmaxf(m0r, t0), mn1 = fmaxf(m1r, t1);
            float a0 = __expf(m0r - mn0), a1 = __expf(m1r - mn1);
            if (!(a0 == 1.0f && a1 == 1.0f)) {
                #pragma unroll
                for (int nt = 0; nt < 16; ++nt) {
                    o[nt][0] *= a0; o[nt][1] *= a0; o[nt][2] *= a1; o[nt][3] *= a1;
                }
            }
            uint32_t ph[2][4];
            float ts0 = 0.f, ts1 = 0.f;
            #pragma unroll
            for (int t = 0; t < 4; ++t) {
                float p0 = __expf(s[t][0] - mn0), p1 = __expf(s[t][1] - mn0);
                float p2 = __expf(s[t][2] - mn1), p3 = __expf(s[t][3] - mn1);
                ts0 += p0 + p1; ts1 += p2 + p3;
                int kt = t >> 1, wc = (t & 1) << 1;
                ph[kt][wc]     = pack_h2(p0, p1);
                ph[kt][wc + 1] = pack_h2(p2, p3);
            }
            ts0 += __shfl_xor_sync(~0u, ts0, 1); ts0 += __shfl_xor_sync(~0u, ts0, 2);
            ts1 += __shfl_xor_sync(~0u, ts1, 1); ts1 += __shfl_xor_sync(~0u, ts1, 2);
            s0r = s0r * a0 + ts0; s1r = s1r * a1 + ts1;
            m0r = mn0; m1r = mn1;

            // ---- O += P V (k = 32, 1 MMA per product) ----
            #pragma unroll
            for (int kt = 0; kt < 2; ++kt) {
                #pragma unroll
                for (int np = 0; np < 8; ++np) {
                    int jrow = (ss << 5) + (kt << 4) + tj;
                    int db = ((np << 4) + tn) << 1;
                    uint32_t rel = ((db >> 7) << 13) + SWZ((jrow << 7) + (db & 127));
                    uint32_t vh4[4];
                    ldmx4t(vh4, vb_s + rel);
                    #pragma unroll
                    for (int sub = 0; sub < 2; ++sub)
                        mma16816h(o[np * 2 + sub], ph[kt], vh4[sub], vh4[sub + 2]);
                }
            }
        }
        __syncthreads();
    }

    // ---- epilogue: normalize -> smem transpose -> coalesced residual+store ----
    __syncthreads();
    float* so = (float*)sm;                 // [128 d][136 stride] fp32
    const float inv0 = 1.f / s0r, inv1 = 1.f / s1r;
    #pragma unroll
    for (int nt = 0; nt < 16; ++nt) {
        const int d0 = (nt << 3) + lcol;
        #pragma unroll
        for (int u = 0; u < 2; ++u) {
            so[(d0 + u) * 136 + wm + r2]     = o[nt][u] * inv0;
            so[(d0 + u) * 136 + wm + r2 + 8] = o[nt][2 + u] * inv1;
        }
    }
    __syncthreads();
    #pragma unroll
    for (int ch = 0; ch < 16; ++ch) {
        const int d = (ch << 3) + (tid >> 5);
        const int i4 = (tid & 31) << 2;
        const size_t idx = ((size_t)(b * C_ + head * D_ + d) << 10) + m0 + i4;
        float4 xr = *(const float4*)(x + idx);
        float4 ov = *(const float4*)(so + d * 136 + i4);
        ov.x += xr.x; ov.y += xr.y; ov.z += xr.z; ov.w += xr.w;
        *(float4*)(g_xres + idx) = ov;
    }
}

// ---------------- conv GEMM via mma.sync fp16 (W single + Y hi/lo, 2 MMA terms) ----------
// tile M=128 (o) x N=256 (l); grid (4,4,8) = 128 CTAs = one full wave. 256 threads.
#define NCHUNK 72
#define CV_SUBA 16384
#define CV_SUBB 32768
#define CV_BUF (CV_SUBA + 2 * CV_SUBB)       // A | Bh | Bl = 80KB
#define CONV_SMEM (1024 + 2 * CV_BUF)
__global__ __launch_bounds__(256, 1) void conv_mma_kernel(const float* __restrict__ bias_fc,
                                                          float* __restrict__ out) {
    extern __shared__ char smraw[];
    char* sm = (char*)(((uintptr_t)smraw + 1023) & ~(uintptr_t)1023);
    const uint32_t smb = smem_u32(sm);
    const int tid = threadIdx.x, wid = tid >> 5, lane = tid & 31;
    const int bb = blockIdx.z, m0 = blockIdx.y * 128, n0 = blockIdx.x * 256;

    const char* gA = (const char*)g_w_f + (size_t)m0 * (KC_ * 2);
    const char* yh = (const char*)g_y2t_hi + (size_t)bb * L_ * 1024;
    const char* yl = (const char*)g_y2t_lo + (size_t)bb * L_ * 1024;

    auto stage = [&](int it, int buf) {
        const size_t koff = (size_t)it * 128;
        const uint32_t sb = smb + buf * CV_BUF;
        #pragma unroll
        for (int p = 0; p < 4; ++p) {   // A: weights 128 rows x 128B
            int e = tid + (p << 8);
            int row = e >> 3;
            int sg = (e & 7) << 4;
            size_t g = (size_t)row * (KC_ * 2) + koff + sg;
            uint32_t s = SWZ((row << 7) + sg);
            cp16(sb + s, gA + g);
        }
        const int r9 = it >> 3;
        const int dh = r9 / 3 - 1, dw = r9 % 3 - 1;
        const int cb2 = ((it & 7) << 6) * 2;
        #pragma unroll
        for (int p = 0; p < 8; ++p) {             // B: 256 rows x 128B (hi + lo)
            int e = tid + (p << 8);
            int row = e >> 3;
            int sg = (e & 7) << 4;
            uint32_t s = SWZ((row << 7) + sg);
            int l = n0 + row;
            int h = (l >> 5) + dh, w = (l & 31) + dw;
            if ((unsigned)h < 32u && (unsigned)w < 32u) {
                size_t g = ((size_t)(l + dh * 32 + dw) << 10) + cb2 + sg;
                cp16(sb + CV_SUBA + s,           yh + g);
                cp16(sb + CV_SUBA + CV_SUBB + s, yl + g);
            } else {
                uint4 z = make_uint4(0u, 0u, 0u, 0u);
                *(uint4*)(sm + ((size_t)buf * CV_BUF + CV_SUBA + s)) = z;
                *(uint4*)(sm + ((size_t)buf * CV_BUF + CV_SUBA + CV_SUBB + s)) = z;
            }
        }
    };

    float acc[2][16][4];
    #pragma unroll
    for (int i = 0; i < 2; i++)
        #pragma unroll
        for (int j = 0; j < 16; j++)
            #pragma unroll
            for (int t = 0; t < 4; t++) acc[i][j][t] = 0.f;

    const int wm = (wid & 3) << 5, wn = (wid >> 2) << 7;
    const int r = lane & 15, hf = lane >> 4;

    stage(0, 0);
    CP_COMMIT();
    #pragma unroll 1
    for (int it = 0; it < NCHUNK; ++it) {
        const int buf = it & 1;
        if (it + 1 < NCHUNK) { stage(it + 1, buf ^ 1); CP_COMMIT(); CP_WAIT(1); }
        else CP_WAIT(0);
        __syncthreads();
        const uint32_t sA = smb + buf * CV_BUF;
        const uint32_t sB = sA + CV_SUBA, sBl = sB + CV_SUBB;
        #pragma unroll
        for (int ks = 0; ks < 4; ++ks) {
            const int kb = ks << 5;
            uint32_t ah[2][4];
            #pragma unroll
            for (int mt = 0; mt < 2; ++mt) {
                uint32_t rel = SWZ(((wm + (mt << 4) + r) << 7) + kb + (hf << 4));
                ldmx4(ah[mt], sA + rel);
            }
            #pragma unroll
            for (int np = 0; np < 8; ++np) {
                uint32_t rel = SWZ(((wn + (np << 4) + r) << 7) + kb + (hf << 4));
                uint32_t bh[4], bl[4];
                ldmx4(bh, sB + rel);
                ldmx4(bl, sBl + rel);
                #pragma unroll
                for (int mt = 0; mt < 2; ++mt)
                    #pragma unroll
                    for (int sub = 0; sub < 2; ++sub) {
                        float* c = acc[mt][np * 2 + sub];
                        mma16816h(c, ah[mt], bh[sub], bh[sub + 2]);
                        mma16816h(c, ah[mt], bl[sub], bl[sub + 2]);
                    }
            }
        }
        __syncthreads();
    }

    const int lrow = lane >> 2, lcol = (lane & 3) << 1;
    #pragma unroll
    for (int mt = 0; mt < 2; ++mt) {
        #pragma unroll
        for (int nt = 0; nt < 16; ++nt) {
            const float* c = acc[mt][nt];
            int l = n0 + wn + (nt << 3) + lcol;
            #pragma unroll
            for (int half = 0; half < 2; ++half) {
                int o = m0 + wm + (mt << 4) + lrow + half * 8;
                float bv = bias_fc[o];
                size_t idx = ((size_t)(bb * C_ + o) << 10) + l;
                float2 xr = *(const float2*)(g_xres + idx);
                float2 o2;
                o2.x = c[half * 2 + 0] + bv + xr.x;
                o2.y = c[half * 2 + 1] + bv + xr.y;
                *(float2*)(out + idx) = o2;
            }
        }
    }
}

// ---------------- launch ----------------
extern "C" void kernel_launch(void* const* d_in, const int* in_sizes, int n_in,
                              void* d_out, int out_size) {
    const float* x       = (const float*)d_in[0];
    const float* w_qk    = (const float*)d_in[1];
    const float* w_v     = (const float*)d_in[2];
    const float* rel_h   = (const float*)d_in[3];
    const float* rel_w   = (const float*)d_in[4];
    const float* g1      = (const float*)d_in[5];
    const float* b1      = (const float*)d_in[6];
    const float* m1      = (const float*)d_in[7];
    const float* v1      = (const float*)d_in[8];
    const float* g2      = (const float*)d_in[9];
    const float* b2      = (const float*)d_in[10];
    const float* m2      = (const float*)d_in[11];
    const float* v2      = (const float*)d_in[12];
    const float* w_fc    = (const float*)d_in[13];
    const float* bias_fc = (const float*)d_in[14];
    float* out = (float*)d_out;

    cudaFuncSetAttribute(proj_mma_kernel, cudaFuncAttributeMaxDynamicSharedMemorySize, PROJ_SMEM);
    cudaFuncSetAttribute(flash_kernel,    cudaFuncAttributeMaxDynamicSharedMemorySize, FA_SMEM);
    cudaFuncSetAttribute(conv_mma_kernel, cudaFuncAttributeMaxDynamicSharedMemorySize, CONV_SMEM);

    wqkv2bf_kernel<<<(1536 * 512 + 16384) / 256, 256>>>(w_qk, w_v, rel_h, rel_w);
    w2bf_kernel<<<(C_ * KC_) / 256, 256>>>(w_fc);
    bn1t_kernel<<<dim3(32, 16, B_), 256>>>(x, g1, b1, m1, v1);
    proj_mma_kernel<<<dim3(12, 8, B_), 256, PROJ_SMEM>>>();
    flash_kernel<<<dim3(8, 32), 256, FA_SMEM>>>(x);
    bn2t_kernel<<<dim3(32, 16, B_), 256>>>(g2, b2, m2, v2);
    conv_mma_kernel<<<dim3(4, 4, B_), 256, CONV_SMEM>>>(bias_fc, out);
}

// round 14
// speedup vs baseline: 2.2775x; 1.2963x over previous
#include <cuda_runtime.h>
#include <cuda_bf16.h>
#include <cuda_fp16.h>
#include <cstdint>

// ---------------- problem constants ----------------
#define B_   8
#define C_   512
#define HH_  32
#define WW_  32
#define L_   1024          // HH*WW
#define NH_  4
#define D_   128
#define KC_  4608          // 512*9 (im2col K)
#define QSCALE 0.08838834764831845f  // 128^-0.5

// ---------------- scratch (device globals; no allocations) ----------------
__device__ __half g_xn[B_*L_*C_];            // relu(bn1(x)) transposed [b][l][c] fp16
__device__ __half g_wqkv[1536*512];          // [o][c], o: q|k|v  fp16
__device__ __half g_rel[128*128];            // rows: 0..62 rel_w, 63..125 rel_h, 126..127 zero
__device__ __half g_q[32*L_*D_];             // [bn][l][d] (scaled) fp16
__device__ __half g_k[32*L_*D_];
__device__ __half g_v[32*L_*D_];
__device__ float g_xres[B_*C_*L_];           // mhsa out + x
__device__ __half g_y2t[B_*L_*C_];           // relu(bn2(xres)) transposed fp16
__device__ __half g_w_f[(size_t)C_*KC_];     // conv weights fp16, reordered [o][r9*512 + c]

// ================= mma.sync helpers =================
__device__ __forceinline__ uint32_t smem_u32(const void* p) {
    uint32_t a;
    asm("{ .reg .u64 t; cvta.to.shared.u64 t, %1; cvt.u32.u64 %0, t; }" : "=r"(a) : "l"(p));
    return a;
}
__device__ __forceinline__ void cp16(uint32_t s, const void* g) {
    asm volatile("cp.async.cg.shared.global [%0], [%1], 16;" :: "r"(s), "l"(g));
}
#define CP_COMMIT() asm volatile("cp.async.commit_group;" ::: "memory")
#define CP_WAIT(n)  asm volatile("cp.async.wait_group %0;" :: "n"(n) : "memory")

__device__ __forceinline__ void ldmx4(uint32_t* d, uint32_t addr) {
    asm volatile("ldmatrix.sync.aligned.m8n8.x4.shared.b16 {%0,%1,%2,%3}, [%4];"
                 : "=r"(d[0]), "=r"(d[1]), "=r"(d[2]), "=r"(d[3]) : "r"(addr));
}
__device__ __forceinline__ void ldmx4t(uint32_t* d, uint32_t addr) {
    asm volatile("ldmatrix.sync.aligned.m8n8.x4.trans.shared.b16 {%0,%1,%2,%3}, [%4];"
                 : "=r"(d[0]), "=r"(d[1]), "=r"(d[2]), "=r"(d[3]) : "r"(addr));
}
__device__ __forceinline__ void mma16816h(float* c, const uint32_t* a, uint32_t b0, uint32_t b1) {
    asm volatile("mma.sync.aligned.m16n8k16.row.col.f32.f16.f16.f32 "
                 "{%0,%1,%2,%3}, {%4,%5,%6,%7}, {%8,%9}, {%0,%1,%2,%3};"
                 : "+f"(c[0]), "+f"(c[1]), "+f"(c[2]), "+f"(c[3])
                 : "r"(a[0]), "r"(a[1]), "r"(a[2]), "r"(a[3]), "r"(b0), "r"(b1));
}
#define SWZ(x) ((x) ^ (((x) >> 3) & 0x70))

__device__ __forceinline__ uint32_t pack_h2(float a, float b) {
    __half2 h = __floats2half2_rn(a, b);
    return *(uint32_t*)&h;
}

// ---------------- BN1 + ReLU + transpose -> fp16 [b][l][c] ----------------
__global__ void bn1t_kernel(const float* __restrict__ x,
                            const float* __restrict__ g, const float* __restrict__ bb,
                            const float* __restrict__ m, const float* __restrict__ v) {
    __shared__ float t[32][33];
    const int b = blockIdx.z, c0 = blockIdx.y * 32, l0 = blockIdx.x * 32;
    const int tid = threadIdx.x;
    {
        const int cr = tid >> 3, l4 = (tid & 7) * 4;
        const int c = c0 + cr;
        float inv = g[c] * rsqrtf(v[c] + 1e-5f);
        float sh  = bb[c] - m[c] * inv;
        float4 xv = *(const float4*)(x + ((size_t)(b * C_ + c) << 10) + l0 + l4);
        t[cr][l4 + 0] = fmaxf(fmaf(xv.x, inv, sh), 0.f);
        t[cr][l4 + 1] = fmaxf(fmaf(xv.y, inv, sh), 0.f);
        t[cr][l4 + 2] = fmaxf(fmaf(xv.z, inv, sh), 0.f);
        t[cr][l4 + 3] = fmaxf(fmaf(xv.w, inv, sh), 0.f);
    }
    __syncthreads();
    {
        const int lr = tid >> 3, c4 = (tid & 7) * 4;
        size_t base = ((size_t)(b * L_ + l0 + lr) << 9) + c0 + c4;
        *(uint32_t*)(g_xn + base)     = pack_h2(t[c4 + 0][lr], t[c4 + 1][lr]);
        *(uint32_t*)(g_xn + base + 2) = pack_h2(t[c4 + 2][lr], t[c4 + 3][lr]);
    }
}

// ---------------- BN2 + ReLU + transpose -> fp16 [b][l][c] ----------------
__global__ void bn2t_kernel(const float* __restrict__ g, const float* __restrict__ bb,
                            const float* __restrict__ m, const float* __restrict__ v) {
    __shared__ float t[32][33];
    const int b = blockIdx.z, c0 = blockIdx.y * 32, l0 = blockIdx.x * 32;
    const int tid = threadIdx.x;
    {
        const int cr = tid >> 3, l4 = (tid & 7) * 4;
        const int c = c0 + cr;
        float inv = g[c] * rsqrtf(v[c] + 1e-5f);
        float sh  = bb[c] - m[c] * inv;
        float4 xv = *(const float4*)(g_xres + ((size_t)(b * C_ + c) << 10) + l0 + l4);
        t[cr][l4 + 0] = fmaxf(fmaf(xv.x, inv, sh), 0.f);
        t[cr][l4 + 1] = fmaxf(fmaf(xv.y, inv, sh), 0.f);
        t[cr][l4 + 2] = fmaxf(fmaf(xv.z, inv, sh), 0.f);
        t[cr][l4 + 3] = fmaxf(fmaf(xv.w, inv, sh), 0.f);
    }
    __syncthreads();
    {
        const int lr = tid >> 3, c4 = (tid & 7) * 4;
        size_t base = ((size_t)(b * L_ + l0 + lr) << 9) + c0 + c4;
        *(uint32_t*)(g_y2t + base)     = pack_h2(t[c4 + 0][lr], t[c4 + 1][lr]);
        *(uint32_t*)(g_y2t + base + 2) = pack_h2(t[c4 + 2][lr], t[c4 + 3][lr]);
    }
}

// ---------------- qkv weights + rel tables -> fp16 ----------------
__global__ void wqkv2bf_kernel(const float* __restrict__ w_qk, const float* __restrict__ w_v,
                               const float* __restrict__ rel_h, const float* __restrict__ rel_w) {
    int i = blockIdx.x * 256 + threadIdx.x;
    if (i < 1024 * 512) {
        g_wqkv[i] = __float2half(w_qk[i]);
    } else if (i < 1536 * 512) {
        g_wqkv[i] = __float2half(w_v[i - 1024 * 512]);
    } else {
        int j = i - 1536 * 512;          // 0..16383
        int rr = j >> 7, d = j & 127;
        float val = 0.f;
        if (rr < 63)       val = rel_w[rr * 128 + d];
        else if (rr < 126) val = rel_h[(rr - 63) * 128 + d];
        g_rel[j] = __float2half(val);
    }
}

// ---------------- conv weights -> fp16 single, reorder k' = r9*512 + c ----------------
__global__ void w2bf_kernel(const float* __restrict__ w) {
    int i = blockIdx.x * 256 + threadIdx.x;   // src: o*4608 + c*9 + r9
    int o = i / KC_, rem = i % KC_;
    int c = rem / 9, r9 = rem % 9;
    size_t dst = (size_t)o * KC_ + r9 * 512 + c;
    g_w_f[dst] = __float2half(w[i]);
}

// ---------------- QKV projection via mma.sync fp16 single ----------------
// block tile 128x128, K-chunk 64, 256 threads. 1 MMA per product.
#define P_SUB 16384
#define P_BUF (2 * P_SUB)
#define PROJ_SMEM (1024 + 2 * P_BUF)
__global__ __launch_bounds__(256, 1) void proj_mma_kernel() {
    extern __shared__ char smraw[];
    char* sm = (char*)(((uintptr_t)smraw + 1023) & ~(uintptr_t)1023);
    const uint32_t smb = smem_u32(sm);
    const int tid = threadIdx.x, wid = tid >> 5, lane = tid & 31;
    const int b = blockIdx.z, m0 = blockIdx.y * 128, n0 = blockIdx.x * 128;

    const char* gA = (const char*)g_xn + (size_t)(b * L_ + m0) * 1024;
    const char* gB = (const char*)g_wqkv + (size_t)n0 * 1024;

    auto stage = [&](int it, int buf) {
        const uint32_t sb = smb + buf * P_BUF;
        #pragma unroll
        for (int p = 0; p < 4; ++p) {
            int e = tid + (p << 8);
            int row = e >> 3;
            int sg = (e & 7) << 4;
            size_t go = (size_t)row * 1024 + (size_t)it * 128 + sg;
            uint32_t s = SWZ((row << 7) + sg);
            cp16(sb + s,         gA + go);
            cp16(sb + P_SUB + s, gB + go);
        }
    };

    float acc[2][8][4];
    #pragma unroll
    for (int i = 0; i < 2; i++)
        #pragma unroll
        for (int j = 0; j < 8; j++)
            #pragma unroll
            for (int t = 0; t < 4; t++) acc[i][j][t] = 0.f;

    const int wm = (wid & 3) << 5, wn = (wid >> 2) << 6;
    const int r = lane & 15, hf = lane >> 4;

    stage(0, 0);
    CP_COMMIT();
    #pragma unroll 1
    for (int it = 0; it < 8; ++it) {
        const int buf = it & 1;
        if (it + 1 < 8) { stage(it + 1, buf ^ 1); CP_COMMIT(); CP_WAIT(1); }
        else CP_WAIT(0);
        __syncthreads();
        const uint32_t sA = smb + buf * P_BUF, sB = sA + P_SUB;
        #pragma unroll
        for (int ks = 0; ks < 4; ++ks) {
            const int kb = ks << 5;
            uint32_t ah[2][4];
            #pragma unroll
            for (int mt = 0; mt < 2; ++mt) {
                uint32_t rel = SWZ(((wm + (mt << 4) + r) << 7) + kb + (hf << 4));
                ldmx4(ah[mt], sA + rel);
            }
            uint32_t bh[4][4];
            #pragma unroll
            for (int np = 0; np < 4; ++np) {
                uint32_t rel = SWZ(((wn + (np << 4) + r) << 7) + kb + (hf << 4));
                ldmx4(bh[np], sB + rel);
            }
            #pragma unroll
            for (int mt = 0; mt < 2; ++mt)
                #pragma unroll
                for (int np = 0; np < 4; ++np)
                    #pragma unroll
                    for (int sub = 0; sub < 2; ++sub)
                        mma16816h(acc[mt][np * 2 + sub], ah[mt], bh[np][sub], bh[np][sub + 2]);
        }
        __syncthreads();
    }

    const int region = n0 >> 9;                 // 0=q,1=k,2=v
    const int head = (n0 >> 7) & 3;
    const float scale = (region == 0) ? QSCALE : 1.0f;
    __half* dst;
    if (region == 0)      dst = g_q;
    else if (region == 1) dst = g_k;
    else                  dst = g_v;
    const size_t bnbase = (size_t)(b * NH_ + head) * L_ * D_;
    const int lrow = lane >> 2, lcol = (lane & 3) << 1;
    #pragma unroll
    for (int mt = 0; mt < 2; ++mt) {
        #pragma unroll
        for (int nt = 0; nt < 8; ++nt) {
            const float* c = acc[mt][nt];
            const int d0 = wn + (nt << 3) + lcol;
            #pragma unroll
            for (int half = 0; half < 2; ++half) {
                int lv = m0 + wm + (mt << 4) + lrow + half * 8;
                size_t base = bnbase + ((size_t)lv << 7) + d0;
                *(uint32_t*)(dst + base) =
                    pack_h2(c[half * 2 + 0] * scale, c[half * 2 + 1] * scale);
            }
        }
    }
}

// ---------------- fused flash attention (fp16 single) + rel-pos + residual ----------------
// grid (8 m-tiles, 32 bn), 256 threads = 8 warps, each warp 16 rows.
// smem: rdot 64KB fp32 | 2 stages x 32KB (K 16K | V 16K)
#define FA_STG 65536
#define FA_STAGE 32768
#define FA_SMEM (1024 + FA_STG + 2 * FA_STAGE)   // 132096
__global__ __launch_bounds__(256, 1) void flash_kernel(const float* __restrict__ x) {
    extern __shared__ char smraw[];
    char* sm = (char*)(((uintptr_t)smraw + 1023) & ~(uintptr_t)1023);
    const uint32_t smb = smem_u32(sm);
    const int tid = threadIdx.x, wid = tid >> 5, lane = tid & 31;
    const int m0 = blockIdx.x * 128, bn = blockIdx.y;
    const int b = bn >> 2, head = bn & 3;
    const int r = lane & 15, hf = lane >> 4;
    const int r2 = lane >> 2, lcol = (lane & 3) << 1;
    const int tj = (lane & 7) + ((lane >> 4) << 3);
    const int tn = ((lane >> 3) & 1) << 3;
    const int wm = wid << 4;

    // Q -> regs via temp staging in stage buf 1 (32KB, two 128B halves)
    uint32_t qh[8][4];
    {
        const char* gQ = (const char*)g_q + ((size_t)bn * L_ + m0) * 256;
        const uint32_t sbq = smb + FA_STG + FA_STAGE;
        #pragma unroll
        for (int p = 0; p < 8; ++p) {
            int e = tid + (p << 8);
            int row = e >> 4, sg = (e & 15) << 4;
            uint32_t s = ((sg >> 7) << 14) + SWZ((row << 7) + (sg & 127));
            cp16(sbq + s, gQ + (size_t)row * 256 + sg);
        }
        CP_COMMIT(); CP_WAIT(0); __syncthreads();
        #pragma unroll
        for (int ks = 0; ks < 8; ++ks) {
            int ab = (ks << 5) + (hf << 4);
            uint32_t rel = ((ab >> 7) << 14) + SWZ(((wm + r) << 7) + (ab & 127));
            ldmx4(qh[ks], sbq + rel);
        }
        __syncthreads();
    }

    // ---- prologue: rdot = Q @ rel^T into rdot smem (rel staged in buf 0, 32KB) ----
    {
        const char* gR = (const char*)g_rel;
        const uint32_t sb = smb + FA_STG;
        #pragma unroll
        for (int p = 0; p < 8; ++p) {
            int e = tid + (p << 8);
            int row = e >> 4, sg = (e & 15) << 4;
            uint32_t s = ((sg >> 7) << 14) + SWZ((row << 7) + (sg & 127));
            cp16(sb + s, gR + (size_t)row * 256 + sg);
        }
        CP_COMMIT(); CP_WAIT(0); __syncthreads();
        float* rsm = (float*)sm;
        #pragma unroll 1
        for (int ss2 = 0; ss2 < 4; ++ss2) {
            float rs[4][4];
            #pragma unroll
            for (int t = 0; t < 4; ++t)
                #pragma unroll
                for (int u = 0; u < 4; ++u) rs[t][u] = 0.f;
            #pragma unroll
            for (int ks = 0; ks < 8; ++ks) {
                const int ab = (ks << 5) + (hf << 4);
                uint32_t bhf[2][4];
                #pragma unroll
                for (int np = 0; np < 2; ++np) {
                    int jr = (ss2 << 5) + (np << 4) + r;
                    uint32_t rel = ((ab >> 7) << 14) + SWZ((jr << 7) + (ab & 127));
                    ldmx4(bhf[np], sb + rel);
                }
                #pragma unroll
                for (int np = 0; np < 2; ++np)
                    #pragma unroll
                    for (int sub = 0; sub < 2; ++sub)
                        mma16816h(rs[np * 2 + sub], qh[ks], bhf[np][sub], bhf[np][sub + 2]);
            }
            const int j0 = ss2 << 5;
            #pragma unroll
            for (int t = 0; t < 4; ++t) {
                int jj = j0 + (t << 3) + lcol;
                rsm[(wm + r2) * 128 + jj]           = rs[t][0];
                rsm[(wm + r2) * 128 + jj + 1]       = rs[t][1];
                rsm[(wm + r2 + 8) * 128 + jj]       = rs[t][2];
                rsm[(wm + r2 + 8) * 128 + jj + 1]   = rs[t][3];
            }
        }
        __syncthreads();
    }

    const char* gK = (const char*)g_k + (size_t)bn * L_ * 256;
    const char* gV = (const char*)g_v + (size_t)bn * L_ * 256;

    auto stageKV = [&](int jt, int buf) {
        const uint32_t sb = smb + FA_STG + buf * FA_STAGE;
        const size_t base = (size_t)(jt * 64) * 256;
        #pragma unroll
        for (int p = 0; p < 4; ++p) {
            int e = tid + (p << 8);
            int row = e >> 4, sg = (e & 15) << 4;
            uint32_t s = ((sg >> 7) << 13) + SWZ((row << 7) + (sg & 127));
            size_t go = base + (size_t)row * 256 + sg;
            cp16(sb + s,         gK + go);
            cp16(sb + 16384 + s, gV + go);
        }
    };

    const int i0 = m0 + wm + r2, i1 = i0 + 8;
    const int h0 = i0 >> 5, w0 = i0 & 31;
    const int h1 = i1 >> 5, w1 = i1 & 31;
    const float* rd0 = (const float*)(sm + (size_t)(wm + r2) * 512);
    const float* rd1 = (const float*)(sm + (size_t)(wm + r2 + 8) * 512);

    float o[16][4];
    #pragma unroll
    for (int nt = 0; nt < 16; ++nt)
        #pragma unroll
        for (int u = 0; u < 4; ++u) o[nt][u] = 0.f;
    float m0r = -1e30f, m1r = -1e30f, s0r = 0.f, s1r = 0.f;

    stageKV(0, 0);
    CP_COMMIT();

    #pragma unroll 1
    for (int jt = 0; jt < 16; ++jt) {
        const int buf = jt & 1;
        if (jt + 1 < 16) { stageKV(jt + 1, buf ^ 1); CP_COMMIT(); CP_WAIT(1); }
        else CP_WAIT(0);
        __syncthreads();
        const uint32_t kb_s = smb + FA_STG + buf * FA_STAGE;
        const uint32_t vb_s = kb_s + 16384;

        #pragma unroll
        for (int ss = 0; ss < 2; ++ss) {
            // ---- S = Q K^T over this 32-j substep (1 MMA per product) ----
            float s[4][4];
            #pragma unroll
            for (int t = 0; t < 4; ++t)
                #pragma unroll
                for (int u = 0; u < 4; ++u) s[t][u] = 0.f;
            #pragma unroll
            for (int ks = 0; ks < 8; ++ks) {
                const int ab = (ks << 5) + (hf << 4);
                uint32_t bhf[2][4];
                #pragma unroll
                for (int np = 0; np < 2; ++np) {
                    int jr = (ss << 5) + (np << 4) + r;
                    uint32_t rel = ((ab >> 7) << 13) + SWZ((jr << 7) + (ab & 127));
                    ldmx4(bhf[np], kb_s + rel);
                }
                #pragma unroll
                for (int np = 0; np < 2; ++np)
                    #pragma unroll
                    for (int sub = 0; sub < 2; ++sub)
                        mma16816h(s[np * 2 + sub], qh[ks], bhf[np][sub], bhf[np][sub + 2]);
            }

            // ---- bias + row max (32 j) ----
            const int j0 = jt * 64 + (ss << 5);
            float t0 = -1e30f, t1 = -1e30f;
            #pragma unroll
            for (int t = 0; t < 4; ++t) {
                int jj = j0 + t * 8 + lcol;
                int h2 = jj >> 5, w2 = jj & 31;
                float bh0 = rd0[94 + h2 - h0];
                float bh1 = rd1[94 + h2 - h1];
                s[t][0] += rd0[w2 - w0 + 31] + bh0;
                s[t][1] += rd0[w2 + 1 - w0 + 31] + bh0;
                s[t][2] += rd1[w2 - w1 + 31] + bh1;
                s[t][3] += rd1[w2 + 1 - w1 + 31] + bh1;
                t0 = fmaxf(t0, fmaxf(s[t][0], s[t][1]));
                t1 = fmaxf(t1, fmaxf(s[t][2], s[t][3]));
            }
            t0 = fmaxf(t0, __shfl_xor_sync(~0u, t0, 1));
            t0 = fmaxf(t0, __shfl_xor_sync(~0u, t0, 2));
            t1 = fmaxf(t1, __shfl_xor_sync(~0u, t1, 1));
            t1 = fmaxf(t1, __shfl_xor_sync(~0u, t1, 2));

            // ---- online softmax update ----
            float mn0 = fmaxf(m0r, t0), mn1 = fmaxf(m1r, t1);
            float a0 = __expf(m0r - mn0), a1 = __expf(m1r - mn1);
            if (!(a0 == 1.0f && a1 == 1.0f)) {
                #pragma unroll
                for (int nt = 0; nt < 16; ++nt) {
                    o[nt][0] *= a0; o[nt][1] *= a0; o[nt][2] *= a1; o[nt][3] *= a1;
                }
            }
            uint32_t ph[2][4];
            float ts0 = 0.f, ts1 = 0.f;
            #pragma unroll
            for (int t = 0; t < 4; ++t) {
                float p0 = __expf(s[t][0] - mn0), p1 = __expf(s[t][1] - mn0);
                float p2 = __expf(s[t][2] - mn1), p3 = __expf(s[t][3] - mn1);
                ts0 += p0 + p1; ts1 += p2 + p3;
                int kt = t >> 1, wc = (t & 1) << 1;
                ph[kt][wc]     = pack_h2(p0, p1);
                ph[kt][wc + 1] = pack_h2(p2, p3);
            }
            ts0 += __shfl_xor_sync(~0u, ts0, 1); ts0 += __shfl_xor_sync(~0u, ts0, 2);
            ts1 += __shfl_xor_sync(~0u, ts1, 1); ts1 += __shfl_xor_sync(~0u, ts1, 2);
            s0r = s0r * a0 + ts0; s1r = s1r * a1 + ts1;
            m0r = mn0; m1r = mn1;

            // ---- O += P V (k = 32, 1 MMA per product) ----
            #pragma unroll
            for (int kt = 0; kt < 2; ++kt) {
                #pragma unroll
                for (int np = 0; np < 8; ++np) {
                    int jrow = (ss << 5) + (kt << 4) + tj;
                    int db = ((np << 4) + tn) << 1;
                    uint32_t rel = ((db >> 7) << 13) + SWZ((jrow << 7) + (db & 127));
                    uint32_t vh4[4];
                    ldmx4t(vh4, vb_s + rel);
                    #pragma unroll
                    for (int sub = 0; sub < 2; ++sub)
                        mma16816h(o[np * 2 + sub], ph[kt], vh4[sub], vh4[sub + 2]);
                }
            }
        }
        __syncthreads();
    }

    // ---- epilogue: normalize -> smem transpose -> coalesced residual+store ----
    __syncthreads();
    float* so = (float*)sm;                 // [128 d][136 stride] fp32
    const float inv0 = 1.f / s0r, inv1 = 1.f / s1r;
    #pragma unroll
    for (int nt = 0; nt < 16; ++nt) {
        const int d0 = (nt << 3) + lcol;
        #pragma unroll
        for (int u = 0; u < 2; ++u) {
            so[(d0 + u) * 136 + wm + r2]     = o[nt][u] * inv0;
            so[(d0 + u) * 136 + wm + r2 + 8] = o[nt][2 + u] * inv1;
        }
    }
    __syncthreads();
    #pragma unroll
    for (int ch = 0; ch < 16; ++ch) {
        const int d = (ch << 3) + (tid >> 5);
        const int i4 = (tid & 31) << 2;
        const size_t idx = ((size_t)(b * C_ + head * D_ + d) << 10) + m0 + i4;
        float4 xr = *(const float4*)(x + idx);
        float4 ov = *(const float4*)(so + d * 136 + i4);
        ov.x += xr.x; ov.y += xr.y; ov.z += xr.z; ov.w += xr.w;
        *(float4*)(g_xres + idx) = ov;
    }
}

// ---------------- conv GEMM via mma.sync fp16 single x single (1 MMA per product) -------
// tile M=128 (o) x N=256 (l); grid (4,4,8) = 128 CTAs = one full wave. 256 threads.
#define NCHUNK 72
#define CV_SUBA 16384
#define CV_SUBB 32768
#define CV_BUF (CV_SUBA + CV_SUBB)           // A | B = 48KB
#define CONV_SMEM (1024 + 2 * CV_BUF)
__global__ __launch_bounds__(256, 1) void conv_mma_kernel(const float* __restrict__ bias_fc,
                                                          float* __restrict__ out) {
    extern __shared__ char smraw[];
    char* sm = (char*)(((uintptr_t)smraw + 1023) & ~(uintptr_t)1023);
    const uint32_t smb = smem_u32(sm);
    const int tid = threadIdx.x, wid = tid >> 5, lane = tid & 31;
    const int bb = blockIdx.z, m0 = blockIdx.y * 128, n0 = blockIdx.x * 256;

    const char* gA = (const char*)g_w_f + (size_t)m0 * (KC_ * 2);
    const char* gY = (const char*)g_y2t + (size_t)bb * L_ * 1024;

    auto stage = [&](int it, int buf) {
        const size_t koff = (size_t)it * 128;
        const uint32_t sb = smb + buf * CV_BUF;
        #pragma unroll
        for (int p = 0; p < 4; ++p) {   // A: weights 128 rows x 128B
            int e = tid + (p << 8);
            int row = e >> 3;
            int sg = (e & 7) << 4;
            size_t g = (size_t)row * (KC_ * 2) + koff + sg;
            uint32_t s = SWZ((row << 7) + sg);
            cp16(sb + s, gA + g);
        }
        const int r9 = it >> 3;
        const int dh = r9 / 3 - 1, dw = r9 % 3 - 1;
        const int cb2 = ((it & 7) << 6) * 2;
        #pragma unroll
        for (int p = 0; p < 8; ++p) {             // B: 256 rows x 128B
            int e = tid + (p << 8);
            int row = e >> 3;
            int sg = (e & 7) << 4;
            uint32_t s = SWZ((row << 7) + sg);
            int l = n0 + row;
            int h = (l >> 5) + dh, w = (l & 31) + dw;
            if ((unsigned)h < 32u && (unsigned)w < 32u) {
                size_t g = ((size_t)(l + dh * 32 + dw) << 10) + cb2 + sg;
                cp16(sb + CV_SUBA + s, gY + g);
            } else {
                uint4 z = make_uint4(0u, 0u, 0u, 0u);
                *(uint4*)(sm + ((size_t)buf * CV_BUF + CV_SUBA + s)) = z;
            }
        }
    };

    float acc[2][16][4];
    #pragma unroll
    for (int i = 0; i < 2; i++)
        #pragma unroll
        for (int j = 0; j < 16; j++)
            #pragma unroll
            for (int t = 0; t < 4; t++) acc[i][j][t] = 0.f;

    const int wm = (wid & 3) << 5, wn = (wid >> 2) << 7;
    const int r = lane & 15, hf = lane >> 4;

    stage(0, 0);
    CP_COMMIT();
    #pragma unroll 1
    for (int it = 0; it < NCHUNK; ++it) {
        const int buf = it & 1;
        if (it + 1 < NCHUNK) { stage(it + 1, buf ^ 1); CP_COMMIT(); CP_WAIT(1); }
        else CP_WAIT(0);
        __syncthreads();
        const uint32_t sA = smb + buf * CV_BUF;
        const uint32_t sB = sA + CV_SUBA;
        #pragma unroll
        for (int ks = 0; ks < 4; ++ks) {
            const int kb = ks << 5;
            uint32_t ah[2][4];
            #pragma unroll
            for (int mt = 0; mt < 2; ++mt) {
                uint32_t rel = SWZ(((wm + (mt << 4) + r) << 7) + kb + (hf << 4));
                ldmx4(ah[mt], sA + rel);
            }
            #pragma unroll
            for (int np = 0; np < 8; ++np) {
                uint32_t rel = SWZ(((wn + (np << 4) + r) << 7) + kb + (hf << 4));
                uint32_t bh[4];
                ldmx4(bh, sB + rel);
                #pragma unroll
                for (int mt = 0; mt < 2; ++mt)
                    #pragma unroll
                    for (int sub = 0; sub < 2; ++sub)
                        mma16816h(acc[mt][np * 2 + sub], ah[mt], bh[sub], bh[sub + 2]);
            }
        }
        __syncthreads();
    }

    const int lrow = lane >> 2, lcol = (lane & 3) << 1;
    #pragma unroll
    for (int mt = 0; mt < 2; ++mt) {
        #pragma unroll
        for (int nt = 0; nt < 16; ++nt) {
            const float* c = acc[mt][nt];
            int l = n0 + wn + (nt << 3) + lcol;
            #pragma unroll
            for (int half = 0; half < 2; ++half) {
                int o = m0 + wm + (mt << 4) + lrow + half * 8;
                float bv = bias_fc[o];
                size_t idx = ((size_t)(bb * C_ + o) << 10) + l;
                float2 xr = *(const float2*)(g_xres + idx);
                float2 o2;
                o2.x = c[half * 2 + 0] + bv + xr.x;
                o2.y = c[half * 2 + 1] + bv + xr.y;
                *(float2*)(out + idx) = o2;
            }
        }
    }
}

// ---------------- launch ----------------
extern "C" void kernel_launch(void* const* d_in, const int* in_sizes, int n_in,
                              void* d_out, int out_size) {
    const float* x       = (const float*)d_in[0];
    const float* w_qk    = (const float*)d_in[1];
    const float* w_v     = (const float*)d_in[2];
    const float* rel_h   = (const float*)d_in[3];
    const float* rel_w   = (const float*)d_in[4];
    const float* g1      = (const float*)d_in[5];
    const float* b1      = (const float*)d_in[6];
    const float* m1      = (const float*)d_in[7];
    const float* v1      = (const float*)d_in[8];
    const float* g2      = (const float*)d_in[9];
    const float* b2      = (const float*)d_in[10];
    const float* m2      = (const float*)d_in[11];
    const float* v2      = (const float*)d_in[12];
    const float* w_fc    = (const float*)d_in[13];
    const float* bias_fc = (const float*)d_in[14];
    float* out = (float*)d_out;

    cudaFuncSetAttribute(proj_mma_kernel, cudaFuncAttributeMaxDynamicSharedMemorySize, PROJ_SMEM);
    cudaFuncSetAttribute(flash_kernel,    cudaFuncAttributeMaxDynamicSharedMemorySize, FA_SMEM);
    cudaFuncSetAttribute(conv_mma_kernel, cudaFuncAttributeMaxDynamicSharedMemorySize, CONV_SMEM);

    wqkv2bf_kernel<<<(1536 * 512 + 16384) / 256, 256>>>(w_qk, w_v, rel_h, rel_w);
    w2bf_kernel<<<(C_ * KC_) / 256, 256>>>(w_fc);
    bn1t_kernel<<<dim3(32, 16, B_), 256>>>(x, g1, b1, m1, v1);
    proj_mma_kernel<<<dim3(12, 8, B_), 256, PROJ_SMEM>>>();
    flash_kernel<<<dim3(8, 32), 256, FA_SMEM>>>(x);
    bn2t_kernel<<<dim3(32, 16, B_), 256>>>(g2, b2, m2, v2);
    conv_mma_kernel<<<dim3(4, 4, B_), 256, CONV_SMEM>>>(bias_fc, out);
}

// round 15
// speedup vs baseline: 2.3345x; 1.0250x over previous
#include <cuda_runtime.h>
#include <cuda_bf16.h>
#include <cuda_fp16.h>
#include <cstdint>

// ---------------- problem constants ----------------
#define B_   8
#define C_   512
#define HH_  32
#define WW_  32
#define L_   1024          // HH*WW
#define NH_  4
#define D_   128
#define KC_  4608          // 512*9 (im2col K)
#define QSCALE 0.08838834764831845f  // 128^-0.5

// ---------------- scratch (device globals; no allocations) ----------------
__device__ __half g_xn[B_*L_*C_];            // relu(bn1(x)) transposed [b][l][c] fp16
__device__ __half g_wqkv[1536*512];          // [o][c], o: q|k|v  fp16
__device__ __half g_rel[128*128];            // rows: 0..62 rel_w, 63..125 rel_h, 126..127 zero
__device__ __half g_q[32*L_*D_];             // [bn][l][d] (scaled) fp16
__device__ __half g_k[32*L_*D_];
__device__ __half g_v[32*L_*D_];
__device__ float g_xres[B_*C_*L_];           // mhsa out + x
__device__ __half g_y2t[B_*L_*C_];           // relu(bn2(xres)) transposed fp16
__device__ __half g_w_f[(size_t)C_*KC_];     // conv weights fp16, reordered [o][r9*512 + c]

// ================= mma.sync helpers =================
__device__ __forceinline__ uint32_t smem_u32(const void* p) {
    uint32_t a;
    asm("{ .reg .u64 t; cvta.to.shared.u64 t, %1; cvt.u32.u64 %0, t; }" : "=r"(a) : "l"(p));
    return a;
}
__device__ __forceinline__ void cp16(uint32_t s, const void* g) {
    asm volatile("cp.async.cg.shared.global [%0], [%1], 16;" :: "r"(s), "l"(g));
}
#define CP_COMMIT() asm volatile("cp.async.commit_group;" ::: "memory")
#define CP_WAIT(n)  asm volatile("cp.async.wait_group %0;" :: "n"(n) : "memory")

__device__ __forceinline__ void ldmx4(uint32_t* d, uint32_t addr) {
    asm volatile("ldmatrix.sync.aligned.m8n8.x4.shared.b16 {%0,%1,%2,%3}, [%4];"
                 : "=r"(d[0]), "=r"(d[1]), "=r"(d[2]), "=r"(d[3]) : "r"(addr));
}
__device__ __forceinline__ void ldmx4t(uint32_t* d, uint32_t addr) {
    asm volatile("ldmatrix.sync.aligned.m8n8.x4.trans.shared.b16 {%0,%1,%2,%3}, [%4];"
                 : "=r"(d[0]), "=r"(d[1]), "=r"(d[2]), "=r"(d[3]) : "r"(addr));
}
__device__ __forceinline__ void mma16816h(float* c, const uint32_t* a, uint32_t b0, uint32_t b1) {
    asm volatile("mma.sync.aligned.m16n8k16.row.col.f32.f16.f16.f32 "
                 "{%0,%1,%2,%3}, {%4,%5,%6,%7}, {%8,%9}, {%0,%1,%2,%3};"
                 : "+f"(c[0]), "+f"(c[1]), "+f"(c[2]), "+f"(c[3])
                 : "r"(a[0]), "r"(a[1]), "r"(a[2]), "r"(a[3]), "r"(b0), "r"(b1));
}
#define SWZ(x) ((x) ^ (((x) >> 3) & 0x70))

__device__ __forceinline__ uint32_t pack_h2(float a, float b) {
    __half2 h = __floats2half2_rn(a, b);
    return *(uint32_t*)&h;
}

// ---------------- BN1 + ReLU + transpose -> fp16 [b][l][c] ----------------
__global__ void bn1t_kernel(const float* __restrict__ x,
                            const float* __restrict__ g, const float* __restrict__ bb,
                            const float* __restrict__ m, const float* __restrict__ v) {
    __shared__ float t[32][33];
    const int b = blockIdx.z, c0 = blockIdx.y * 32, l0 = blockIdx.x * 32;
    const int tid = threadIdx.x;
    {
        const int cr = tid >> 3, l4 = (tid & 7) * 4;
        const int c = c0 + cr;
        float inv = g[c] * rsqrtf(v[c] + 1e-5f);
        float sh  = bb[c] - m[c] * inv;
        float4 xv = *(const float4*)(x + ((size_t)(b * C_ + c) << 10) + l0 + l4);
        t[cr][l4 + 0] = fmaxf(fmaf(xv.x, inv, sh), 0.f);
        t[cr][l4 + 1] = fmaxf(fmaf(xv.y, inv, sh), 0.f);
        t[cr][l4 + 2] = fmaxf(fmaf(xv.z, inv, sh), 0.f);
        t[cr][l4 + 3] = fmaxf(fmaf(xv.w, inv, sh), 0.f);
    }
    __syncthreads();
    {
        const int lr = tid >> 3, c4 = (tid & 7) * 4;
        size_t base = ((size_t)(b * L_ + l0 + lr) << 9) + c0 + c4;
        *(uint32_t*)(g_xn + base)     = pack_h2(t[c4 + 0][lr], t[c4 + 1][lr]);
        *(uint32_t*)(g_xn + base + 2) = pack_h2(t[c4 + 2][lr], t[c4 + 3][lr]);
    }
}

// ---------------- BN2 + ReLU + transpose -> fp16 [b][l][c] ----------------
__global__ void bn2t_kernel(const float* __restrict__ g, const float* __restrict__ bb,
                            const float* __restrict__ m, const float* __restrict__ v) {
    __shared__ float t[32][33];
    const int b = blockIdx.z, c0 = blockIdx.y * 32, l0 = blockIdx.x * 32;
    const int tid = threadIdx.x;
    {
        const int cr = tid >> 3, l4 = (tid & 7) * 4;
        const int c = c0 + cr;
        float inv = g[c] * rsqrtf(v[c] + 1e-5f);
        float sh  = bb[c] - m[c] * inv;
        float4 xv = *(const float4*)(g_xres + ((size_t)(b * C_ + c) << 10) + l0 + l4);
        t[cr][l4 + 0] = fmaxf(fmaf(xv.x, inv, sh), 0.f);
        t[cr][l4 + 1] = fmaxf(fmaf(xv.y, inv, sh), 0.f);
        t[cr][l4 + 2] = fmaxf(fmaf(xv.z, inv, sh), 0.f);
        t[cr][l4 + 3] = fmaxf(fmaf(xv.w, inv, sh), 0.f);
    }
    __syncthreads();
    {
        const int lr = tid >> 3, c4 = (tid & 7) * 4;
        size_t base = ((size_t)(b * L_ + l0 + lr) << 9) + c0 + c4;
        *(uint32_t*)(g_y2t + base)     = pack_h2(t[c4 + 0][lr], t[c4 + 1][lr]);
        *(uint32_t*)(g_y2t + base + 2) = pack_h2(t[c4 + 2][lr], t[c4 + 3][lr]);
    }
}

// ---------------- qkv weights + rel tables -> fp16 ----------------
__global__ void wqkv2bf_kernel(const float* __restrict__ w_qk, const float* __restrict__ w_v,
                               const float* __restrict__ rel_h, const float* __restrict__ rel_w) {
    int i = blockIdx.x * 256 + threadIdx.x;
    if (i < 1024 * 512) {
        g_wqkv[i] = __float2half(w_qk[i]);
    } else if (i < 1536 * 512) {
        g_wqkv[i] = __float2half(w_v[i - 1024 * 512]);
    } else {
        int j = i - 1536 * 512;          // 0..16383
        int rr = j >> 7, d = j & 127;
        float val = 0.f;
        if (rr < 63)       val = rel_w[rr * 128 + d];
        else if (rr < 126) val = rel_h[(rr - 63) * 128 + d];
        g_rel[j] = __float2half(val);
    }
}

// ---------------- conv weights -> fp16 single, reorder k' = r9*512 + c ----------------
__global__ void w2bf_kernel(const float* __restrict__ w) {
    int i = blockIdx.x * 256 + threadIdx.x;   // src: o*4608 + c*9 + r9
    int o = i / KC_, rem = i % KC_;
    int c = rem / 9, r9 = rem % 9;
    size_t dst = (size_t)o * KC_ + r9 * 512 + c;
    g_w_f[dst] = __float2half(w[i]);
}

// ---------------- QKV projection via mma.sync fp16 single ----------------
#define P_SUB 16384
#define P_BUF (2 * P_SUB)
#define PROJ_SMEM (1024 + 2 * P_BUF)
__global__ __launch_bounds__(256, 1) void proj_mma_kernel() {
    extern __shared__ char smraw[];
    char* sm = (char*)(((uintptr_t)smraw + 1023) & ~(uintptr_t)1023);
    const uint32_t smb = smem_u32(sm);
    const int tid = threadIdx.x, wid = tid >> 5, lane = tid & 31;
    const int b = blockIdx.z, m0 = blockIdx.y * 128, n0 = blockIdx.x * 128;

    const char* gA = (const char*)g_xn + (size_t)(b * L_ + m0) * 1024;
    const char* gB = (const char*)g_wqkv + (size_t)n0 * 1024;

    auto stage = [&](int it, int buf) {
        const uint32_t sb = smb + buf * P_BUF;
        #pragma unroll
        for (int p = 0; p < 4; ++p) {
            int e = tid + (p << 8);
            int row = e >> 3;
            int sg = (e & 7) << 4;
            size_t go = (size_t)row * 1024 + (size_t)it * 128 + sg;
            uint32_t s = SWZ((row << 7) + sg);
            cp16(sb + s,         gA + go);
            cp16(sb + P_SUB + s, gB + go);
        }
    };

    float acc[2][8][4];
    #pragma unroll
    for (int i = 0; i < 2; i++)
        #pragma unroll
        for (int j = 0; j < 8; j++)
            #pragma unroll
            for (int t = 0; t < 4; t++) acc[i][j][t] = 0.f;

    const int wm = (wid & 3) << 5, wn = (wid >> 2) << 6;
    const int r = lane & 15, hf = lane >> 4;

    stage(0, 0);
    CP_COMMIT();
    #pragma unroll 1
    for (int it = 0; it < 8; ++it) {
        const int buf = it & 1;
        if (it + 1 < 8) { stage(it + 1, buf ^ 1); CP_COMMIT(); CP_WAIT(1); }
        else CP_WAIT(0);
        __syncthreads();
        const uint32_t sA = smb + buf * P_BUF, sB = sA + P_SUB;
        #pragma unroll
        for (int ks = 0; ks < 4; ++ks) {
            const int kb = ks << 5;
            uint32_t ah[2][4];
            #pragma unroll
            for (int mt = 0; mt < 2; ++mt) {
                uint32_t rel = SWZ(((wm + (mt << 4) + r) << 7) + kb + (hf << 4));
                ldmx4(ah[mt], sA + rel);
            }
            uint32_t bh[4][4];
            #pragma unroll
            for (int np = 0; np < 4; ++np) {
                uint32_t rel = SWZ(((wn + (np << 4) + r) << 7) + kb + (hf << 4));
                ldmx4(bh[np], sB + rel);
            }
            #pragma unroll
            for (int mt = 0; mt < 2; ++mt)
                #pragma unroll
                for (int np = 0; np < 4; ++np)
                    #pragma unroll
                    for (int sub = 0; sub < 2; ++sub)
                        mma16816h(acc[mt][np * 2 + sub], ah[mt], bh[np][sub], bh[np][sub + 2]);
        }
        __syncthreads();
    }

    const int region = n0 >> 9;                 // 0=q,1=k,2=v
    const int head = (n0 >> 7) & 3;
    const float scale = (region == 0) ? QSCALE : 1.0f;
    __half* dst;
    if (region == 0)      dst = g_q;
    else if (region == 1) dst = g_k;
    else                  dst = g_v;
    const size_t bnbase = (size_t)(b * NH_ + head) * L_ * D_;
    const int lrow = lane >> 2, lcol = (lane & 3) << 1;
    #pragma unroll
    for (int mt = 0; mt < 2; ++mt) {
        #pragma unroll
        for (int nt = 0; nt < 8; ++nt) {
            const float* c = acc[mt][nt];
            const int d0 = wn + (nt << 3) + lcol;
            #pragma unroll
            for (int half = 0; half < 2; ++half) {
                int lv = m0 + wm + (mt << 4) + lrow + half * 8;
                size_t base = bnbase + ((size_t)lv << 7) + d0;
                *(uint32_t*)(dst + base) =
                    pack_h2(c[half * 2 + 0] * scale, c[half * 2 + 1] * scale);
            }
        }
    }
}

// ---------------- fused flash attention (fp16) + rel-pos + residual ----------------
// grid (8 m-tiles, 32 bn), 256 threads = 8 warps, each warp 16 rows.
// One 64-j softmax step per jt (registers fit in single-fp16 mode).
// smem: rdot 64KB fp32 | 2 stages x 32KB (K 16K | V 16K)
#define FA_STG 65536
#define FA_STAGE 32768
#define FA_SMEM (1024 + FA_STG + 2 * FA_STAGE)   // 132096
__global__ __launch_bounds__(256, 1) void flash_kernel(const float* __restrict__ x) {
    extern __shared__ char smraw[];
    char* sm = (char*)(((uintptr_t)smraw + 1023) & ~(uintptr_t)1023);
    const uint32_t smb = smem_u32(sm);
    const int tid = threadIdx.x, wid = tid >> 5, lane = tid & 31;
    const int m0 = blockIdx.x * 128, bn = blockIdx.y;
    const int b = bn >> 2, head = bn & 3;
    const int r = lane & 15, hf = lane >> 4;
    const int r2 = lane >> 2, lcol = (lane & 3) << 1;
    const int tj = (lane & 7) + ((lane >> 4) << 3);
    const int tn = ((lane >> 3) & 1) << 3;
    const int wm = wid << 4;

    // Q -> regs via temp staging in stage buf 1 (32KB, two 128B halves)
    uint32_t qh[8][4];
    {
        const char* gQ = (const char*)g_q + ((size_t)bn * L_ + m0) * 256;
        const uint32_t sbq = smb + FA_STG + FA_STAGE;
        #pragma unroll
        for (int p = 0; p < 8; ++p) {
            int e = tid + (p << 8);
            int row = e >> 4, sg = (e & 15) << 4;
            uint32_t s = ((sg >> 7) << 14) + SWZ((row << 7) + (sg & 127));
            cp16(sbq + s, gQ + (size_t)row * 256 + sg);
        }
        CP_COMMIT(); CP_WAIT(0); __syncthreads();
        #pragma unroll
        for (int ks = 0; ks < 8; ++ks) {
            int ab = (ks << 5) + (hf << 4);
            uint32_t rel = ((ab >> 7) << 14) + SWZ(((wm + r) << 7) + (ab & 127));
            ldmx4(qh[ks], sbq + rel);
        }
        __syncthreads();
    }

    // ---- prologue: rdot = Q @ rel^T into rdot smem (rel staged in buf 0, 32KB) ----
    {
        const char* gR = (const char*)g_rel;
        const uint32_t sb = smb + FA_STG;
        #pragma unroll
        for (int p = 0; p < 8; ++p) {
            int e = tid + (p << 8);
            int row = e >> 4, sg = (e & 15) << 4;
            uint32_t s = ((sg >> 7) << 14) + SWZ((row << 7) + (sg & 127));
            cp16(sb + s, gR + (size_t)row * 256 + sg);
        }
        CP_COMMIT(); CP_WAIT(0); __syncthreads();
        float* rsm = (float*)sm;
        #pragma unroll 1
        for (int ss2 = 0; ss2 < 4; ++ss2) {
            float rs[4][4];
            #pragma unroll
            for (int t = 0; t < 4; ++t)
                #pragma unroll
                for (int u = 0; u < 4; ++u) rs[t][u] = 0.f;
            #pragma unroll
            for (int ks = 0; ks < 8; ++ks) {
                const int ab = (ks << 5) + (hf << 4);
                uint32_t bhf[2][4];
                #pragma unroll
                for (int np = 0; np < 2; ++np) {
                    int jr = (ss2 << 5) + (np << 4) + r;
                    uint32_t rel = ((ab >> 7) << 14) + SWZ((jr << 7) + (ab & 127));
                    ldmx4(bhf[np], sb + rel);
                }
                #pragma unroll
                for (int np = 0; np < 2; ++np)
                    #pragma unroll
                    for (int sub = 0; sub < 2; ++sub)
                        mma16816h(rs[np * 2 + sub], qh[ks], bhf[np][sub], bhf[np][sub + 2]);
            }
            const int j0 = ss2 << 5;
            #pragma unroll
            for (int t = 0; t < 4; ++t) {
                int jj = j0 + (t << 3) + lcol;
                rsm[(wm + r2) * 128 + jj]           = rs[t][0];
                rsm[(wm + r2) * 128 + jj + 1]       = rs[t][1];
                rsm[(wm + r2 + 8) * 128 + jj]       = rs[t][2];
                rsm[(wm + r2 + 8) * 128 + jj + 1]   = rs[t][3];
            }
        }
        __syncthreads();
    }

    const char* gK = (const char*)g_k + (size_t)bn * L_ * 256;
    const char* gV = (const char*)g_v + (size_t)bn * L_ * 256;

    auto stageKV = [&](int jt, int buf) {
        const uint32_t sb = smb + FA_STG + buf * FA_STAGE;
        const size_t base = (size_t)(jt * 64) * 256;
        #pragma unroll
        for (int p = 0; p < 4; ++p) {
            int e = tid + (p << 8);
            int row = e >> 4, sg = (e & 15) << 4;
            uint32_t s = ((sg >> 7) << 13) + SWZ((row << 7) + (sg & 127));
            size_t go = base + (size_t)row * 256 + sg;
            cp16(sb + s,         gK + go);
            cp16(sb + 16384 + s, gV + go);
        }
    };

    const int i0 = m0 + wm + r2, i1 = i0 + 8;
    const int h0 = i0 >> 5, w0 = i0 & 31;
    const int h1 = i1 >> 5, w1 = i1 & 31;
    const float* rd0 = (const float*)(sm + (size_t)(wm + r2) * 512);
    const float* rd1 = (const float*)(sm + (size_t)(wm + r2 + 8) * 512);

    float o[16][4];
    #pragma unroll
    for (int nt = 0; nt < 16; ++nt)
        #pragma unroll
        for (int u = 0; u < 4; ++u) o[nt][u] = 0.f;
    float m0r = -1e30f, m1r = -1e30f, s0r = 0.f, s1r = 0.f;

    stageKV(0, 0);
    CP_COMMIT();

    #pragma unroll 1
    for (int jt = 0; jt < 16; ++jt) {
        const int buf = jt & 1;
        if (jt + 1 < 16) { stageKV(jt + 1, buf ^ 1); CP_COMMIT(); CP_WAIT(1); }
        else CP_WAIT(0);
        __syncthreads();
        const uint32_t kb_s = smb + FA_STG + buf * FA_STAGE;
        const uint32_t vb_s = kb_s + 16384;

        // ---- S = Q K^T over the full 64-j tile ----
        float s[8][4];
        #pragma unroll
        for (int t = 0; t < 8; ++t)
            #pragma unroll
            for (int u = 0; u < 4; ++u) s[t][u] = 0.f;
        #pragma unroll
        for (int ks = 0; ks < 8; ++ks) {
            const int ab = (ks << 5) + (hf << 4);
            uint32_t bhf[4][4];
            #pragma unroll
            for (int np = 0; np < 4; ++np) {
                int jr = (np << 4) + r;
                uint32_t rel = ((ab >> 7) << 13) + SWZ((jr << 7) + (ab & 127));
                ldmx4(bhf[np], kb_s + rel);
            }
            #pragma unroll
            for (int np = 0; np < 4; ++np)
                #pragma unroll
                for (int sub = 0; sub < 2; ++sub)
                    mma16816h(s[np * 2 + sub], qh[ks], bhf[np][sub], bhf[np][sub + 2]);
        }

        // ---- bias + row max (64 j) ----
        const int j0 = jt * 64;
        float t0 = -1e30f, t1 = -1e30f;
        #pragma unroll
        for (int t = 0; t < 8; ++t) {
            int jj = j0 + t * 8 + lcol;
            int h2 = jj >> 5, w2 = jj & 31;
            float bh0 = rd0[94 + h2 - h0];
            float bh1 = rd1[94 + h2 - h1];
            s[t][0] += rd0[w2 - w0 + 31] + bh0;
            s[t][1] += rd0[w2 + 1 - w0 + 31] + bh0;
            s[t][2] += rd1[w2 - w1 + 31] + bh1;
            s[t][3] += rd1[w2 + 1 - w1 + 31] + bh1;
            t0 = fmaxf(t0, fmaxf(s[t][0], s[t][1]));
            t1 = fmaxf(t1, fmaxf(s[t][2], s[t][3]));
        }
        t0 = fmaxf(t0, __shfl_xor_sync(~0u, t0, 1));
        t0 = fmaxf(t0, __shfl_xor_sync(~0u, t0, 2));
        t1 = fmaxf(t1, __shfl_xor_sync(~0u, t1, 1));
        t1 = fmaxf(t1, __shfl_xor_sync(~0u, t1, 2));

        // ---- online softmax update ----
        float mn0 = fmaxf(m0r, t0), mn1 = fmaxf(m1r, t1);
        float a0 = __expf(m0r - mn0), a1 = __expf(m1r - mn1);
        if (!(a0 == 1.0f && a1 == 1.0f)) {
            #pragma unroll
            for (int nt = 0; nt < 16; ++nt) {
                o[nt][0] *= a0; o[nt][1] *= a0; o[nt][2] *= a1; o[nt][3] *= a1;
            }
        }
        uint32_t ph[4][4];
        float ts0 = 0.f, ts1 = 0.f;
        #pragma unroll
        for (int t = 0; t < 8; ++t) {
            float p0 = __expf(s[t][0] - mn0), p1 = __expf(s[t][1] - mn0);
            float p2 = __expf(s[t][2] - mn1), p3 = __expf(s[t][3] - mn1);
            ts0 += p0 + p1; ts1 += p2 + p3;
            int kt = t >> 1, wc = (t & 1) << 1;
            ph[kt][wc]     = pack_h2(p0, p1);
            ph[kt][wc + 1] = pack_h2(p2, p3);
        }
        ts0 += __shfl_xor_sync(~0u, ts0, 1); ts0 += __shfl_xor_sync(~0u, ts0, 2);
        ts1 += __shfl_xor_sync(~0u, ts1, 1); ts1 += __shfl_xor_sync(~0u, ts1, 2);
        s0r = s0r * a0 + ts0; s1r = s1r * a1 + ts1;
        m0r = mn0; m1r = mn1;

        // ---- O += P V (k = 64) ----
        #pragma unroll
        for (int kt = 0; kt < 4; ++kt) {
            #pragma unroll
            for (int np = 0; np < 8; ++np) {
                int jrow = (kt << 4) + tj;
                int db = ((np << 4) + tn) << 1;
                uint32_t rel = ((db >> 7) << 13) + SWZ((jrow << 7) + (db & 127));
                uint32_t vh4[4];
                ldmx4t(vh4, vb_s + rel);
                #pragma unroll
                for (int sub = 0; sub < 2; ++sub)
                    mma16816h(o[np * 2 + sub], ph[kt], vh4[sub], vh4[sub + 2]);
            }
        }
        __syncthreads();
    }

    // ---- epilogue: normalize -> smem transpose -> coalesced residual+store ----
    __syncthreads();
    float* so = (float*)sm;                 // [128 d][136 stride] fp32
    const float inv0 = 1.f / s0r, inv1 = 1.f / s1r;
    #pragma unroll
    for (int nt = 0; nt < 16; ++nt) {
        const int d0 = (nt << 3) + lcol;
        #pragma unroll
        for (int u = 0; u < 2; ++u) {
            so[(d0 + u) * 136 + wm + r2]     = o[nt][u] * inv0;
            so[(d0 + u) * 136 + wm + r2 + 8] = o[nt][2 + u] * inv1;
        }
    }
    __syncthreads();
    #pragma unroll
    for (int ch = 0; ch < 16; ++ch) {
        const int d = (ch << 3) + (tid >> 5);
        const int i4 = (tid & 31) << 2;
        const size_t idx = ((size_t)(b * C_ + head * D_ + d) << 10) + m0 + i4;
        float4 xr = *(const float4*)(x + idx);
        float4 ov = *(const float4*)(so + d * 136 + i4);
        ov.x += xr.x; ov.y += xr.y; ov.z += xr.z; ov.w += xr.w;
        *(float4*)(g_xres + idx) = ov;
    }
}

// ---------------- conv GEMM via mma.sync fp16 single x single (1 MMA per product) -------
// tile M=128 (o) x N=256 (l); grid (4,4,8) = 128 CTAs = one full wave. 256 threads.
#define NCHUNK 72
#define CV_SUBA 16384
#define CV_SUBB 32768
#define CV_BUF (CV_SUBA + CV_SUBB)           // A | B = 48KB
#define CONV_SMEM (1024 + 2 * CV_BUF)
__global__ __launch_bounds__(256, 1) void conv_mma_kernel(const float* __restrict__ bias_fc,
                                                          float* __restrict__ out) {
    extern __shared__ char smraw[];
    char* sm = (char*)(((uintptr_t)smraw + 1023) & ~(uintptr_t)1023);
    const uint32_t smb = smem_u32(sm);
    const int tid = threadIdx.x, wid = tid >> 5, lane = tid & 31;
    const int bb = blockIdx.z, m0 = blockIdx.y * 128, n0 = blockIdx.x * 256;

    const char* gA = (const char*)g_w_f + (size_t)m0 * (KC_ * 2);
    const char* gY = (const char*)g_y2t + (size_t)bb * L_ * 1024;

    auto stage = [&](int it, int buf) {
        const size_t koff = (size_t)it * 128;
        const uint32_t sb = smb + buf * CV_BUF;
        #pragma unroll
        for (int p = 0; p < 4; ++p) {   // A: weights 128 rows x 128B
            int e = tid + (p << 8);
            int row = e >> 3;
            int sg = (e & 7) << 4;
            size_t g = (size_t)row * (KC_ * 2) + koff + sg;
            uint32_t s = SWZ((row << 7) + sg);
            cp16(sb + s, gA + g);
        }
        const int r9 = it >> 3;
        const int dh = r9 / 3 - 1, dw = r9 % 3 - 1;
        const int cb2 = ((it & 7) << 6) * 2;
        #pragma unroll
        for (int p = 0; p < 8; ++p) {             // B: 256 rows x 128B
            int e = tid + (p << 8);
            int row = e >> 3;
            int sg = (e & 7) << 4;
            uint32_t s = SWZ((row << 7) + sg);
            int l = n0 + row;
            int h = (l >> 5) + dh, w = (l & 31) + dw;
            if ((unsigned)h < 32u && (unsigned)w < 32u) {
                size_t g = ((size_t)(l + dh * 32 + dw) << 10) + cb2 + sg;
                cp16(sb + CV_SUBA + s, gY + g);
            } else {
                uint4 z = make_uint4(0u, 0u, 0u, 0u);
                *(uint4*)(sm + ((size_t)buf * CV_BUF + CV_SUBA + s)) = z;
            }
        }
    };

    float acc[2][16][4];
    #pragma unroll
    for (int i = 0; i < 2; i++)
        #pragma unroll
        for (int j = 0; j < 16; j++)
            #pragma unroll
            for (int t = 0; t < 4; t++) acc[i][j][t] = 0.f;

    const int wm = (wid & 3) << 5, wn = (wid >> 2) << 7;
    const int r = lane & 15, hf = lane >> 4;

    stage(0, 0);
    CP_COMMIT();
    #pragma unroll 1
    for (int it = 0; it < NCHUNK; ++it) {
        const int buf = it & 1;
        if (it + 1 < NCHUNK) { stage(it + 1, buf ^ 1); CP_COMMIT(); CP_WAIT(1); }
        else CP_WAIT(0);
        __syncthreads();
        const uint32_t sA = smb + buf * CV_BUF;
        const uint32_t sB = sA + CV_SUBA;
        #pragma unroll
        for (int ks = 0; ks < 4; ++ks) {
            const int kb = ks << 5;
            uint32_t ah[2][4];
            #pragma unroll
            for (int mt = 0; mt < 2; ++mt) {
                uint32_t rel = SWZ(((wm + (mt << 4) + r) << 7) + kb + (hf << 4));
                ldmx4(ah[mt], sA + rel);
            }
            #pragma unroll
            for (int np = 0; np < 8; ++np) {
                uint32_t rel = SWZ(((wn + (np << 4) + r) << 7) + kb + (hf << 4));
                uint32_t bh[4];
                ldmx4(bh, sB + rel);
                #pragma unroll
                for (int mt = 0; mt < 2; ++mt)
                    #pragma unroll
                    for (int sub = 0; sub < 2; ++sub)
                        mma16816h(acc[mt][np * 2 + sub], ah[mt], bh[sub], bh[sub + 2]);
            }
        }
        __syncthreads();
    }

    const int lrow = lane >> 2, lcol = (lane & 3) << 1;
    #pragma unroll
    for (int mt = 0; mt < 2; ++mt) {
        #pragma unroll
        for (int nt = 0; nt < 16; ++nt) {
            const float* c = acc[mt][nt];
            int l = n0 + wn + (nt << 3) + lcol;
            #pragma unroll
            for (int half = 0; half < 2; ++half) {
                int o = m0 + wm + (mt << 4) + lrow + half * 8;
                float bv = bias_fc[o];
                size_t idx = ((size_t)(bb * C_ + o) << 10) + l;
                float2 xr = *(const float2*)(g_xres + idx);
                float2 o2;
                o2.x = c[half * 2 + 0] + bv + xr.x;
                o2.y = c[half * 2 + 1] + bv + xr.y;
                *(float2*)(out + idx) = o2;
            }
        }
    }
}

// ---------------- launch ----------------
extern "C" void kernel_launch(void* const* d_in, const int* in_sizes, int n_in,
                              void* d_out, int out_size) {
    const float* x       = (const float*)d_in[0];
    const float* w_qk    = (const float*)d_in[1];
    const float* w_v     = (const float*)d_in[2];
    const float* rel_h   = (const float*)d_in[3];
    const float* rel_w   = (const float*)d_in[4];
    const float* g1      = (const float*)d_in[5];
    const float* b1      = (const float*)d_in[6];
    const float* m1      = (const float*)d_in[7];
    const float* v1      = (const float*)d_in[8];
    const float* g2      = (const float*)d_in[9];
    const float* b2      = (const float*)d_in[10];
    const float* m2      = (const float*)d_in[11];
    const float* v2      = (const float*)d_in[12];
    const float* w_fc    = (const float*)d_in[13];
    const float* bias_fc = (const float*)d_in[14];
    float* out = (float*)d_out;

    cudaFuncSetAttribute(proj_mma_kernel, cudaFuncAttributeMaxDynamicSharedMemorySize, PROJ_SMEM);
    cudaFuncSetAttribute(flash_kernel,    cudaFuncAttributeMaxDynamicSharedMemorySize, FA_SMEM);
    cudaFuncSetAttribute(conv_mma_kernel, cudaFuncAttributeMaxDynamicSharedMemorySize, CONV_SMEM);

    wqkv2bf_kernel<<<(1536 * 512 + 16384) / 256, 256>>>(w_qk, w_v, rel_h, rel_w);
    w2bf_kernel<<<(C_ * KC_) / 256, 256>>>(w_fc);
    bn1t_kernel<<<dim3(32, 16, B_), 256>>>(x, g1, b1, m1, v1);
    proj_mma_kernel<<<dim3(12, 8, B_), 256, PROJ_SMEM>>>();
    flash_kernel<<<dim3(8, 32), 256, FA_SMEM>>>(x);
    bn2t_kernel<<<dim3(32, 16, B_), 256>>>(g2, b2, m2, v2);
    conv_mma_kernel<<<dim3(4, 4, B_), 256, CONV_SMEM>>>(bias_fc, out);
}

// round 16
// speedup vs baseline: 2.4163x; 1.0350x over previous
#include <cuda_runtime.h>
#include <cuda_bf16.h>
#include <cuda_fp16.h>
#include <cstdint>

// ---------------- problem constants ----------------
#define B_   8
#define C_   512
#define HH_  32
#define WW_  32
#define L_   1024          // HH*WW
#define NH_  4
#define D_   128
#define KC_  4608          // 512*9 (im2col K)
#define QSCALE 0.08838834764831845f  // 128^-0.5

// ---------------- scratch (device globals; no allocations) ----------------
__device__ __half g_xn[B_*L_*C_];            // relu(bn1(x)) transposed [b][l][c] fp16
__device__ __half g_wqkv[1536*512];          // [o][c], o: q|k|v  fp16
__device__ __half g_rel[128*128];            // rows: 0..62 rel_w, 63..125 rel_h, 126..127 zero
__device__ __half g_q[32*L_*D_];             // [bn][l][d] (scaled) fp16
__device__ __half g_k[32*L_*D_];
__device__ __half g_v[32*L_*D_];
__device__ float g_xres[B_*C_*L_];           // mhsa out + x
__device__ __half g_y2t[B_*L_*C_];           // relu(bn2(xres)) transposed fp16
__device__ __half g_w_f[(size_t)C_*KC_];     // conv weights fp16, reordered [o][r9*512 + c]

// ================= mma.sync helpers =================
__device__ __forceinline__ uint32_t smem_u32(const void* p) {
    uint32_t a;
    asm("{ .reg .u64 t; cvta.to.shared.u64 t, %1; cvt.u32.u64 %0, t; }" : "=r"(a) : "l"(p));
    return a;
}
__device__ __forceinline__ void cp16(uint32_t s, const void* g) {
    asm volatile("cp.async.cg.shared.global [%0], [%1], 16;" :: "r"(s), "l"(g));
}
#define CP_COMMIT() asm volatile("cp.async.commit_group;" ::: "memory")
#define CP_WAIT(n)  asm volatile("cp.async.wait_group %0;" :: "n"(n) : "memory")

__device__ __forceinline__ void ldmx4(uint32_t* d, uint32_t addr) {
    asm volatile("ldmatrix.sync.aligned.m8n8.x4.shared.b16 {%0,%1,%2,%3}, [%4];"
                 : "=r"(d[0]), "=r"(d[1]), "=r"(d[2]), "=r"(d[3]) : "r"(addr));
}
__device__ __forceinline__ void ldmx4t(uint32_t* d, uint32_t addr) {
    asm volatile("ldmatrix.sync.aligned.m8n8.x4.trans.shared.b16 {%0,%1,%2,%3}, [%4];"
                 : "=r"(d[0]), "=r"(d[1]), "=r"(d[2]), "=r"(d[3]) : "r"(addr));
}
__device__ __forceinline__ void mma16816h(float* c, const uint32_t* a, uint32_t b0, uint32_t b1) {
    asm volatile("mma.sync.aligned.m16n8k16.row.col.f32.f16.f16.f32 "
                 "{%0,%1,%2,%3}, {%4,%5,%6,%7}, {%8,%9}, {%0,%1,%2,%3};"
                 : "+f"(c[0]), "+f"(c[1]), "+f"(c[2]), "+f"(c[3])
                 : "r"(a[0]), "r"(a[1]), "r"(a[2]), "r"(a[3]), "r"(b0), "r"(b1));
}
#define SWZ(x) ((x) ^ (((x) >> 3) & 0x70))

__device__ __forceinline__ uint32_t pack_h2(float a, float b) {
    __half2 h = __floats2half2_rn(a, b);
    return *(uint32_t*)&h;
}

// ---------------- BN1 + ReLU + transpose -> fp16 [b][l][c] ----------------
__global__ void bn1t_kernel(const float* __restrict__ x,
                            const float* __restrict__ g, const float* __restrict__ bb,
                            const float* __restrict__ m, const float* __restrict__ v) {
    __shared__ float t[32][33];
    const int b = blockIdx.z, c0 = blockIdx.y * 32, l0 = blockIdx.x * 32;
    const int tid = threadIdx.x;
    {
        const int cr = tid >> 3, l4 = (tid & 7) * 4;
        const int c = c0 + cr;
        float inv = g[c] * rsqrtf(v[c] + 1e-5f);
        float sh  = bb[c] - m[c] * inv;
        float4 xv = *(const float4*)(x + ((size_t)(b * C_ + c) << 10) + l0 + l4);
        t[cr][l4 + 0] = fmaxf(fmaf(xv.x, inv, sh), 0.f);
        t[cr][l4 + 1] = fmaxf(fmaf(xv.y, inv, sh), 0.f);
        t[cr][l4 + 2] = fmaxf(fmaf(xv.z, inv, sh), 0.f);
        t[cr][l4 + 3] = fmaxf(fmaf(xv.w, inv, sh), 0.f);
    }
    __syncthreads();
    {
        const int lr = tid >> 3, c4 = (tid & 7) * 4;
        size_t base = ((size_t)(b * L_ + l0 + lr) << 9) + c0 + c4;
        *(uint32_t*)(g_xn + base)     = pack_h2(t[c4 + 0][lr], t[c4 + 1][lr]);
        *(uint32_t*)(g_xn + base + 2) = pack_h2(t[c4 + 2][lr], t[c4 + 3][lr]);
    }
}

// ---------------- BN2 + ReLU + transpose -> fp16 [b][l][c] ----------------
__global__ void bn2t_kernel(const float* __restrict__ g, const float* __restrict__ bb,
                            const float* __restrict__ m, const float* __restrict__ v) {
    __shared__ float t[32][33];
    const int b = blockIdx.z, c0 = blockIdx.y * 32, l0 = blockIdx.x * 32;
    const int tid = threadIdx.x;
    {
        const int cr = tid >> 3, l4 = (tid & 7) * 4;
        const int c = c0 + cr;
        float inv = g[c] * rsqrtf(v[c] + 1e-5f);
        float sh  = bb[c] - m[c] * inv;
        float4 xv = *(const float4*)(g_xres + ((size_t)(b * C_ + c) << 10) + l0 + l4);
        t[cr][l4 + 0] = fmaxf(fmaf(xv.x, inv, sh), 0.f);
        t[cr][l4 + 1] = fmaxf(fmaf(xv.y, inv, sh), 0.f);
        t[cr][l4 + 2] = fmaxf(fmaf(xv.z, inv, sh), 0.f);
        t[cr][l4 + 3] = fmaxf(fmaf(xv.w, inv, sh), 0.f);
    }
    __syncthreads();
    {
        const int lr = tid >> 3, c4 = (tid & 7) * 4;
        size_t base = ((size_t)(b * L_ + l0 + lr) << 9) + c0 + c4;
        *(uint32_t*)(g_y2t + base)     = pack_h2(t[c4 + 0][lr], t[c4 + 1][lr]);
        *(uint32_t*)(g_y2t + base + 2) = pack_h2(t[c4 + 2][lr], t[c4 + 3][lr]);
    }
}

// ---------------- all weights + rel tables -> fp16 (single merged kernel) ----------------
// ranges: [0, 786432) qkv | [786432, 802816) rel | [802816, 3162112) conv
__global__ void wcvt_kernel(const float* __restrict__ w_qk, const float* __restrict__ w_v,
                            const float* __restrict__ rel_h, const float* __restrict__ rel_w,
                            const float* __restrict__ w_fc) {
    int i = blockIdx.x * 256 + threadIdx.x;
    if (i < 1024 * 512) {
        g_wqkv[i] = __float2half(w_qk[i]);
    } else if (i < 1536 * 512) {
        g_wqkv[i] = __float2half(w_v[i - 1024 * 512]);
    } else if (i < 1536 * 512 + 16384) {
        int j = i - 1536 * 512;
        int rr = j >> 7, d = j & 127;
        float val = 0.f;
        if (rr < 63)       val = rel_w[rr * 128 + d];
        else if (rr < 126) val = rel_h[(rr - 63) * 128 + d];
        g_rel[j] = __float2half(val);
    } else {
        int j = i - (1536 * 512 + 16384);     // src: o*4608 + c*9 + r9
        int o = j / KC_, rem = j % KC_;
        int c = rem / 9, r9 = rem % 9;
        size_t dst = (size_t)o * KC_ + r9 * 512 + c;
        g_w_f[dst] = __float2half(w_fc[j]);
    }
}

// ---------------- QKV projection via mma.sync fp16 single (2 CTAs/SM) ----------------
#define P_SUB 16384
#define P_BUF (2 * P_SUB)
#define PROJ_SMEM (1024 + 2 * P_BUF)
__global__ __launch_bounds__(256, 2) void proj_mma_kernel() {
    extern __shared__ char smraw[];
    char* sm = (char*)(((uintptr_t)smraw + 1023) & ~(uintptr_t)1023);
    const uint32_t smb = smem_u32(sm);
    const int tid = threadIdx.x, wid = tid >> 5, lane = tid & 31;
    const int b = blockIdx.z, m0 = blockIdx.y * 128, n0 = blockIdx.x * 128;

    const char* gA = (const char*)g_xn + (size_t)(b * L_ + m0) * 1024;
    const char* gB = (const char*)g_wqkv + (size_t)n0 * 1024;

    auto stage = [&](int it, int buf) {
        const uint32_t sb = smb + buf * P_BUF;
        #pragma unroll
        for (int p = 0; p < 4; ++p) {
            int e = tid + (p << 8);
            int row = e >> 3;
            int sg = (e & 7) << 4;
            size_t go = (size_t)row * 1024 + (size_t)it * 128 + sg;
            uint32_t s = SWZ((row << 7) + sg);
            cp16(sb + s,         gA + go);
            cp16(sb + P_SUB + s, gB + go);
        }
    };

    float acc[2][8][4];
    #pragma unroll
    for (int i = 0; i < 2; i++)
        #pragma unroll
        for (int j = 0; j < 8; j++)
            #pragma unroll
            for (int t = 0; t < 4; t++) acc[i][j][t] = 0.f;

    const int wm = (wid & 3) << 5, wn = (wid >> 2) << 6;
    const int r = lane & 15, hf = lane >> 4;

    stage(0, 0);
    CP_COMMIT();
    #pragma unroll 1
    for (int it = 0; it < 8; ++it) {
        const int buf = it & 1;
        if (it + 1 < 8) { stage(it + 1, buf ^ 1); CP_COMMIT(); CP_WAIT(1); }
        else CP_WAIT(0);
        __syncthreads();
        const uint32_t sA = smb + buf * P_BUF, sB = sA + P_SUB;
        #pragma unroll
        for (int ks = 0; ks < 4; ++ks) {
            const int kb = ks << 5;
            uint32_t ah[2][4];
            #pragma unroll
            for (int mt = 0; mt < 2; ++mt) {
                uint32_t rel = SWZ(((wm + (mt << 4) + r) << 7) + kb + (hf << 4));
                ldmx4(ah[mt], sA + rel);
            }
            uint32_t bh[4][4];
            #pragma unroll
            for (int np = 0; np < 4; ++np) {
                uint32_t rel = SWZ(((wn + (np << 4) + r) << 7) + kb + (hf << 4));
                ldmx4(bh[np], sB + rel);
            }
            #pragma unroll
            for (int mt = 0; mt < 2; ++mt)
                #pragma unroll
                for (int np = 0; np < 4; ++np)
                    #pragma unroll
                    for (int sub = 0; sub < 2; ++sub)
                        mma16816h(acc[mt][np * 2 + sub], ah[mt], bh[np][sub], bh[np][sub + 2]);
        }
        __syncthreads();
    }

    const int region = n0 >> 9;                 // 0=q,1=k,2=v
    const int head = (n0 >> 7) & 3;
    const float scale = (region == 0) ? QSCALE : 1.0f;
    __half* dst;
    if (region == 0)      dst = g_q;
    else if (region == 1) dst = g_k;
    else                  dst = g_v;
    const size_t bnbase = (size_t)(b * NH_ + head) * L_ * D_;
    const int lrow = lane >> 2, lcol = (lane & 3) << 1;
    #pragma unroll
    for (int mt = 0; mt < 2; ++mt) {
        #pragma unroll
        for (int nt = 0; nt < 8; ++nt) {
            const float* c = acc[mt][nt];
            const int d0 = wn + (nt << 3) + lcol;
            #pragma unroll
            for (int half = 0; half < 2; ++half) {
                int lv = m0 + wm + (mt << 4) + lrow + half * 8;
                size_t base = bnbase + ((size_t)lv << 7) + d0;
                *(uint32_t*)(dst + base) =
                    pack_h2(c[half * 2 + 0] * scale, c[half * 2 + 1] * scale);
            }
        }
    }
}

// ---------------- fused flash attention (fp16) + rel-pos + residual ----------------
// grid (8 m-tiles, 32 bn), 256 threads = 8 warps, each warp 16 rows.
// One 64-j softmax step per jt. smem: rdot 64KB fp32 | 2 stages x 32KB (K|V)
#define FA_STG 65536
#define FA_STAGE 32768
#define FA_SMEM (1024 + FA_STG + 2 * FA_STAGE)   // 132096
__global__ __launch_bounds__(256, 1) void flash_kernel(const float* __restrict__ x) {
    extern __shared__ char smraw[];
    char* sm = (char*)(((uintptr_t)smraw + 1023) & ~(uintptr_t)1023);
    const uint32_t smb = smem_u32(sm);
    const int tid = threadIdx.x, wid = tid >> 5, lane = tid & 31;
    const int m0 = blockIdx.x * 128, bn = blockIdx.y;
    const int b = bn >> 2, head = bn & 3;
    const int r = lane & 15, hf = lane >> 4;
    const int r2 = lane >> 2, lcol = (lane & 3) << 1;
    const int tj = (lane & 7) + ((lane >> 4) << 3);
    const int tn = ((lane >> 3) & 1) << 3;
    const int wm = wid << 4;

    // Q -> regs via temp staging in stage buf 1 (32KB, two 128B halves)
    uint32_t qh[8][4];
    {
        const char* gQ = (const char*)g_q + ((size_t)bn * L_ + m0) * 256;
        const uint32_t sbq = smb + FA_STG + FA_STAGE;
        #pragma unroll
        for (int p = 0; p < 8; ++p) {
            int e = tid + (p << 8);
            int row = e >> 4, sg = (e & 15) << 4;
            uint32_t s = ((sg >> 7) << 14) + SWZ((row << 7) + (sg & 127));
            cp16(sbq + s, gQ + (size_t)row * 256 + sg);
        }
        CP_COMMIT(); CP_WAIT(0); __syncthreads();
        #pragma unroll
        for (int ks = 0; ks < 8; ++ks) {
            int ab = (ks << 5) + (hf << 4);
            uint32_t rel = ((ab >> 7) << 14) + SWZ(((wm + r) << 7) + (ab & 127));
            ldmx4(qh[ks], sbq + rel);
        }
        __syncthreads();
    }

    // ---- prologue: rdot = Q @ rel^T into rdot smem (rel staged in buf 0, 32KB) ----
    {
        const char* gR = (const char*)g_rel;
        const uint32_t sb = smb + FA_STG;
        #pragma unroll
        for (int p = 0; p < 8; ++p) {
            int e = tid + (p << 8);
            int row = e >> 4, sg = (e & 15) << 4;
            uint32_t s = ((sg >> 7) << 14) + SWZ((row << 7) + (sg & 127));
            cp16(sb + s, gR + (size_t)row * 256 + sg);
        }
        CP_COMMIT(); CP_WAIT(0); __syncthreads();
        float* rsm = (float*)sm;
        #pragma unroll 1
        for (int ss2 = 0; ss2 < 4; ++ss2) {
            float rs[4][4];
            #pragma unroll
            for (int t = 0; t < 4; ++t)
                #pragma unroll
                for (int u = 0; u < 4; ++u) rs[t][u] = 0.f;
            #pragma unroll
            for (int ks = 0; ks < 8; ++ks) {
                const int ab = (ks << 5) + (hf << 4);
                uint32_t bhf[2][4];
                #pragma unroll
                for (int np = 0; np < 2; ++np) {
                    int jr = (ss2 << 5) + (np << 4) + r;
                    uint32_t rel = ((ab >> 7) << 14) + SWZ((jr << 7) + (ab & 127));
                    ldmx4(bhf[np], sb + rel);
                }
                #pragma unroll
                for (int np = 0; np < 2; ++np)
                    #pragma unroll
                    for (int sub = 0; sub < 2; ++sub)
                        mma16816h(rs[np * 2 + sub], qh[ks], bhf[np][sub], bhf[np][sub + 2]);
            }
            const int j0 = ss2 << 5;
            #pragma unroll
            for (int t = 0; t < 4; ++t) {
                int jj = j0 + (t << 3) + lcol;
                rsm[(wm + r2) * 128 + jj]           = rs[t][0];
                rsm[(wm + r2) * 128 + jj + 1]       = rs[t][1];
                rsm[(wm + r2 + 8) * 128 + jj]       = rs[t][2];
                rsm[(wm + r2 + 8) * 128 + jj + 1]   = rs[t][3];
            }
        }
        __syncthreads();
    }

    const char* gK = (const char*)g_k + (size_t)bn * L_ * 256;
    const char* gV = (const char*)g_v + (size_t)bn * L_ * 256;

    auto stageKV = [&](int jt, int buf) {
        const uint32_t sb = smb + FA_STG + buf * FA_STAGE;
        const size_t base = (size_t)(jt * 64) * 256;
        #pragma unroll
        for (int p = 0; p < 4; ++p) {
            int e = tid + (p << 8);
            int row = e >> 4, sg = (e & 15) << 4;
            uint32_t s = ((sg >> 7) << 13) + SWZ((row << 7) + (sg & 127));
            size_t go = base + (size_t)row * 256 + sg;
            cp16(sb + s,         gK + go);
            cp16(sb + 16384 + s, gV + go);
        }
    };

    const int i0 = m0 + wm + r2, i1 = i0 + 8;
    const int h0 = i0 >> 5, w0 = i0 & 31;
    const int h1 = i1 >> 5, w1 = i1 & 31;
    const float* rd0 = (const float*)(sm + (size_t)(wm + r2) * 512);
    const float* rd1 = (const float*)(sm + (size_t)(wm + r2 + 8) * 512);

    float o[16][4];
    #pragma unroll
    for (int nt = 0; nt < 16; ++nt)
        #pragma unroll
        for (int u = 0; u < 4; ++u) o[nt][u] = 0.f;
    float m0r = -1e30f, m1r = -1e30f, s0r = 0.f, s1r = 0.f;

    stageKV(0, 0);
    CP_COMMIT();

    #pragma unroll 1
    for (int jt = 0; jt < 16; ++jt) {
        const int buf = jt & 1;
        if (jt + 1 < 16) { stageKV(jt + 1, buf ^ 1); CP_COMMIT(); CP_WAIT(1); }
        else CP_WAIT(0);
        __syncthreads();
        const uint32_t kb_s = smb + FA_STG + buf * FA_STAGE;
        const uint32_t vb_s = kb_s + 16384;

        // ---- S = Q K^T over the full 64-j tile ----
        float s[8][4];
        #pragma unroll
        for (int t = 0; t < 8; ++t)
            #pragma unroll
            for (int u = 0; u < 4; ++u) s[t][u] = 0.f;
        #pragma unroll
        for (int ks = 0; ks < 8; ++ks) {
            const int ab = (ks << 5) + (hf << 4);
            uint32_t bhf[4][4];
            #pragma unroll
            for (int np = 0; np < 4; ++np) {
                int jr = (np << 4) + r;
                uint32_t rel = ((ab >> 7) << 13) + SWZ((jr << 7) + (ab & 127));
                ldmx4(bhf[np], kb_s + rel);
            }
            #pragma unroll
            for (int np = 0; np < 4; ++np)
                #pragma unroll
                for (int sub = 0; sub < 2; ++sub)
                    mma16816h(s[np * 2 + sub], qh[ks], bhf[np][sub], bhf[np][sub + 2]);
        }

        // ---- bias + row max (64 j) ----
        const int j0 = jt * 64;
        float t0 = -1e30f, t1 = -1e30f;
        #pragma unroll
        for (int t = 0; t < 8; ++t) {
            int jj = j0 + t * 8 + lcol;
            int h2 = jj >> 5, w2 = jj & 31;
            float bh0 = rd0[94 + h2 - h0];
            float bh1 = rd1[94 + h2 - h1];
            s[t][0] += rd0[w2 - w0 + 31] + bh0;
            s[t][1] += rd0[w2 + 1 - w0 + 31] + bh0;
            s[t][2] += rd1[w2 - w1 + 31] + bh1;
            s[t][3] += rd1[w2 + 1 - w1 + 31] + bh1;
            t0 = fmaxf(t0, fmaxf(s[t][0], s[t][1]));
            t1 = fmaxf(t1, fmaxf(s[t][2], s[t][3]));
        }
        t0 = fmaxf(t0, __shfl_xor_sync(~0u, t0, 1));
        t0 = fmaxf(t0, __shfl_xor_sync(~0u, t0, 2));
        t1 = fmaxf(t1, __shfl_xor_sync(~0u, t1, 1));
        t1 = fmaxf(t1, __shfl_xor_sync(~0u, t1, 2));

        // ---- online softmax update ----
        float mn0 = fmaxf(m0r, t0), mn1 = fmaxf(m1r, t1);
        float a0 = __expf(m0r - mn0), a1 = __expf(m1r - mn1);
        if (!(a0 == 1.0f && a1 == 1.0f)) {
            #pragma unroll
            for (int nt = 0; nt < 16; ++nt) {
                o[nt][0] *= a0; o[nt][1] *= a0; o[nt][2] *= a1; o[nt][3] *= a1;
            }
        }
        uint32_t ph[4][4];
        float ts0 = 0.f, ts1 = 0.f;
        #pragma unroll
        for (int t = 0; t < 8; ++t) {
            float p0 = __expf(s[t][0] - mn0), p1 = __expf(s[t][1] - mn0);
            float p2 = __expf(s[t][2] - mn1), p3 = __expf(s[t][3] - mn1);
            ts0 += p0 + p1; ts1 += p2 + p3;
            int kt = t >> 1, wc = (t & 1) << 1;
            ph[kt][wc]     = pack_h2(p0, p1);
            ph[kt][wc + 1] = pack_h2(p2, p3);
        }
        ts0 += __shfl_xor_sync(~0u, ts0, 1); ts0 += __shfl_xor_sync(~0u, ts0, 2);
        ts1 += __shfl_xor_sync(~0u, ts1, 1); ts1 += __shfl_xor_sync(~0u, ts1, 2);
        s0r = s0r * a0 + ts0; s1r = s1r * a1 + ts1;
        m0r = mn0; m1r = mn1;

        // ---- O += P V (k = 64) ----
        #pragma unroll
        for (int kt = 0; kt < 4; ++kt) {
            #pragma unroll
            for (int np = 0; np < 8; ++np) {
                int jrow = (kt << 4) + tj;
                int db = ((np << 4) + tn) << 1;
                uint32_t rel = ((db >> 7) << 13) + SWZ((jrow << 7) + (db & 127));
                uint32_t vh4[4];
                ldmx4t(vh4, vb_s + rel);
                #pragma unroll
                for (int sub = 0; sub < 2; ++sub)
                    mma16816h(o[np * 2 + sub], ph[kt], vh4[sub], vh4[sub + 2]);
            }
        }
        __syncthreads();
    }

    // ---- epilogue: normalize -> smem transpose -> coalesced residual+store ----
    __syncthreads();
    float* so = (float*)sm;                 // [128 d][136 stride] fp32
    const float inv0 = 1.f / s0r, inv1 = 1.f / s1r;
    #pragma unroll
    for (int nt = 0; nt < 16; ++nt) {
        const int d0 = (nt << 3) + lcol;
        #pragma unroll
        for (int u = 0; u < 2; ++u) {
            so[(d0 + u) * 136 + wm + r2]     = o[nt][u] * inv0;
            so[(d0 + u) * 136 + wm + r2 + 8] = o[nt][2 + u] * inv1;
        }
    }
    __syncthreads();
    #pragma unroll
    for (int ch = 0; ch < 16; ++ch) {
        const int d = (ch << 3) + (tid >> 5);
        const int i4 = (tid & 31) << 2;
        const size_t idx = ((size_t)(b * C_ + head * D_ + d) << 10) + m0 + i4;
        float4 xr = *(const float4*)(x + idx);
        float4 ov = *(const float4*)(so + d * 136 + i4);
        ov.x += xr.x; ov.y += xr.y; ov.z += xr.z; ov.w += xr.w;
        *(float4*)(g_xres + idx) = ov;
    }
}

// ---------------- conv GEMM via mma.sync fp16 single x single (1 MMA per product) -------
// tile M=128 (o) x N=256 (l); grid (4,4,8) = 128 CTAs = one full wave. 256 threads.
#define NCHUNK 72
#define CV_SUBA 16384
#define CV_SUBB 32768
#define CV_BUF (CV_SUBA + CV_SUBB)           // A | B = 48KB
#define CONV_SMEM (1024 + 2 * CV_BUF)
__global__ __launch_bounds__(256, 1) void conv_mma_kernel(const float* __restrict__ bias_fc,
                                                          float* __restrict__ out) {
    extern __shared__ char smraw[];
    char* sm = (char*)(((uintptr_t)smraw + 1023) & ~(uintptr_t)1023);
    const uint32_t smb = smem_u32(sm);
    const int tid = threadIdx.x, wid = tid >> 5, lane = tid & 31;
    const int bb = blockIdx.z, m0 = blockIdx.y * 128, n0 = blockIdx.x * 256;

    const char* gA = (const char*)g_w_f + (size_t)m0 * (KC_ * 2);
    const char* gY = (const char*)g_y2t + (size_t)bb * L_ * 1024;

    auto stage = [&](int it, int buf) {
        const size_t koff = (size_t)it * 128;
        const uint32_t sb = smb + buf * CV_BUF;
        #pragma unroll
        for (int p = 0; p < 4; ++p) {   // A: weights 128 rows x 128B
            int e = tid + (p << 8);
            int row = e >> 3;
            int sg = (e & 7) << 4;
            size_t g = (size_t)row * (KC_ * 2) + koff + sg;
            uint32_t s = SWZ((row << 7) + sg);
            cp16(sb + s, gA + g);
        }
        const int r9 = it >> 3;
        const int dh = r9 / 3 - 1, dw = r9 % 3 - 1;
        const int cb2 = ((it & 7) << 6) * 2;
        #pragma unroll
        for (int p = 0; p < 8; ++p) {             // B: 256 rows x 128B
            int e = tid + (p << 8);
            int row = e >> 3;
            int sg = (e & 7) << 4;
            uint32_t s = SWZ((row << 7) + sg);
            int l = n0 + row;
            int h = (l >> 5) + dh, w = (l & 31) + dw;
            if ((unsigned)h < 32u && (unsigned)w < 32u) {
                size_t g = ((size_t)(l + dh * 32 + dw) << 10) + cb2 + sg;
                cp16(sb + CV_SUBA + s, gY + g);
            } else {
                uint4 z = make_uint4(0u, 0u, 0u, 0u);
                *(uint4*)(sm + ((size_t)buf * CV_BUF + CV_SUBA + s)) = z;
            }
        }
    };

    float acc[2][16][4];
    #pragma unroll
    for (int i = 0; i < 2; i++)
        #pragma unroll
        for (int j = 0; j < 16; j++)
            #pragma unroll
            for (int t = 0; t < 4; t++) acc[i][j][t] = 0.f;

    const int wm = (wid & 3) << 5, wn = (wid >> 2) << 7;
    const int r = lane & 15, hf = lane >> 4;

    stage(0, 0);
    CP_COMMIT();
    #pragma unroll 1
    for (int it = 0; it < NCHUNK; ++it) {
        const int buf = it & 1;
        if (it + 1 < NCHUNK) { stage(it + 1, buf ^ 1); CP_COMMIT(); CP_WAIT(1); }
        else CP_WAIT(0);
        __syncthreads();
        const uint32_t sA = smb + buf * CV_BUF;
        const uint32_t sB = sA + CV_SUBA;
        #pragma unroll
        for (int ks = 0; ks < 4; ++ks) {
            const int kb = ks << 5;
            uint32_t ah[2][4];
            #pragma unroll
            for (int mt = 0; mt < 2; ++mt) {
                uint32_t rel = SWZ(((wm + (mt << 4) + r) << 7) + kb + (hf << 4));
                ldmx4(ah[mt], sA + rel);
            }
            #pragma unroll
            for (int np = 0; np < 8; ++np) {
                uint32_t rel = SWZ(((wn + (np << 4) + r) << 7) + kb + (hf << 4));
                uint32_t bh[4];
                ldmx4(bh, sB + rel);
                #pragma unroll
                for (int mt = 0; mt < 2; ++mt)
                    #pragma unroll
                    for (int sub = 0; sub < 2; ++sub)
                        mma16816h(acc[mt][np * 2 + sub], ah[mt], bh[sub], bh[sub + 2]);
            }
        }
        __syncthreads();
    }

    const int lrow = lane >> 2, lcol = (lane & 3) << 1;
    #pragma unroll
    for (int mt = 0; mt < 2; ++mt) {
        #pragma unroll
        for (int nt = 0; nt < 16; ++nt) {
            const float* c = acc[mt][nt];
            int l = n0 + wn + (nt << 3) + lcol;
            #pragma unroll
            for (int half = 0; half < 2; ++half) {
                int o = m0 + wm + (mt << 4) + lrow + half * 8;
                float bv = bias_fc[o];
                size_t idx = ((size_t)(bb * C_ + o) << 10) + l;
                float2 xr = *(const float2*)(g_xres + idx);
                float2 o2;
                o2.x = c[half * 2 + 0] + bv + xr.x;
                o2.y = c[half * 2 + 1] + bv + xr.y;
                *(float2*)(out + idx) = o2;
            }
        }
    }
}

// ---------------- launch ----------------
extern "C" void kernel_launch(void* const* d_in, const int* in_sizes, int n_in,
                              void* d_out, int out_size) {
    const float* x       = (const float*)d_in[0];
    const float* w_qk    = (const float*)d_in[1];
    const float* w_v     = (const float*)d_in[2];
    const float* rel_h   = (const float*)d_in[3];
    const float* rel_w   = (const float*)d_in[4];
    const float* g1      = (const float*)d_in[5];
    const float* b1      = (const float*)d_in[6];
    const float* m1      = (const float*)d_in[7];
    const float* v1      = (const float*)d_in[8];
    const float* g2      = (const float*)d_in[9];
    const float* b2      = (const float*)d_in[10];
    const float* m2      = (const float*)d_in[11];
    const float* v2      = (const float*)d_in[12];
    const float* w_fc    = (const float*)d_in[13];
    const float* bias_fc = (const float*)d_in[14];
    float* out = (float*)d_out;

    cudaFuncSetAttribute(proj_mma_kernel, cudaFuncAttributeMaxDynamicSharedMemorySize, PROJ_SMEM);
    cudaFuncSetAttribute(flash_kernel,    cudaFuncAttributeMaxDynamicSharedMemorySize, FA_SMEM);
    cudaFuncSetAttribute(conv_mma_kernel, cudaFuncAttributeMaxDynamicSharedMemorySize, CONV_SMEM);

    wcvt_kernel<<<(1536 * 512 + 16384 + C_ * KC_) / 256, 256>>>(w_qk, w_v, rel_h, rel_w, w_fc);
    bn1t_kernel<<<dim3(32, 16, B_), 256>>>(x, g1, b1, m1, v1);
    proj_mma_kernel<<<dim3(12, 8, B_), 256, PROJ_SMEM>>>();
    flash_kernel<<<dim3(8, 32), 256, FA_SMEM>>>(x);
    bn2t_kernel<<<dim3(32, 16, B_), 256>>>(g2, b2, m2, v2);
    conv_mma_kernel<<<dim3(4, 4, B_), 256, CONV_SMEM>>>(bias_fc, out);
}

// round 17
// speedup vs baseline: 2.4487x; 1.0134x over previous
#include <cuda_runtime.h>
#include <cuda_bf16.h>
#include <cuda_fp16.h>
#include <cstdint>

// ---------------- problem constants ----------------
#define B_   8
#define C_   512
#define HH_  32
#define WW_  32
#define L_   1024          // HH*WW
#define NH_  4
#define D_   128
#define KC_  4608          // 512*9 (im2col K)
#define QSCALE 0.08838834764831845f  // 128^-0.5

// ---------------- scratch (device globals; no allocations) ----------------
__device__ __half g_xn[B_*L_*C_];            // relu(bn1(x)) transposed [b][l][c] fp16
__device__ __half g_wqkv[1536*512];          // [o][c], o: q|k|v  fp16
__device__ __half g_rel[128*128];            // rows: 0..62 rel_w, 63..125 rel_h, 126..127 zero
__device__ __half g_q[32*L_*D_];             // [bn][l][d] (scaled) fp16
__device__ __half g_k[32*L_*D_];
__device__ __half g_v[32*L_*D_];
__device__ float g_xres[B_*C_*L_];           // mhsa out + x
__device__ __half g_y2t[B_*L_*C_];           // relu(bn2(xres)) transposed fp16
__device__ __half g_w_f[(size_t)C_*KC_];     // conv weights fp16, reordered [o][r9*512 + c]

// ================= mma.sync helpers =================
__device__ __forceinline__ uint32_t smem_u32(const void* p) {
    uint32_t a;
    asm("{ .reg .u64 t; cvta.to.shared.u64 t, %1; cvt.u32.u64 %0, t; }" : "=r"(a) : "l"(p));
    return a;
}
__device__ __forceinline__ void cp16(uint32_t s, const void* g) {
    asm volatile("cp.async.cg.shared.global [%0], [%1], 16;" :: "r"(s), "l"(g));
}
#define CP_COMMIT() asm volatile("cp.async.commit_group;" ::: "memory")
#define CP_WAIT(n)  asm volatile("cp.async.wait_group %0;" :: "n"(n) : "memory")

__device__ __forceinline__ void ldmx4(uint32_t* d, uint32_t addr) {
    asm volatile("ldmatrix.sync.aligned.m8n8.x4.shared.b16 {%0,%1,%2,%3}, [%4];"
                 : "=r"(d[0]), "=r"(d[1]), "=r"(d[2]), "=r"(d[3]) : "r"(addr));
}
__device__ __forceinline__ void ldmx4t(uint32_t* d, uint32_t addr) {
    asm volatile("ldmatrix.sync.aligned.m8n8.x4.trans.shared.b16 {%0,%1,%2,%3}, [%4];"
                 : "=r"(d[0]), "=r"(d[1]), "=r"(d[2]), "=r"(d[3]) : "r"(addr));
}
__device__ __forceinline__ void mma16816h(float* c, const uint32_t* a, uint32_t b0, uint32_t b1) {
    asm volatile("mma.sync.aligned.m16n8k16.row.col.f32.f16.f16.f32 "
                 "{%0,%1,%2,%3}, {%4,%5,%6,%7}, {%8,%9}, {%0,%1,%2,%3};"
                 : "+f"(c[0]), "+f"(c[1]), "+f"(c[2]), "+f"(c[3])
                 : "r"(a[0]), "r"(a[1]), "r"(a[2]), "r"(a[3]), "r"(b0), "r"(b1));
}
#define SWZ(x) ((x) ^ (((x) >> 3) & 0x70))

__device__ __forceinline__ uint32_t pack_h2(float a, float b) {
    __half2 h = __floats2half2_rn(a, b);
    return *(uint32_t*)&h;
}

// ---------------- BN1 + ReLU + transpose -> fp16 [b][l][c] ----------------
__global__ void bn1t_kernel(const float* __restrict__ x,
                            const float* __restrict__ g, const float* __restrict__ bb,
                            const float* __restrict__ m, const float* __restrict__ v) {
    __shared__ float t[32][33];
    const int b = blockIdx.z, c0 = blockIdx.y * 32, l0 = blockIdx.x * 32;
    const int tid = threadIdx.x;
    {
        const int cr = tid >> 3, l4 = (tid & 7) * 4;
        const int c = c0 + cr;
        float inv = g[c] * rsqrtf(v[c] + 1e-5f);
        float sh  = bb[c] - m[c] * inv;
        float4 xv = *(const float4*)(x + ((size_t)(b * C_ + c) << 10) + l0 + l4);
        t[cr][l4 + 0] = fmaxf(fmaf(xv.x, inv, sh), 0.f);
        t[cr][l4 + 1] = fmaxf(fmaf(xv.y, inv, sh), 0.f);
        t[cr][l4 + 2] = fmaxf(fmaf(xv.z, inv, sh), 0.f);
        t[cr][l4 + 3] = fmaxf(fmaf(xv.w, inv, sh), 0.f);
    }
    __syncthreads();
    {
        const int lr = tid >> 3, c4 = (tid & 7) * 4;
        size_t base = ((size_t)(b * L_ + l0 + lr) << 9) + c0 + c4;
        *(uint32_t*)(g_xn + base)     = pack_h2(t[c4 + 0][lr], t[c4 + 1][lr]);
        *(uint32_t*)(g_xn + base + 2) = pack_h2(t[c4 + 2][lr], t[c4 + 3][lr]);
    }
}

// ---------------- all weights + rel tables -> fp16 (single merged kernel) ----------------
__global__ void wcvt_kernel(const float* __restrict__ w_qk, const float* __restrict__ w_v,
                            const float* __restrict__ rel_h, const float* __restrict__ rel_w,
                            const float* __restrict__ w_fc) {
    int i = blockIdx.x * 256 + threadIdx.x;
    if (i < 1024 * 512) {
        g_wqkv[i] = __float2half(w_qk[i]);
    } else if (i < 1536 * 512) {
        g_wqkv[i] = __float2half(w_v[i - 1024 * 512]);
    } else if (i < 1536 * 512 + 16384) {
        int j = i - 1536 * 512;
        int rr = j >> 7, d = j & 127;
        float val = 0.f;
        if (rr < 63)       val = rel_w[rr * 128 + d];
        else if (rr < 126) val = rel_h[(rr - 63) * 128 + d];
        g_rel[j] = __float2half(val);
    } else {
        int j = i - (1536 * 512 + 16384);     // src: o*4608 + c*9 + r9
        int o = j / KC_, rem = j % KC_;
        int c = rem / 9, r9 = rem % 9;
        size_t dst = (size_t)o * KC_ + r9 * 512 + c;
        g_w_f[dst] = __float2half(w_fc[j]);
    }
}

// ---------------- QKV projection via mma.sync fp16 single (2 CTAs/SM) ----------------
#define P_SUB 16384
#define P_BUF (2 * P_SUB)
#define PROJ_SMEM (1024 + 2 * P_BUF)
__global__ __launch_bounds__(256, 2) void proj_mma_kernel() {
    extern __shared__ char smraw[];
    char* sm = (char*)(((uintptr_t)smraw + 1023) & ~(uintptr_t)1023);
    const uint32_t smb = smem_u32(sm);
    const int tid = threadIdx.x, wid = tid >> 5, lane = tid & 31;
    const int b = blockIdx.z, m0 = blockIdx.y * 128, n0 = blockIdx.x * 128;

    const char* gA = (const char*)g_xn + (size_t)(b * L_ + m0) * 1024;
    const char* gB = (const char*)g_wqkv + (size_t)n0 * 1024;

    auto stage = [&](int it, int buf) {
        const uint32_t sb = smb + buf * P_BUF;
        #pragma unroll
        for (int p = 0; p < 4; ++p) {
            int e = tid + (p << 8);
            int row = e >> 3;
            int sg = (e & 7) << 4;
            size_t go = (size_t)row * 1024 + (size_t)it * 128 + sg;
            uint32_t s = SWZ((row << 7) + sg);
            cp16(sb + s,         gA + go);
            cp16(sb + P_SUB + s, gB + go);
        }
    };

    float acc[2][8][4];
    #pragma unroll
    for (int i = 0; i < 2; i++)
        #pragma unroll
        for (int j = 0; j < 8; j++)
            #pragma unroll
            for (int t = 0; t < 4; t++) acc[i][j][t] = 0.f;

    const int wm = (wid & 3) << 5, wn = (wid >> 2) << 6;
    const int r = lane & 15, hf = lane >> 4;

    stage(0, 0);
    CP_COMMIT();
    #pragma unroll 1
    for (int it = 0; it < 8; ++it) {
        const int buf = it & 1;
        if (it + 1 < 8) { stage(it + 1, buf ^ 1); CP_COMMIT(); CP_WAIT(1); }
        else CP_WAIT(0);
        __syncthreads();
        const uint32_t sA = smb + buf * P_BUF, sB = sA + P_SUB;
        #pragma unroll
        for (int ks = 0; ks < 4; ++ks) {
            const int kb = ks << 5;
            uint32_t ah[2][4];
            #pragma unroll
            for (int mt = 0; mt < 2; ++mt) {
                uint32_t rel = SWZ(((wm + (mt << 4) + r) << 7) + kb + (hf << 4));
                ldmx4(ah[mt], sA + rel);
            }
            uint32_t bh[4][4];
            #pragma unroll
            for (int np = 0; np < 4; ++np) {
                uint32_t rel = SWZ(((wn + (np << 4) + r) << 7) + kb + (hf << 4));
                ldmx4(bh[np], sB + rel);
            }
            #pragma unroll
            for (int mt = 0; mt < 2; ++mt)
                #pragma unroll
                for (int np = 0; np < 4; ++np)
                    #pragma unroll
                    for (int sub = 0; sub < 2; ++sub)
                        mma16816h(acc[mt][np * 2 + sub], ah[mt], bh[np][sub], bh[np][sub + 2]);
        }
        __syncthreads();
    }

    const int region = n0 >> 9;                 // 0=q,1=k,2=v
    const int head = (n0 >> 7) & 3;
    const float scale = (region == 0) ? QSCALE : 1.0f;
    __half* dst;
    if (region == 0)      dst = g_q;
    else if (region == 1) dst = g_k;
    else                  dst = g_v;
    const size_t bnbase = (size_t)(b * NH_ + head) * L_ * D_;
    const int lrow = lane >> 2, lcol = (lane & 3) << 1;
    #pragma unroll
    for (int mt = 0; mt < 2; ++mt) {
        #pragma unroll
        for (int nt = 0; nt < 8; ++nt) {
            const float* c = acc[mt][nt];
            const int d0 = wn + (nt << 3) + lcol;
            #pragma unroll
            for (int half = 0; half < 2; ++half) {
                int lv = m0 + wm + (mt << 4) + lrow + half * 8;
                size_t base = bnbase + ((size_t)lv << 7) + d0;
                *(uint32_t*)(dst + base) =
                    pack_h2(c[half * 2 + 0] * scale, c[half * 2 + 1] * scale);
            }
        }
    }
}

// ---------------- fused flash attention (fp16) + rel-pos + residual + BN2 ----------------
// grid (8 m-tiles, 32 bn), 256 threads = 8 warps, each warp 16 rows.
// smem: rdot 64KB fp32 | 2 stages x 32KB (K|V). Epilogue writes xres AND y2t(bn2+relu).
#define FA_STG 65536
#define FA_STAGE 32768
#define FA_SMEM (1024 + FA_STG + 2 * FA_STAGE)   // 132096
__global__ __launch_bounds__(256, 1) void flash_kernel(const float* __restrict__ x,
                                                       const float* __restrict__ g2,
                                                       const float* __restrict__ bb2,
                                                       const float* __restrict__ m2,
                                                       const float* __restrict__ v2) {
    extern __shared__ char smraw[];
    char* sm = (char*)(((uintptr_t)smraw + 1023) & ~(uintptr_t)1023);
    const uint32_t smb = smem_u32(sm);
    const int tid = threadIdx.x, wid = tid >> 5, lane = tid & 31;
    const int m0 = blockIdx.x * 128, bn = blockIdx.y;
    const int b = bn >> 2, head = bn & 3;
    const int r = lane & 15, hf = lane >> 4;
    const int r2 = lane >> 2, lcol = (lane & 3) << 1;
    const int tj = (lane & 7) + ((lane >> 4) << 3);
    const int tn = ((lane >> 3) & 1) << 3;
    const int wm = wid << 4;

    // Q -> regs via temp staging in stage buf 1 (32KB, two 128B halves)
    uint32_t qh[8][4];
    {
        const char* gQ = (const char*)g_q + ((size_t)bn * L_ + m0) * 256;
        const uint32_t sbq = smb + FA_STG + FA_STAGE;
        #pragma unroll
        for (int p = 0; p < 8; ++p) {
            int e = tid + (p << 8);
            int row = e >> 4, sg = (e & 15) << 4;
            uint32_t s = ((sg >> 7) << 14) + SWZ((row << 7) + (sg & 127));
            cp16(sbq + s, gQ + (size_t)row * 256 + sg);
        }
        CP_COMMIT(); CP_WAIT(0); __syncthreads();
        #pragma unroll
        for (int ks = 0; ks < 8; ++ks) {
            int ab = (ks << 5) + (hf << 4);
            uint32_t rel = ((ab >> 7) << 14) + SWZ(((wm + r) << 7) + (ab & 127));
            ldmx4(qh[ks], sbq + rel);
        }
        __syncthreads();
    }

    // ---- prologue: rdot = Q @ rel^T into rdot smem (rel staged in buf 0, 32KB) ----
    {
        const char* gR = (const char*)g_rel;
        const uint32_t sb = smb + FA_STG;
        #pragma unroll
        for (int p = 0; p < 8; ++p) {
            int e = tid + (p << 8);
            int row = e >> 4, sg = (e & 15) << 4;
            uint32_t s = ((sg >> 7) << 14) + SWZ((row << 7) + (sg & 127));
            cp16(sb + s, gR + (size_t)row * 256 + sg);
        }
        CP_COMMIT(); CP_WAIT(0); __syncthreads();
        float* rsm = (float*)sm;
        #pragma unroll 1
        for (int ss2 = 0; ss2 < 4; ++ss2) {
            float rs[4][4];
            #pragma unroll
            for (int t = 0; t < 4; ++t)
                #pragma unroll
                for (int u = 0; u < 4; ++u) rs[t][u] = 0.f;
            #pragma unroll
            for (int ks = 0; ks < 8; ++ks) {
                const int ab = (ks << 5) + (hf << 4);
                uint32_t bhf[2][4];
                #pragma unroll
                for (int np = 0; np < 2; ++np) {
                    int jr = (ss2 << 5) + (np << 4) + r;
                    uint32_t rel = ((ab >> 7) << 14) + SWZ((jr << 7) + (ab & 127));
                    ldmx4(bhf[np], sb + rel);
                }
                #pragma unroll
                for (int np = 0; np < 2; ++np)
                    #pragma unroll
                    for (int sub = 0; sub < 2; ++sub)
                        mma16816h(rs[np * 2 + sub], qh[ks], bhf[np][sub], bhf[np][sub + 2]);
            }
            const int j0 = ss2 << 5;
            #pragma unroll
            for (int t = 0; t < 4; ++t) {
                int jj = j0 + (t << 3) + lcol;
                rsm[(wm + r2) * 128 + jj]           = rs[t][0];
                rsm[(wm + r2) * 128 + jj + 1]       = rs[t][1];
                rsm[(wm + r2 + 8) * 128 + jj]       = rs[t][2];
                rsm[(wm + r2 + 8) * 128 + jj + 1]   = rs[t][3];
            }
        }
        __syncthreads();
    }

    const char* gK = (const char*)g_k + (size_t)bn * L_ * 256;
    const char* gV = (const char*)g_v + (size_t)bn * L_ * 256;

    auto stageKV = [&](int jt, int buf) {
        const uint32_t sb = smb + FA_STG + buf * FA_STAGE;
        const size_t base = (size_t)(jt * 64) * 256;
        #pragma unroll
        for (int p = 0; p < 4; ++p) {
            int e = tid + (p << 8);
            int row = e >> 4, sg = (e & 15) << 4;
            uint32_t s = ((sg >> 7) << 13) + SWZ((row << 7) + (sg & 127));
            size_t go = base + (size_t)row * 256 + sg;
            cp16(sb + s,         gK + go);
            cp16(sb + 16384 + s, gV + go);
        }
    };

    const int i0 = m0 + wm + r2, i1 = i0 + 8;
    const int h0 = i0 >> 5, w0 = i0 & 31;
    const int h1 = i1 >> 5, w1 = i1 & 31;
    const float* rd0 = (const float*)(sm + (size_t)(wm + r2) * 512);
    const float* rd1 = (const float*)(sm + (size_t)(wm + r2 + 8) * 512);

    float o[16][4];
    #pragma unroll
    for (int nt = 0; nt < 16; ++nt)
        #pragma unroll
        for (int u = 0; u < 4; ++u) o[nt][u] = 0.f;
    float m0r = -1e30f, m1r = -1e30f, s0r = 0.f, s1r = 0.f;

    stageKV(0, 0);
    CP_COMMIT();

    #pragma unroll 1
    for (int jt = 0; jt < 16; ++jt) {
        const int buf = jt & 1;
        if (jt + 1 < 16) { stageKV(jt + 1, buf ^ 1); CP_COMMIT(); CP_WAIT(1); }
        else CP_WAIT(0);
        __syncthreads();
        const uint32_t kb_s = smb + FA_STG + buf * FA_STAGE;
        const uint32_t vb_s = kb_s + 16384;

        // ---- S = Q K^T over the full 64-j tile ----
        float s[8][4];
        #pragma unroll
        for (int t = 0; t < 8; ++t)
            #pragma unroll
            for (int u = 0; u < 4; ++u) s[t][u] = 0.f;
        #pragma unroll
        for (int ks = 0; ks < 8; ++ks) {
            const int ab = (ks << 5) + (hf << 4);
            uint32_t bhf[4][4];
            #pragma unroll
            for (int np = 0; np < 4; ++np) {
                int jr = (np << 4) + r;
                uint32_t rel = ((ab >> 7) << 13) + SWZ((jr << 7) + (ab & 127));
                ldmx4(bhf[np], kb_s + rel);
            }
            #pragma unroll
            for (int np = 0; np < 4; ++np)
                #pragma unroll
                for (int sub = 0; sub < 2; ++sub)
                    mma16816h(s[np * 2 + sub], qh[ks], bhf[np][sub], bhf[np][sub + 2]);
        }

        // ---- bias + row max (64 j) ----
        const int j0 = jt * 64;
        float t0 = -1e30f, t1 = -1e30f;
        #pragma unroll
        for (int t = 0; t < 8; ++t) {
            int jj = j0 + t * 8 + lcol;
            int h2 = jj >> 5, w2 = jj & 31;
            float bh0 = rd0[94 + h2 - h0];
            float bh1 = rd1[94 + h2 - h1];
            s[t][0] += rd0[w2 - w0 + 31] + bh0;
            s[t][1] += rd0[w2 + 1 - w0 + 31] + bh0;
            s[t][2] += rd1[w2 - w1 + 31] + bh1;
            s[t][3] += rd1[w2 + 1 - w1 + 31] + bh1;
            t0 = fmaxf(t0, fmaxf(s[t][0], s[t][1]));
            t1 = fmaxf(t1, fmaxf(s[t][2], s[t][3]));
        }
        t0 = fmaxf(t0, __shfl_xor_sync(~0u, t0, 1));
        t0 = fmaxf(t0, __shfl_xor_sync(~0u, t0, 2));
        t1 = fmaxf(t1, __shfl_xor_sync(~0u, t1, 1));
        t1 = fmaxf(t1, __shfl_xor_sync(~0u, t1, 2));

        // ---- online softmax update ----
        float mn0 = fmaxf(m0r, t0), mn1 = fmaxf(m1r, t1);
        float a0 = __expf(m0r - mn0), a1 = __expf(m1r - mn1);
        if (!(a0 == 1.0f && a1 == 1.0f)) {
            #pragma unroll
            for (int nt = 0; nt < 16; ++nt) {
                o[nt][0] *= a0; o[nt][1] *= a0; o[nt][2] *= a1; o[nt][3] *= a1;
            }
        }
        uint32_t ph[4][4];
        float ts0 = 0.f, ts1 = 0.f;
        #pragma unroll
        for (int t = 0; t < 8; ++t) {
            float p0 = __expf(s[t][0] - mn0), p1 = __expf(s[t][1] - mn0);
            float p2 = __expf(s[t][2] - mn1), p3 = __expf(s[t][3] - mn1);
            ts0 += p0 + p1; ts1 += p2 + p3;
            int kt = t >> 1, wc = (t & 1) << 1;
            ph[kt][wc]     = pack_h2(p0, p1);
            ph[kt][wc + 1] = pack_h2(p2, p3);
        }
        ts0 += __shfl_xor_sync(~0u, ts0, 1); ts0 += __shfl_xor_sync(~0u, ts0, 2);
        ts1 += __shfl_xor_sync(~0u, ts1, 1); ts1 += __shfl_xor_sync(~0u, ts1, 2);
        s0r = s0r * a0 + ts0; s1r = s1r * a1 + ts1;
        m0r = mn0; m1r = mn1;

        // ---- O += P V (k = 64) ----
        #pragma unroll
        for (int kt = 0; kt < 4; ++kt) {
            #pragma unroll
            for (int np = 0; np < 8; ++np) {
                int jrow = (kt << 4) + tj;
                int db = ((np << 4) + tn) << 1;
                uint32_t rel = ((db >> 7) << 13) + SWZ((jrow << 7) + (db & 127));
                uint32_t vh4[4];
                ldmx4t(vh4, vb_s + rel);
                #pragma unroll
                for (int sub = 0; sub < 2; ++sub)
                    mma16816h(o[np * 2 + sub], ph[kt], vh4[sub], vh4[sub + 2]);
            }
        }
        __syncthreads();
    }

    // ---- epilogue: normalize -> smem; bn2 coeffs; coalesced xres; coalesced y2t ----
    __syncthreads();
    float* so = (float*)sm;                     // [128 d][136 stride] fp32
    float* binv = (float*)(sm + 70656);         // [128]
    float* bsh  = binv + 128;                   // [128]
    if (tid < 128) {
        int c = head * D_ + tid;
        float iv = g2[c] * rsqrtf(v2[c] + 1e-5f);
        binv[tid] = iv;
        bsh[tid] = bb2[c] - m2[c] * iv;
    }
    const float inv0 = 1.f / s0r, inv1 = 1.f / s1r;
    #pragma unroll
    for (int nt = 0; nt < 16; ++nt) {
        const int d0 = (nt << 3) + lcol;
        #pragma unroll
        for (int u = 0; u < 2; ++u) {
            so[(d0 + u) * 136 + wm + r2]     = o[nt][u] * inv0;
            so[(d0 + u) * 136 + wm + r2 + 8] = o[nt][2 + u] * inv1;
        }
    }
    __syncthreads();
    // xres (fp32, coalesced along l)
    #pragma unroll
    for (int ch = 0; ch < 16; ++ch) {
        const int d = (ch << 3) + (tid >> 5);
        const int i4 = (tid & 31) << 2;
        const size_t idx = ((size_t)(b * C_ + head * D_ + d) << 10) + m0 + i4;
        float4 xr = *(const float4*)(x + idx);
        float4 ov = *(const float4*)(so + d * 136 + i4);
        ov.x += xr.x; ov.y += xr.y; ov.z += xr.z; ov.w += xr.w;
        *(float4*)(g_xres + idx) = ov;
        // write back xres into so (so it holds final values for the y2t pass)
        *(float4*)(so + d * 136 + i4) = ov;
    }
    __syncthreads();
    // y2t = relu(bn2(xres)), coalesced per l-row (warp covers one row, 8B/lane)
    {
        const int d4 = lane << 2;
        const float iv0 = binv[d4], iv1 = binv[d4 + 1], iv2 = binv[d4 + 2], iv3 = binv[d4 + 3];
        const float sh0 = bsh[d4], sh1 = bsh[d4 + 1], sh2 = bsh[d4 + 2], sh3 = bsh[d4 + 3];
        #pragma unroll
        for (int k = 0; k < 16; ++k) {
            const int i = (k << 3) + wid;
            float v0 = so[(d4 + 0) * 136 + i];
            float v1 = so[(d4 + 1) * 136 + i];
            float v2f = so[(d4 + 2) * 136 + i];
            float v3 = so[(d4 + 3) * 136 + i];
            float y0 = fmaxf(fmaf(v0, iv0, sh0), 0.f);
            float y1 = fmaxf(fmaf(v1, iv1, sh1), 0.f);
            float y2v = fmaxf(fmaf(v2f, iv2, sh2), 0.f);
            float y3 = fmaxf(fmaf(v3, iv3, sh3), 0.f);
            size_t addr = ((size_t)(b * L_ + m0 + i) << 9) + head * D_ + d4;
            uint2 pk; pk.x = pack_h2(y0, y1); pk.y = pack_h2(y2v, y3);
            *(uint2*)(g_y2t + addr) = pk;
        }
    }
}

// ---------------- conv GEMM via mma.sync fp16 (1 MMA/product), 2 CTAs/SM --------------
// tile M=128 (o) x N=128 (l); grid (8,4,8) = 256 CTAs, 2/SM = one wave. 256 threads.
#define NCHUNK 72
#define CV_SUBA 16384
#define CV_SUBB 16384
#define CV_BUF (CV_SUBA + CV_SUBB)           // A | B = 32KB
#define CONV_SMEM (1024 + 2 * CV_BUF)
__global__ __launch_bounds__(256, 2) void conv_mma_kernel(const float* __restrict__ bias_fc,
                                                          float* __restrict__ out) {
    extern __shared__ char smraw[];
    char* sm = (char*)(((uintptr_t)smraw + 1023) & ~(uintptr_t)1023);
    const uint32_t smb = smem_u32(sm);
    const int tid = threadIdx.x, wid = tid >> 5, lane = tid & 31;
    const int bb = blockIdx.z, m0 = blockIdx.y * 128, n0 = blockIdx.x * 128;

    const char* gA = (const char*)g_w_f + (size_t)m0 * (KC_ * 2);
    const char* gY = (const char*)g_y2t + (size_t)bb * L_ * 1024;

    auto stage = [&](int it, int buf) {
        const size_t koff = (size_t)it * 128;
        const uint32_t sb = smb + buf * CV_BUF;
        #pragma unroll
        for (int p = 0; p < 4; ++p) {   // A: weights 128 rows x 128B
            int e = tid + (p << 8);
            int row = e >> 3;
            int sg = (e & 7) << 4;
            size_t g = (size_t)row * (KC_ * 2) + koff + sg;
            uint32_t s = SWZ((row << 7) + sg);
            cp16(sb + s, gA + g);
        }
        const int r9 = it >> 3;
        const int dh = r9 / 3 - 1, dw = r9 % 3 - 1;
        const int cb2 = ((it & 7) << 6) * 2;
        #pragma unroll
        for (int p = 0; p < 4; ++p) {             // B: 128 rows x 128B
            int e = tid + (p << 8);
            int row = e >> 3;
            int sg = (e & 7) << 4;
            uint32_t s = SWZ((row << 7) + sg);
            int l = n0 + row;
            int h = (l >> 5) + dh, w = (l & 31) + dw;
            if ((unsigned)h < 32u && (unsigned)w < 32u) {
                size_t g = ((size_t)(l + dh * 32 + dw) << 10) + cb2 + sg;
                cp16(sb + CV_SUBA + s, gY + g);
            } else {
                uint4 z = make_uint4(0u, 0u, 0u, 0u);
                *(uint4*)(sm + ((size_t)buf * CV_BUF + CV_SUBA + s)) = z;
            }
        }
    };

    float acc[2][8][4];
    #pragma unroll
    for (int i = 0; i < 2; i++)
        #pragma unroll
        for (int j = 0; j < 8; j++)
            #pragma unroll
            for (int t = 0; t < 4; t++) acc[i][j][t] = 0.f;

    const int wm = (wid & 3) << 5, wn = (wid >> 2) << 6;
    const int r = lane & 15, hf = lane >> 4;

    stage(0, 0);
    CP_COMMIT();
    #pragma unroll 1
    for (int it = 0; it < NCHUNK; ++it) {
        const int buf = it & 1;
        if (it + 1 < NCHUNK) { stage(it + 1, buf ^ 1); CP_COMMIT(); CP_WAIT(1); }
        else CP_WAIT(0);
        __syncthreads();
        const uint32_t sA = smb + buf * CV_BUF;
        const uint32_t sB = sA + CV_SUBA;
        #pragma unroll
        for (int ks = 0; ks < 4; ++ks) {
            const int kb = ks << 5;
            uint32_t ah[2][4];
            #pragma unroll
            for (int mt = 0; mt < 2; ++mt) {
                uint32_t rel = SWZ(((wm + (mt << 4) + r) << 7) + kb + (hf << 4));
                ldmx4(ah[mt], sA + rel);
            }
            #pragma unroll
            for (int np = 0; np < 4; ++np) {
                uint32_t rel = SWZ(((wn + (np << 4) + r) << 7) + kb + (hf << 4));
                uint32_t bh[4];
                ldmx4(bh, sB + rel);
                #pragma unroll
                for (int mt = 0; mt < 2; ++mt)
                    #pragma unroll
                    for (int sub = 0; sub < 2; ++sub)
                        mma16816h(acc[mt][np * 2 + sub], ah[mt], bh[sub], bh[sub + 2]);
            }
        }
        __syncthreads();
    }

    const int lrow = lane >> 2, lcol = (lane & 3) << 1;
    #pragma unroll
    for (int mt = 0; mt < 2; ++mt) {
        #pragma unroll
        for (int nt = 0; nt < 8; ++nt) {
            const float* c = acc[mt][nt];
            int l = n0 + wn + (nt << 3) + lcol;
            #pragma unroll
            for (int half = 0; half < 2; ++half) {
                int o = m0 + wm + (mt << 4) + lrow + half * 8;
                float bv = bias_fc[o];
                size_t idx = ((size_t)(bb * C_ + o) << 10) + l;
                float2 xr = *(const float2*)(g_xres + idx);
                float2 o2;
                o2.x = c[half * 2 + 0] + bv + xr.x;
                o2.y = c[half * 2 + 1] + bv + xr.y;
                *(float2*)(out + idx) = o2;
            }
        }
    }
}

// ---------------- launch ----------------
extern "C" void kernel_launch(void* const* d_in, const int* in_sizes, int n_in,
                              void* d_out, int out_size) {
    const float* x       = (const float*)d_in[0];
    const float* w_qk    = (const float*)d_in[1];
    const float* w_v     = (const float*)d_in[2];
    const float* rel_h   = (const float*)d_in[3];
    const float* rel_w   = (const float*)d_in[4];
    const float* g1      = (const float*)d_in[5];
    const float* b1      = (const float*)d_in[6];
    const float* m1      = (const float*)d_in[7];
    const float* v1      = (const float*)d_in[8];
    const float* g2      = (const float*)d_in[9];
    const float* b2      = (const float*)d_in[10];
    const float* m2      = (const float*)d_in[11];
    const float* v2      = (const float*)d_in[12];
    const float* w_fc    = (const float*)d_in[13];
    const float* bias_fc = (const float*)d_in[14];
    float* out = (float*)d_out;

    cudaFuncSetAttribute(proj_mma_kernel, cudaFuncAttributeMaxDynamicSharedMemorySize, PROJ_SMEM);
    cudaFuncSetAttribute(flash_kernel,    cudaFuncAttributeMaxDynamicSharedMemorySize, FA_SMEM);
    cudaFuncSetAttribute(conv_mma_kernel, cudaFuncAttributeMaxDynamicSharedMemorySize, CONV_SMEM);

    wcvt_kernel<<<(1536 * 512 + 16384 + C_ * KC_) / 256, 256>>>(w_qk, w_v, rel_h, rel_w, w_fc);
    bn1t_kernel<<<dim3(32, 16, B_), 256>>>(x, g1, b1, m1, v1);
    proj_mma_kernel<<<dim3(12, 8, B_), 256, PROJ_SMEM>>>();
    flash_kernel<<<dim3(8, 32), 256, FA_SMEM>>>(x, g2, b2, m2, v2);
    conv_mma_kernel<<<dim3(8, 4, B_), 256, CONV_SMEM>>>(bias_fc, out);
}